// round 1
// baseline (speedup 1.0000x reference)
#include <cuda_runtime.h>
#include <cuda_bf16.h>
#include <math.h>

// ---------------------------------------------------------------------------
// Problem constants
// ---------------------------------------------------------------------------
#define Bn   4
#define Sn   1024
#define Dn   1024
#define Hn   16
#define HDn  64
#define Cn   64
#define NCn  16
#define DFFn 256
#define EPSc 1e-6f
#define BSD  (Bn*Sn*Dn)

// ---------------------------------------------------------------------------
// Device scratch (static allocation — no cudaMalloc allowed)
// ---------------------------------------------------------------------------
__device__ float g_h [BSD];   // LN1 output; later reused for post-LN output
__device__ float g_q [BSD];   // q; later reused for XQ
__device__ float g_k [BSD];   // k; later reused for XK
__device__ float g_v [BSD];   // v; later reused for XV
__device__ float g_o [BSD];   // attention out; later reused for ttt_out
__device__ float g_x1[BSD];   // x after attention residual (= "residual")
__device__ float g_lr[Bn*Hn*Sn];

// TTT state per (b,h)
__device__ float g_W1s[Bn*Hn*HDn*DFFn];
__device__ float g_b1s[Bn*Hn*DFFn];
__device__ float g_W2s[Bn*Hn*DFFn*HDn];
__device__ float g_b2s[Bn*Hn*HDn];
// TTT per-chunk temporaries per (b,h)
__device__ float g_Z1t [Bn*Hn*Cn*DFFn];
__device__ float g_X2t [Bn*Hn*Cn*DFFn];
__device__ float g_gZ1t[Bn*Hn*Cn*DFFn];
__device__ float g_X2bt[Bn*Hn*Cn*DFFn];

// ---------------------------------------------------------------------------
// Helpers
// ---------------------------------------------------------------------------
__device__ __forceinline__ float warpsum(float v) {
#pragma unroll
    for (int o = 16; o > 0; o >>= 1) v += __shfl_xor_sync(0xffffffffu, v, o);
    return v;
}

// block (256 threads) all-reduce sum
__device__ __forceinline__ float blocksum256(float v) {
    __shared__ float red[8];
    int lane = threadIdx.x & 31, w = threadIdx.x >> 5;
    v = warpsum(v);
    if (lane == 0) red[w] = v;
    __syncthreads();
    float r = (lane < 8) ? red[lane] : 0.f;
    r = warpsum(r);
    __syncthreads();   // protect red[] for the next call
    return r;
}

__device__ __forceinline__ float gelu_f(float x) {
    float x3 = x * x * x;
    return 0.5f * x * (1.f + tanhf(0.79788456f * (x + 0.044715f * x3)));
}
__device__ __forceinline__ float gelu_bwd_f(float x) {
    float t = tanhf(0.79788456f * (x + 0.044715f * x * x * x));
    return 0.5f * x * (1.f - t * t) * (0.79788456f + 0.1070322243f * x * x) + 0.5f * (1.f + t);
}

// ---------------------------------------------------------------------------
// LayerNorm over rows of length 1024 (one block / row, 256 threads)
// ---------------------------------------------------------------------------
__global__ __launch_bounds__(256) void ln_kernel(
    const float* __restrict__ x, const float* __restrict__ g,
    const float* __restrict__ b, float* __restrict__ y)
{
    int row = blockIdx.x;
    int tid = threadIdx.x;
    const float* xr = x + (size_t)row * Dn;
    float v[4];
    float s = 0.f;
#pragma unroll
    for (int i = 0; i < 4; i++) { v[i] = xr[tid + 256 * i]; s += v[i]; }
    s = blocksum256(s);
    float mu = s * (1.f / Dn);
    float ss = 0.f;
#pragma unroll
    for (int i = 0; i < 4; i++) { float d = v[i] - mu; ss += d * d; }
    ss = blocksum256(ss);
    float rstd = rsqrtf(ss * (1.f / Dn) + EPSc);
    float* yr = y + (size_t)row * Dn;
#pragma unroll
    for (int i = 0; i < 4; i++) {
        int c = tid + 256 * i;
        yr[c] = (v[i] - mu) * rstd * g[c] + b[c];
    }
}

// ---------------------------------------------------------------------------
// GEMM: C[m,n] = sum_k A[m,k]*B[n,k]  (+bias[n]) with optional epilogues
//   gate!=null : C = res + tanh(gate[n]) * (dot + bias[n])
//   res !=null : C = res + dot (+bias)
// BM=128, BN=64, BK=16, 256 threads, 8x4 per thread.
// ---------------------------------------------------------------------------
__global__ __launch_bounds__(256) void gemm_nt_kernel(
    const float* __restrict__ A, const float* __restrict__ B, float* __restrict__ C,
    int M, int N, int K,
    const float* __restrict__ bias, const float* __restrict__ res,
    const float* __restrict__ gate)
{
    const int BM = 128, BN = 64, BK = 16;
    __shared__ float As[BK][BM];
    __shared__ float Bs[BK][BN];
    int bm = blockIdx.y * BM, bn = blockIdx.x * BN;
    int t = threadIdx.x;
    int tx = t & 15, ty = t >> 4;
    float acc[8][4];
#pragma unroll
    for (int i = 0; i < 8; i++)
#pragma unroll
        for (int j = 0; j < 4; j++) acc[i][j] = 0.f;

    int ar = t >> 1, akc = (t & 1) * 8;
    int br = t >> 2, bkc = (t & 3) * 4;
    const float* Ab = A + (size_t)(bm + ar) * K + akc;
    const float* Bb = B + (size_t)(bn + br) * K + bkc;

    for (int k0 = 0; k0 < K; k0 += BK) {
        float4 a0 = *(const float4*)(Ab + k0);
        float4 a1 = *(const float4*)(Ab + k0 + 4);
        As[akc + 0][ar] = a0.x; As[akc + 1][ar] = a0.y;
        As[akc + 2][ar] = a0.z; As[akc + 3][ar] = a0.w;
        As[akc + 4][ar] = a1.x; As[akc + 5][ar] = a1.y;
        As[akc + 6][ar] = a1.z; As[akc + 7][ar] = a1.w;
        float4 b0 = *(const float4*)(Bb + k0);
        Bs[bkc + 0][br] = b0.x; Bs[bkc + 1][br] = b0.y;
        Bs[bkc + 2][br] = b0.z; Bs[bkc + 3][br] = b0.w;
        __syncthreads();
#pragma unroll
        for (int kk = 0; kk < BK; kk++) {
            float ra[8], rb[4];
#pragma unroll
            for (int i = 0; i < 8; i++) ra[i] = As[kk][ty * 8 + i];
#pragma unroll
            for (int j = 0; j < 4; j++) rb[j] = Bs[kk][tx * 4 + j];
#pragma unroll
            for (int i = 0; i < 8; i++)
#pragma unroll
                for (int j = 0; j < 4; j++) acc[i][j] += ra[i] * rb[j];
        }
        __syncthreads();
    }

#pragma unroll
    for (int i = 0; i < 8; i++) {
        int m = bm + ty * 8 + i;
#pragma unroll
        for (int j = 0; j < 4; j++) {
            int n = bn + tx * 4 + j;
            float val = acc[i][j];
            if (bias) val += bias[n];
            if (gate)       val = res[(size_t)m * N + n] + tanhf(gate[n]) * val;
            else if (res)   val = res[(size_t)m * N + n] + val;
            C[(size_t)m * N + n] = val;
        }
    }
}

// ---------------------------------------------------------------------------
// Causal attention, online softmax, one warp per (b,h,s) query row.
// Scale 1/sqrt(64)=0.125 folded into q.
// ---------------------------------------------------------------------------
__global__ __launch_bounds__(256) void attn_kernel(
    const float* __restrict__ q, const float* __restrict__ k,
    const float* __restrict__ v, float* __restrict__ o)
{
    int w = (blockIdx.x * blockDim.x + threadIdx.x) >> 5;
    if (w >= Bn * Hn * Sn) return;
    int lane = threadIdx.x & 31;
    int s  = w & (Sn - 1);
    int bh = w >> 10;
    int b  = bh >> 4;
    int h  = bh & 15;

    size_t qb = ((size_t)(b * Sn + s) * Dn) + h * HDn;
    float q0 = q[qb + lane] * 0.125f;
    float q1 = q[qb + lane + 32] * 0.125f;

    float m = -1e30f, l = 0.f, a0 = 0.f, a1 = 0.f;
    size_t kb = ((size_t)b * Sn) * Dn + h * HDn;
    for (int j = 0; j <= s; j++) {
        size_t kk = kb + (size_t)j * Dn;
        float sc = q0 * k[kk + lane] + q1 * k[kk + lane + 32];
        sc = warpsum(sc);
        float nm = fmaxf(m, sc);
        float p    = expf(sc - nm);
        float corr = expf(m - nm);
        l  = l * corr + p;
        a0 = a0 * corr + p * v[kk + lane];
        a1 = a1 * corr + p * v[kk + lane + 32];
        m = nm;
    }
    float inv = 1.f / l;
    o[qb + lane]      = a0 * inv;
    o[qb + lane + 32] = a1 * inv;
}

// ---------------------------------------------------------------------------
// TTT prep: L2-normalize XQ and XK rows (per (b,s,h), HD=64);
// XV = ttt_nw * LN(XV) + ttt_nb + XK_normalized.   One warp per (b,s,h).
// ---------------------------------------------------------------------------
__global__ __launch_bounds__(256) void prep_kernel(
    float* __restrict__ XQ, float* __restrict__ XK, float* __restrict__ XV,
    const float* __restrict__ nw, const float* __restrict__ nb)
{
    int w = (blockIdx.x * blockDim.x + threadIdx.x) >> 5;
    if (w >= Bn * Sn * Hn) return;
    int lane = threadIdx.x & 31;
    int h = w & 15;
    int bs = w >> 4;
    size_t base = (size_t)bs * Dn + h * HDn;

    float q0 = XQ[base + lane], q1 = XQ[base + lane + 32];
    float qi = 1.f / fmaxf(sqrtf(warpsum(q0 * q0 + q1 * q1)), 1e-12f);
    XQ[base + lane]      = q0 * qi;
    XQ[base + lane + 32] = q1 * qi;

    float k0 = XK[base + lane], k1 = XK[base + lane + 32];
    float ki = 1.f / fmaxf(sqrtf(warpsum(k0 * k0 + k1 * k1)), 1e-12f);
    k0 *= ki; k1 *= ki;
    XK[base + lane]      = k0;
    XK[base + lane + 32] = k1;

    float v0 = XV[base + lane], v1 = XV[base + lane + 32];
    float mu = warpsum(v0 + v1) * (1.f / 64.f);
    float d0 = v0 - mu, d1 = v1 - mu;
    float var = warpsum(d0 * d0 + d1 * d1) * (1.f / 64.f);
    float rstd = rsqrtf(var + EPSc);
    XV[base + lane]      = nw[h * 64 + lane]      * d0 * rstd + nb[h * 64 + lane]      + k0;
    XV[base + lane + 32] = nw[h * 64 + lane + 32] * d1 * rstd + nb[h * 64 + lane + 32] + k1;
}

// ---------------------------------------------------------------------------
// Per-token learning rate: lr[b,h,s] = sigmoid(x1[b,s,:]·lr_w[h,:] + lr_b[h])
// One warp per (b,s,h).
// ---------------------------------------------------------------------------
__global__ __launch_bounds__(256) void lr_kernel(
    const float* __restrict__ x1, const float* __restrict__ lrw,
    const float* __restrict__ lrb, float* __restrict__ lro)
{
    int w = (blockIdx.x * blockDim.x + threadIdx.x) >> 5;
    if (w >= Bn * Sn * Hn) return;
    int lane = threadIdx.x & 31;
    int h = w & 15;
    int bs = w >> 4;
    int b = bs >> 10, s = bs & (Sn - 1);
    const float* xr = x1 + (size_t)bs * Dn;
    const float* wr = lrw + h * Dn;
    float acc = 0.f;
    for (int c = lane; c < Dn; c += 32) acc += xr[c] * wr[c];
    acc = warpsum(acc);
    if (lane == 0)
        lro[(size_t)(b * Hn + h) * Sn + s] = 1.f / (1.f + expf(-(acc + lrb[h])));
}

// ---------------------------------------------------------------------------
// TTT scan: one block per (b,h), sequential over NC=16 chunks.
// Dynamic smem tiles, stride-65 padding on 64x64 tiles.
// ---------------------------------------------------------------------------
#define TSx 65
#define SCAN_SMEM ((6 * 64 * TSx + 64) * 4)

__global__ __launch_bounds__(256) void ttt_scan_kernel(
    const float* __restrict__ XQ, const float* __restrict__ XK, const float* __restrict__ XV,
    const float* __restrict__ lr,
    const float* __restrict__ W1i, const float* __restrict__ b1i,
    const float* __restrict__ W2i, const float* __restrict__ b2i,
    const float* __restrict__ nw,  const float* __restrict__ nb,
    float* __restrict__ W1s, float* __restrict__ b1s,
    float* __restrict__ W2s, float* __restrict__ b2s,
    float* __restrict__ Z1t, float* __restrict__ X2t,
    float* __restrict__ gZ1t, float* __restrict__ X2bt,
    float* __restrict__ outp)
{
    extern __shared__ float sm[];
    float* sxq  = sm;
    float* sxk  = sxq  + 64 * TSx;
    float* sxv  = sxk  + 64 * TSx;
    float* sZ2  = sxv  + 64 * TSx;   // Z2, later Z2b
    float* sgZ2 = sZ2  + 64 * TSx;
    float* scoef= sgZ2 + 64 * TSx;
    float* seta = scoef+ 64 * TSx;   // [64]

    int bh = blockIdx.x;
    int b = bh >> 4, h = bh & 15;
    int tid = threadIdx.x;
    int warp = tid >> 5, lane = tid & 31;

    float* W1g = W1s + (size_t)bh * HDn * DFFn;
    float* b1g = b1s + (size_t)bh * DFFn;
    float* W2g = W2s + (size_t)bh * DFFn * HDn;
    float* b2g = b2s + (size_t)bh * HDn;
    float* Z1  = Z1t  + (size_t)bh * Cn * DFFn;
    float* X2  = X2t  + (size_t)bh * Cn * DFFn;
    float* gZ1 = gZ1t + (size_t)bh * Cn * DFFn;
    float* X2b = X2bt + (size_t)bh * Cn * DFFn;
    const float* nwh = nw + h * HDn;
    const float* nbh = nb + h * HDn;

    // init state from inputs
    for (int i = tid; i < HDn * DFFn; i += 256) {
        W1g[i] = W1i[(size_t)h * HDn * DFFn + i];
        W2g[i] = W2i[(size_t)h * DFFn * HDn + i];
    }
    if (tid < DFFn) b1g[tid] = b1i[h * DFFn + tid];
    if (tid < HDn)  b2g[tid] = b2i[h * HDn + tid];
    __syncthreads();

    for (int n = 0; n < NCn; n++) {
        size_t tokbase = (size_t)b * Sn + n * Cn;

        // load chunk tiles
        for (int idx = tid; idx < Cn * HDn; idx += 256) {
            int i = idx >> 6, e = idx & 63;
            size_t g = (tokbase + i) * Dn + h * HDn + e;
            sxq[i * TSx + e] = XQ[g];
            sxk[i * TSx + e] = XK[g];
            sxv[i * TSx + e] = XV[g];
        }
        if (tid < Cn) seta[tid] = lr[(size_t)(b * Hn + h) * Sn + n * Cn + tid] * (1.f / 64.f);
        __syncthreads();

        // A: Z1 = xk@W1 + b1 ; X2 = gelu(Z1)
        for (int it = 0; it < Cn; it++) {
            int i = it, j = tid;
            float acc = b1g[j];
            const float* xkr = sxk + i * TSx;
#pragma unroll 8
            for (int e = 0; e < HDn; e++) acc += xkr[e] * W1g[e * DFFn + j];
            Z1[i * DFFn + j] = acc;
            X2[i * DFFn + j] = gelu_f(acc);
        }
        __syncthreads();

        // B: Z2 = X2@W2 + b2
        for (int idx = tid; idx < Cn * HDn; idx += 256) {
            int i = idx >> 6, j = idx & 63;
            float acc = b2g[j];
            const float* x2r = X2 + i * DFFn;
#pragma unroll 8
            for (int f = 0; f < DFFn; f++) acc += x2r[f] * W2g[f * HDn + j];
            sZ2[i * TSx + j] = acc;
        }
        __syncthreads();

        // C: gZ2 = ln_l2_bwd(Z2, xv-xk, nw, nb), row-wise (warp per row)
        for (int i = warp; i < Cn; i += 8) {
            float z0 = sZ2[i * TSx + lane], z1 = sZ2[i * TSx + lane + 32];
            float mu = warpsum(z0 + z1) * (1.f / 64.f);
            float d0 = z0 - mu, d1 = z1 - mu;
            float var = warpsum(d0 * d0 + d1 * d1) * (1.f / 64.f);
            float rstd = rsqrtf(var + EPSc);
            float xh0 = d0 * rstd, xh1 = d1 * rstd;
            float g0 = nwh[lane], g1 = nwh[lane + 32];
            float bb0 = nbh[lane], bb1 = nbh[lane + 32];
            float t0 = sxv[i * TSx + lane]      - sxk[i * TSx + lane];
            float t1 = sxv[i * TSx + lane + 32] - sxk[i * TSx + lane + 32];
            float gh0 = (g0 * xh0 + bb0 - t0) * g0;
            float gh1 = (g1 * xh1 + bb1 - t1) * g1;
            float sgh = warpsum(gh0 + gh1);
            float sgx = warpsum(gh0 * xh0 + gh1 * xh1);
            float cc = rstd * (1.f / 64.f);
            sgZ2[i * TSx + lane]      = (64.f * gh0 - sgh - xh0 * sgx) * cc;
            sgZ2[i * TSx + lane + 32] = (64.f * gh1 - sgh - xh1 * sgx) * cc;
        }
        __syncthreads();

        // D: gZ1 = (gZ2 @ W2^T) * gelu_bwd(Z1)
        for (int it = 0; it < Cn; it++) {
            int i = it, j = tid;
            float acc = 0.f;
            const float* gz = sgZ2 + i * TSx;
            const float* w2r = W2g + (size_t)j * HDn;
#pragma unroll 8
            for (int e = 0; e < HDn; e++) acc += gz[e] * w2r[e];
            gZ1[i * DFFn + j] = acc * gelu_bwd_f(Z1[i * DFFn + j]);
        }
        __syncthreads();

        // E: coef1[i,k] = eta[k]*(A1[i,k]+1) for k<=i (A1 = tril(xq@xk^T))
        for (int idx = tid; idx < Cn * Cn; idx += 256) {
            int i = idx >> 6, j = idx & 63;
            float c = 0.f;
            if (j <= i) {
                float a = 0.f;
                const float* qa = sxq + i * TSx;
                const float* kb = sxk + j * TSx;
#pragma unroll 8
                for (int e = 0; e < HDn; e++) a += qa[e] * kb[e];
                c = seta[j] * (a + 1.f);
            }
            scoef[i * TSx + j] = c;
        }
        __syncthreads();

        // F: Z1b = xq@W1 + b1 - coef1@gZ1 ; X2b = gelu(Z1b)
        for (int it = 0; it < Cn; it++) {
            int i = it, j = tid;
            float acc = b1g[j];
            const float* qr = sxq + i * TSx;
#pragma unroll 8
            for (int e = 0; e < HDn; e++) acc += qr[e] * W1g[e * DFFn + j];
            const float* cf = scoef + i * TSx;
            for (int k2 = 0; k2 <= i; k2++) acc -= cf[k2] * gZ1[k2 * DFFn + j];
            X2b[i * DFFn + j] = gelu_f(acc);
        }
        __syncthreads();

        // G: coef2[i,k] = eta[k]*(A2[i,k]+1) for k<=i (A2 = tril(X2b@X2^T))
        for (int idx = tid; idx < Cn * Cn; idx += 256) {
            int i = idx >> 6, j = idx & 63;
            float c = 0.f;
            if (j <= i) {
                float a = 0.f;
                const float* xa = X2b + i * DFFn;
                const float* xb = X2  + j * DFFn;
#pragma unroll 8
                for (int f = 0; f < DFFn; f++) a += xa[f] * xb[f];
                c = seta[j] * (a + 1.f);
            }
            scoef[i * TSx + j] = c;
        }
        __syncthreads();

        // H: Z2b = X2b@W2 + b2 - coef2@gZ2  (into sZ2)
        for (int idx = tid; idx < Cn * HDn; idx += 256) {
            int i = idx >> 6, j = idx & 63;
            float acc = b2g[j];
            const float* xr = X2b + i * DFFn;
#pragma unroll 8
            for (int f = 0; f < DFFn; f++) acc += xr[f] * W2g[f * HDn + j];
            const float* cf = scoef + i * TSx;
            for (int k2 = 0; k2 <= i; k2++) acc -= cf[k2] * sgZ2[k2 * TSx + j];
            sZ2[i * TSx + j] = acc;
        }
        __syncthreads();

        // I: out = xq + LN(Z2b, nw, nb)
        for (int i = warp; i < Cn; i += 8) {
            float z0 = sZ2[i * TSx + lane], z1 = sZ2[i * TSx + lane + 32];
            float mu = warpsum(z0 + z1) * (1.f / 64.f);
            float d0 = z0 - mu, d1 = z1 - mu;
            float var = warpsum(d0 * d0 + d1 * d1) * (1.f / 64.f);
            float rstd = rsqrtf(var + EPSc);
            size_t g = (tokbase + i) * Dn + h * HDn;
            outp[g + lane]      = sxq[i * TSx + lane]      + nwh[lane]      * d0 * rstd + nbh[lane];
            outp[g + lane + 32] = sxq[i * TSx + lane + 32] + nwh[lane + 32] * d1 * rstd + nbh[lane + 32];
        }

        // J: state updates (reads all finished above; no extra sync needed here)
        for (int it = 0; it < HDn; it++) {
            int e = it, j = tid;
            float acc = 0.f;
#pragma unroll 8
            for (int i = 0; i < Cn; i++) acc += seta[i] * sxk[i * TSx + e] * gZ1[i * DFFn + j];
            W1g[e * DFFn + j] -= acc;
        }
        {
            int j = tid;  // 256 == DFF
            float acc = 0.f;
#pragma unroll 8
            for (int i = 0; i < Cn; i++) acc += seta[i] * gZ1[i * DFFn + j];
            b1g[j] -= acc;
        }
        for (int idx = tid; idx < DFFn * HDn; idx += 256) {
            int f = idx >> 6, j = idx & 63;
            float acc = 0.f;
#pragma unroll 8
            for (int i = 0; i < Cn; i++) acc += seta[i] * X2[i * DFFn + f] * sgZ2[i * TSx + j];
            W2g[f * HDn + j] -= acc;
        }
        if (tid < HDn) {
            int j = tid;
            float acc = 0.f;
#pragma unroll 8
            for (int i = 0; i < Cn; i++) acc += seta[i] * sgZ2[i * TSx + j];
            b2g[j] -= acc;
        }
        __syncthreads();
    }
}

// ---------------------------------------------------------------------------
// Launch
// ---------------------------------------------------------------------------
extern "C" void kernel_launch(void* const* d_in, const int* in_sizes, int n_in,
                              void* d_out, int out_size)
{
    const float* x       = (const float*)d_in[0];
    const float* ln1_w   = (const float*)d_in[1];
    const float* ln1_b   = (const float*)d_in[2];
    const float* attn_wq = (const float*)d_in[3];
    const float* attn_wk = (const float*)d_in[4];
    const float* attn_wv = (const float*)d_in[5];
    const float* attn_wo = (const float*)d_in[6];
    const float* wq_w    = (const float*)d_in[7];
    const float* wq_b    = (const float*)d_in[8];
    const float* wk_w    = (const float*)d_in[9];
    const float* wk_b    = (const float*)d_in[10];
    const float* wv_w    = (const float*)d_in[11];
    const float* wv_b    = (const float*)d_in[12];
    const float* wo_w    = (const float*)d_in[13];
    const float* wo_b    = (const float*)d_in[14];
    const float* W1      = (const float*)d_in[15];
    const float* b1      = (const float*)d_in[16];
    const float* W2      = (const float*)d_in[17];
    const float* b2      = (const float*)d_in[18];
    const float* ttt_nw  = (const float*)d_in[19];
    const float* ttt_nb  = (const float*)d_in[20];
    const float* lr_w    = (const float*)d_in[21];
    const float* lr_b    = (const float*)d_in[22];
    const float* pn_w    = (const float*)d_in[23];
    const float* pn_b    = (const float*)d_in[24];
    const float* gate_a  = (const float*)d_in[25];
    float* out = (float*)d_out;

    float *p_h, *p_q, *p_k, *p_v, *p_o, *p_x1, *p_lr;
    float *p_W1s, *p_b1s, *p_W2s, *p_b2s, *p_Z1, *p_X2, *p_gZ1, *p_X2b;
    cudaGetSymbolAddress((void**)&p_h,  g_h);
    cudaGetSymbolAddress((void**)&p_q,  g_q);
    cudaGetSymbolAddress((void**)&p_k,  g_k);
    cudaGetSymbolAddress((void**)&p_v,  g_v);
    cudaGetSymbolAddress((void**)&p_o,  g_o);
    cudaGetSymbolAddress((void**)&p_x1, g_x1);
    cudaGetSymbolAddress((void**)&p_lr, g_lr);
    cudaGetSymbolAddress((void**)&p_W1s, g_W1s);
    cudaGetSymbolAddress((void**)&p_b1s, g_b1s);
    cudaGetSymbolAddress((void**)&p_W2s, g_W2s);
    cudaGetSymbolAddress((void**)&p_b2s, g_b2s);
    cudaGetSymbolAddress((void**)&p_Z1,  g_Z1t);
    cudaGetSymbolAddress((void**)&p_X2,  g_X2t);
    cudaGetSymbolAddress((void**)&p_gZ1, g_gZ1t);
    cudaGetSymbolAddress((void**)&p_X2b, g_X2bt);

    cudaFuncSetAttribute(ttt_scan_kernel,
                         cudaFuncAttributeMaxDynamicSharedMemorySize, SCAN_SMEM);

    const int M = Bn * Sn;           // 4096
    dim3 ggrid(Dn / 64, M / 128);    // (16, 32)
    int nwarp_grid = (Bn * Sn * Hn) / 8;  // 8192 blocks of 256 threads (8 warps)

    // 1) LN1
    ln_kernel<<<M, 256>>>(x, ln1_w, ln1_b, p_h);
    // 2-4) q, k, v
    gemm_nt_kernel<<<ggrid, 256>>>(p_h, attn_wq, p_q, M, Dn, Dn, nullptr, nullptr, nullptr);
    gemm_nt_kernel<<<ggrid, 256>>>(p_h, attn_wk, p_k, M, Dn, Dn, nullptr, nullptr, nullptr);
    gemm_nt_kernel<<<ggrid, 256>>>(p_h, attn_wv, p_v, M, Dn, Dn, nullptr, nullptr, nullptr);
    // 5) attention
    attn_kernel<<<nwarp_grid, 256>>>(p_q, p_k, p_v, p_o);
    // 6) x1 = x + o @ wo^T
    gemm_nt_kernel<<<ggrid, 256>>>(p_o, attn_wo, p_x1, M, Dn, Dn, nullptr, x, nullptr);
    // 7-9) XQ, XK, XV (reuse q/k/v buffers)
    gemm_nt_kernel<<<ggrid, 256>>>(p_x1, wq_w, p_q, M, Dn, Dn, wq_b, nullptr, nullptr);
    gemm_nt_kernel<<<ggrid, 256>>>(p_x1, wk_w, p_k, M, Dn, Dn, wk_b, nullptr, nullptr);
    gemm_nt_kernel<<<ggrid, 256>>>(p_x1, wv_w, p_v, M, Dn, Dn, wv_b, nullptr, nullptr);
    // 10) normalize XQ/XK, build XV
    prep_kernel<<<nwarp_grid, 256>>>(p_q, p_k, p_v, ttt_nw, ttt_nb);
    // 11) learning rates
    lr_kernel<<<nwarp_grid, 256>>>(p_x1, lr_w, lr_b, p_lr);
    // 12) TTT scan (ttt_out into p_o)
    ttt_scan_kernel<<<Bn * Hn, 256, SCAN_SMEM>>>(
        p_q, p_k, p_v, p_lr, W1, b1, W2, b2, ttt_nw, ttt_nb,
        p_W1s, p_b1s, p_W2s, p_b2s, p_Z1, p_X2, p_gZ1, p_X2b, p_o);
    // 13) post-LN (into p_h)
    ln_kernel<<<M, 256>>>(p_o, pn_w, pn_b, p_h);
    // 14) out = residual + tanh(gate) * (LN @ wo_w^T + wo_b)
    gemm_nt_kernel<<<ggrid, 256>>>(p_h, wo_w, out, M, Dn, Dn, wo_b, p_x1, gate_a);
}

// round 2
// speedup vs baseline: 1.0047x; 1.0047x over previous
#include <cuda_runtime.h>
#include <cuda_bf16.h>
#include <math.h>

// ---------------------------------------------------------------------------
// Problem constants
// ---------------------------------------------------------------------------
#define Bn   4
#define Sn   1024
#define Dn   1024
#define Hn   16
#define HDn  64
#define Cn   64
#define NCn  16
#define DFFn 256
#define EPSc 1e-6f
#define BSD  (Bn*Sn*Dn)

// ---------------------------------------------------------------------------
// Device scratch (static allocation — no cudaMalloc allowed)
// ---------------------------------------------------------------------------
__device__ float g_h [BSD];   // LN1 output; later reused for post-LN output
__device__ float g_q [BSD];   // q; later reused for XQ
__device__ float g_k [BSD];   // k; later reused for XK
__device__ float g_v [BSD];   // v; later reused for XV
__device__ float g_o [BSD];   // attention out; later reused for ttt_out
__device__ float g_x1[BSD];   // x after attention residual (= "residual")
__device__ float g_lr[Bn*Hn*Sn];

// TTT state per (b,h)
__device__ float g_W1s[Bn*Hn*HDn*DFFn];
__device__ float g_b1s[Bn*Hn*DFFn];
__device__ float g_W2s[Bn*Hn*DFFn*HDn];
__device__ float g_b2s[Bn*Hn*HDn];
// TTT per-chunk temporaries per (b,h)
__device__ float g_Z1t [Bn*Hn*Cn*DFFn];
__device__ float g_X2t [Bn*Hn*Cn*DFFn];
__device__ float g_gZ1t[Bn*Hn*Cn*DFFn];
__device__ float g_X2bt[Bn*Hn*Cn*DFFn];

// ---------------------------------------------------------------------------
// Helpers
// ---------------------------------------------------------------------------
__device__ __forceinline__ float warpsum(float v) {
#pragma unroll
    for (int o = 16; o > 0; o >>= 1) v += __shfl_xor_sync(0xffffffffu, v, o);
    return v;
}

// block (256 threads) all-reduce sum
__device__ __forceinline__ float blocksum256(float v) {
    __shared__ float red[8];
    int lane = threadIdx.x & 31, w = threadIdx.x >> 5;
    v = warpsum(v);
    if (lane == 0) red[w] = v;
    __syncthreads();
    float r = (lane < 8) ? red[lane] : 0.f;
    r = warpsum(r);
    __syncthreads();   // protect red[] for the next call
    return r;
}

__device__ __forceinline__ float gelu_f(float x) {
    float x3 = x * x * x;
    return 0.5f * x * (1.f + tanhf(0.79788456f * (x + 0.044715f * x3)));
}
__device__ __forceinline__ float gelu_bwd_f(float x) {
    float t = tanhf(0.79788456f * (x + 0.044715f * x * x * x));
    return 0.5f * x * (1.f - t * t) * (0.79788456f + 0.1070322243f * x * x) + 0.5f * (1.f + t);
}

// ---------------------------------------------------------------------------
// LayerNorm over rows of length 1024 (one block / row, 256 threads)
// ---------------------------------------------------------------------------
__global__ __launch_bounds__(256) void ln_kernel(
    const float* __restrict__ x, const float* __restrict__ g,
    const float* __restrict__ b, float* __restrict__ y)
{
    int row = blockIdx.x;
    int tid = threadIdx.x;
    const float* xr = x + (size_t)row * Dn;
    float v[4];
    float s = 0.f;
#pragma unroll
    for (int i = 0; i < 4; i++) { v[i] = xr[tid + 256 * i]; s += v[i]; }
    s = blocksum256(s);
    float mu = s * (1.f / Dn);
    float ss = 0.f;
#pragma unroll
    for (int i = 0; i < 4; i++) { float d = v[i] - mu; ss += d * d; }
    ss = blocksum256(ss);
    float rstd = rsqrtf(ss * (1.f / Dn) + EPSc);
    float* yr = y + (size_t)row * Dn;
#pragma unroll
    for (int i = 0; i < 4; i++) {
        int c = tid + 256 * i;
        yr[c] = (v[i] - mu) * rstd * g[c] + b[c];
    }
}

// ---------------------------------------------------------------------------
// GEMM: C[m,n] = sum_k A[m,k]*B[n,k]  (+bias[n]) with optional epilogues
//   gate!=null : C = res + tanh(gate[n]) * (dot + bias[n])
//   res !=null : C = res + dot (+bias)
// BM=128, BN=64, BK=16, 256 threads, 8x4 per thread.
// ---------------------------------------------------------------------------
__global__ __launch_bounds__(256) void gemm_nt_kernel(
    const float* __restrict__ A, const float* __restrict__ B, float* __restrict__ C,
    int M, int N, int K,
    const float* __restrict__ bias, const float* __restrict__ res,
    const float* __restrict__ gate)
{
    const int BM = 128, BN = 64, BK = 16;
    __shared__ float As[BK][BM];
    __shared__ float Bs[BK][BN];
    int bm = blockIdx.y * BM, bn = blockIdx.x * BN;
    int t = threadIdx.x;
    int tx = t & 15, ty = t >> 4;
    float acc[8][4];
#pragma unroll
    for (int i = 0; i < 8; i++)
#pragma unroll
        for (int j = 0; j < 4; j++) acc[i][j] = 0.f;

    int ar = t >> 1, akc = (t & 1) * 8;
    int br = t >> 2, bkc = (t & 3) * 4;
    const float* Ab = A + (size_t)(bm + ar) * K + akc;
    const float* Bb = B + (size_t)(bn + br) * K + bkc;

    for (int k0 = 0; k0 < K; k0 += BK) {
        float4 a0 = *(const float4*)(Ab + k0);
        float4 a1 = *(const float4*)(Ab + k0 + 4);
        As[akc + 0][ar] = a0.x; As[akc + 1][ar] = a0.y;
        As[akc + 2][ar] = a0.z; As[akc + 3][ar] = a0.w;
        As[akc + 4][ar] = a1.x; As[akc + 5][ar] = a1.y;
        As[akc + 6][ar] = a1.z; As[akc + 7][ar] = a1.w;
        float4 b0 = *(const float4*)(Bb + k0);
        Bs[bkc + 0][br] = b0.x; Bs[bkc + 1][br] = b0.y;
        Bs[bkc + 2][br] = b0.z; Bs[bkc + 3][br] = b0.w;
        __syncthreads();
#pragma unroll
        for (int kk = 0; kk < BK; kk++) {
            float ra[8], rb[4];
#pragma unroll
            for (int i = 0; i < 8; i++) ra[i] = As[kk][ty * 8 + i];
#pragma unroll
            for (int j = 0; j < 4; j++) rb[j] = Bs[kk][tx * 4 + j];
#pragma unroll
            for (int i = 0; i < 8; i++)
#pragma unroll
                for (int j = 0; j < 4; j++) acc[i][j] += ra[i] * rb[j];
        }
        __syncthreads();
    }

#pragma unroll
    for (int i = 0; i < 8; i++) {
        int m = bm + ty * 8 + i;
#pragma unroll
        for (int j = 0; j < 4; j++) {
            int n = bn + tx * 4 + j;
            float val = acc[i][j];
            if (bias) val += bias[n];
            if (gate)       val = res[(size_t)m * N + n] + tanhf(gate[n]) * val;
            else if (res)   val = res[(size_t)m * N + n] + val;
            C[(size_t)m * N + n] = val;
        }
    }
}

// ---------------------------------------------------------------------------
// Causal attention, online softmax, one warp per (b,h,s) query row.
// Scale 1/sqrt(64)=0.125 folded into q.
// ---------------------------------------------------------------------------
__global__ __launch_bounds__(256) void attn_kernel(
    const float* __restrict__ q, const float* __restrict__ k,
    const float* __restrict__ v, float* __restrict__ o)
{
    int w = (blockIdx.x * blockDim.x + threadIdx.x) >> 5;
    if (w >= Bn * Hn * Sn) return;
    int lane = threadIdx.x & 31;
    int s  = w & (Sn - 1);
    int bh = w >> 10;
    int b  = bh >> 4;
    int h  = bh & 15;

    size_t qb = ((size_t)(b * Sn + s) * Dn) + h * HDn;
    float q0 = q[qb + lane] * 0.125f;
    float q1 = q[qb + lane + 32] * 0.125f;

    float m = -1e30f, l = 0.f, a0 = 0.f, a1 = 0.f;
    size_t kb = ((size_t)b * Sn) * Dn + h * HDn;
    for (int j = 0; j <= s; j++) {
        size_t kk = kb + (size_t)j * Dn;
        float sc = q0 * k[kk + lane] + q1 * k[kk + lane + 32];
        sc = warpsum(sc);
        float nm = fmaxf(m, sc);
        float p    = expf(sc - nm);
        float corr = expf(m - nm);
        l  = l * corr + p;
        a0 = a0 * corr + p * v[kk + lane];
        a1 = a1 * corr + p * v[kk + lane + 32];
        m = nm;
    }
    float inv = 1.f / l;
    o[qb + lane]      = a0 * inv;
    o[qb + lane + 32] = a1 * inv;
}

// ---------------------------------------------------------------------------
// TTT prep: L2-normalize XQ and XK rows (per (b,s,h), HD=64);
// XV = ttt_nw * LN(XV) + ttt_nb + XK_normalized.   One warp per (b,s,h).
// ---------------------------------------------------------------------------
__global__ __launch_bounds__(256) void prep_kernel(
    float* __restrict__ XQ, float* __restrict__ XK, float* __restrict__ XV,
    const float* __restrict__ nw, const float* __restrict__ nb)
{
    int w = (blockIdx.x * blockDim.x + threadIdx.x) >> 5;
    if (w >= Bn * Sn * Hn) return;
    int lane = threadIdx.x & 31;
    int h = w & 15;
    int bs = w >> 4;
    size_t base = (size_t)bs * Dn + h * HDn;

    float q0 = XQ[base + lane], q1 = XQ[base + lane + 32];
    float qi = 1.f / fmaxf(sqrtf(warpsum(q0 * q0 + q1 * q1)), 1e-12f);
    XQ[base + lane]      = q0 * qi;
    XQ[base + lane + 32] = q1 * qi;

    float k0 = XK[base + lane], k1 = XK[base + lane + 32];
    float ki = 1.f / fmaxf(sqrtf(warpsum(k0 * k0 + k1 * k1)), 1e-12f);
    k0 *= ki; k1 *= ki;
    XK[base + lane]      = k0;
    XK[base + lane + 32] = k1;

    float v0 = XV[base + lane], v1 = XV[base + lane + 32];
    float mu = warpsum(v0 + v1) * (1.f / 64.f);
    float d0 = v0 - mu, d1 = v1 - mu;
    float var = warpsum(d0 * d0 + d1 * d1) * (1.f / 64.f);
    float rstd = rsqrtf(var + EPSc);
    XV[base + lane]      = nw[h * 64 + lane]      * d0 * rstd + nb[h * 64 + lane]      + k0;
    XV[base + lane + 32] = nw[h * 64 + lane + 32] * d1 * rstd + nb[h * 64 + lane + 32] + k1;
}

// ---------------------------------------------------------------------------
// Per-token learning rate: lr[b,h,s] = sigmoid(x1[b,s,:]·lr_w[h,:] + lr_b[h])
// One warp per (b,s,h).
// ---------------------------------------------------------------------------
__global__ __launch_bounds__(256) void lr_kernel(
    const float* __restrict__ x1, const float* __restrict__ lrw,
    const float* __restrict__ lrb, float* __restrict__ lro)
{
    int w = (blockIdx.x * blockDim.x + threadIdx.x) >> 5;
    if (w >= Bn * Sn * Hn) return;
    int lane = threadIdx.x & 31;
    int h = w & 15;
    int bs = w >> 4;
    int b = bs >> 10, s = bs & (Sn - 1);
    const float* xr = x1 + (size_t)bs * Dn;
    const float* wr = lrw + h * Dn;
    float acc = 0.f;
    for (int c = lane; c < Dn; c += 32) acc += xr[c] * wr[c];
    acc = warpsum(acc);
    if (lane == 0)
        lro[(size_t)(b * Hn + h) * Sn + s] = 1.f / (1.f + expf(-(acc + lrb[h])));
}

// ---------------------------------------------------------------------------
// TTT scan: one block per (b,h), sequential over NC=16 chunks.
// Dynamic smem tiles, stride-65 padding on 64x64 tiles.
// ---------------------------------------------------------------------------
#define TSx 65
#define SCAN_SMEM ((6 * 64 * TSx + 64) * 4)

__global__ __launch_bounds__(256) void ttt_scan_kernel(
    const float* __restrict__ XQ, const float* __restrict__ XK, const float* __restrict__ XV,
    const float* __restrict__ lr,
    const float* __restrict__ W1i, const float* __restrict__ b1i,
    const float* __restrict__ W2i, const float* __restrict__ b2i,
    const float* __restrict__ nw,  const float* __restrict__ nb,
    float* __restrict__ W1s, float* __restrict__ b1s,
    float* __restrict__ W2s, float* __restrict__ b2s,
    float* __restrict__ Z1t, float* __restrict__ X2t,
    float* __restrict__ gZ1t, float* __restrict__ X2bt,
    float* __restrict__ outp)
{
    extern __shared__ float sm[];
    float* sxq  = sm;
    float* sxk  = sxq  + 64 * TSx;
    float* sxv  = sxk  + 64 * TSx;
    float* sZ2  = sxv  + 64 * TSx;   // Z2, later Z2b
    float* sgZ2 = sZ2  + 64 * TSx;
    float* scoef= sgZ2 + 64 * TSx;
    float* seta = scoef+ 64 * TSx;   // [64]

    int bh = blockIdx.x;
    int b = bh >> 4, h = bh & 15;
    int tid = threadIdx.x;
    int warp = tid >> 5, lane = tid & 31;

    float* W1g = W1s + (size_t)bh * HDn * DFFn;
    float* b1g = b1s + (size_t)bh * DFFn;
    float* W2g = W2s + (size_t)bh * DFFn * HDn;
    float* b2g = b2s + (size_t)bh * HDn;
    float* Z1  = Z1t  + (size_t)bh * Cn * DFFn;
    float* X2  = X2t  + (size_t)bh * Cn * DFFn;
    float* gZ1 = gZ1t + (size_t)bh * Cn * DFFn;
    float* X2b = X2bt + (size_t)bh * Cn * DFFn;
    const float* nwh = nw + h * HDn;
    const float* nbh = nb + h * HDn;

    // init state from inputs
    for (int i = tid; i < HDn * DFFn; i += 256) {
        W1g[i] = W1i[(size_t)h * HDn * DFFn + i];
        W2g[i] = W2i[(size_t)h * DFFn * HDn + i];
    }
    if (tid < DFFn) b1g[tid] = b1i[h * DFFn + tid];
    if (tid < HDn)  b2g[tid] = b2i[h * HDn + tid];
    __syncthreads();

    for (int n = 0; n < NCn; n++) {
        size_t tokbase = (size_t)b * Sn + n * Cn;

        // load chunk tiles
        for (int idx = tid; idx < Cn * HDn; idx += 256) {
            int i = idx >> 6, e = idx & 63;
            size_t g = (tokbase + i) * Dn + h * HDn + e;
            sxq[i * TSx + e] = XQ[g];
            sxk[i * TSx + e] = XK[g];
            sxv[i * TSx + e] = XV[g];
        }
        if (tid < Cn) seta[tid] = lr[(size_t)(b * Hn + h) * Sn + n * Cn + tid] * (1.f / 64.f);
        __syncthreads();

        // A: Z1 = xk@W1 + b1 ; X2 = gelu(Z1)
        for (int it = 0; it < Cn; it++) {
            int i = it, j = tid;
            float acc = b1g[j];
            const float* xkr = sxk + i * TSx;
#pragma unroll 8
            for (int e = 0; e < HDn; e++) acc += xkr[e] * W1g[e * DFFn + j];
            Z1[i * DFFn + j] = acc;
            X2[i * DFFn + j] = gelu_f(acc);
        }
        __syncthreads();

        // B: Z2 = X2@W2 + b2
        for (int idx = tid; idx < Cn * HDn; idx += 256) {
            int i = idx >> 6, j = idx & 63;
            float acc = b2g[j];
            const float* x2r = X2 + i * DFFn;
#pragma unroll 8
            for (int f = 0; f < DFFn; f++) acc += x2r[f] * W2g[f * HDn + j];
            sZ2[i * TSx + j] = acc;
        }
        __syncthreads();

        // C: gZ2 = ln_l2_bwd(Z2, xv-xk, nw, nb), row-wise (warp per row)
        for (int i = warp; i < Cn; i += 8) {
            float z0 = sZ2[i * TSx + lane], z1 = sZ2[i * TSx + lane + 32];
            float mu = warpsum(z0 + z1) * (1.f / 64.f);
            float d0 = z0 - mu, d1 = z1 - mu;
            float var = warpsum(d0 * d0 + d1 * d1) * (1.f / 64.f);
            float rstd = rsqrtf(var + EPSc);
            float xh0 = d0 * rstd, xh1 = d1 * rstd;
            float g0 = nwh[lane], g1 = nwh[lane + 32];
            float bb0 = nbh[lane], bb1 = nbh[lane + 32];
            float t0 = sxv[i * TSx + lane]      - sxk[i * TSx + lane];
            float t1 = sxv[i * TSx + lane + 32] - sxk[i * TSx + lane + 32];
            float gh0 = (g0 * xh0 + bb0 - t0) * g0;
            float gh1 = (g1 * xh1 + bb1 - t1) * g1;
            float sgh = warpsum(gh0 + gh1);
            float sgx = warpsum(gh0 * xh0 + gh1 * xh1);
            float cc = rstd * (1.f / 64.f);
            sgZ2[i * TSx + lane]      = (64.f * gh0 - sgh - xh0 * sgx) * cc;
            sgZ2[i * TSx + lane + 32] = (64.f * gh1 - sgh - xh1 * sgx) * cc;
        }
        __syncthreads();

        // D: gZ1 = (gZ2 @ W2^T) * gelu_bwd(Z1)
        for (int it = 0; it < Cn; it++) {
            int i = it, j = tid;
            float acc = 0.f;
            const float* gz = sgZ2 + i * TSx;
            const float* w2r = W2g + (size_t)j * HDn;
#pragma unroll 8
            for (int e = 0; e < HDn; e++) acc += gz[e] * w2r[e];
            gZ1[i * DFFn + j] = acc * gelu_bwd_f(Z1[i * DFFn + j]);
        }
        __syncthreads();

        // E: coef1[i,k] = eta[k]*(A1[i,k]+1) for k<=i (A1 = tril(xq@xk^T))
        for (int idx = tid; idx < Cn * Cn; idx += 256) {
            int i = idx >> 6, j = idx & 63;
            float c = 0.f;
            if (j <= i) {
                float a = 0.f;
                const float* qa = sxq + i * TSx;
                const float* kb = sxk + j * TSx;
#pragma unroll 8
                for (int e = 0; e < HDn; e++) a += qa[e] * kb[e];
                c = seta[j] * (a + 1.f);
            }
            scoef[i * TSx + j] = c;
        }
        __syncthreads();

        // F: Z1b = xq@W1 + b1 - coef1@gZ1 ; X2b = gelu(Z1b)
        for (int it = 0; it < Cn; it++) {
            int i = it, j = tid;
            float acc = b1g[j];
            const float* qr = sxq + i * TSx;
#pragma unroll 8
            for (int e = 0; e < HDn; e++) acc += qr[e] * W1g[e * DFFn + j];
            const float* cf = scoef + i * TSx;
            for (int k2 = 0; k2 <= i; k2++) acc -= cf[k2] * gZ1[k2 * DFFn + j];
            X2b[i * DFFn + j] = gelu_f(acc);
        }
        __syncthreads();

        // G: coef2[i,k] = eta[k]*(A2[i,k]+1) for k<=i (A2 = tril(X2b@X2^T))
        for (int idx = tid; idx < Cn * Cn; idx += 256) {
            int i = idx >> 6, j = idx & 63;
            float c = 0.f;
            if (j <= i) {
                float a = 0.f;
                const float* xa = X2b + i * DFFn;
                const float* xb = X2  + j * DFFn;
#pragma unroll 8
                for (int f = 0; f < DFFn; f++) a += xa[f] * xb[f];
                c = seta[j] * (a + 1.f);
            }
            scoef[i * TSx + j] = c;
        }
        __syncthreads();

        // H: Z2b = X2b@W2 + b2 - coef2@gZ2  (into sZ2)
        for (int idx = tid; idx < Cn * HDn; idx += 256) {
            int i = idx >> 6, j = idx & 63;
            float acc = b2g[j];
            const float* xr = X2b + i * DFFn;
#pragma unroll 8
            for (int f = 0; f < DFFn; f++) acc += xr[f] * W2g[f * HDn + j];
            const float* cf = scoef + i * TSx;
            for (int k2 = 0; k2 <= i; k2++) acc -= cf[k2] * sgZ2[k2 * TSx + j];
            sZ2[i * TSx + j] = acc;
        }
        __syncthreads();

        // I: out = xq + LN(Z2b, nw, nb)
        for (int i = warp; i < Cn; i += 8) {
            float z0 = sZ2[i * TSx + lane], z1 = sZ2[i * TSx + lane + 32];
            float mu = warpsum(z0 + z1) * (1.f / 64.f);
            float d0 = z0 - mu, d1 = z1 - mu;
            float var = warpsum(d0 * d0 + d1 * d1) * (1.f / 64.f);
            float rstd = rsqrtf(var + EPSc);
            size_t g = (tokbase + i) * Dn + h * HDn;
            outp[g + lane]      = sxq[i * TSx + lane]      + nwh[lane]      * d0 * rstd + nbh[lane];
            outp[g + lane + 32] = sxq[i * TSx + lane + 32] + nwh[lane + 32] * d1 * rstd + nbh[lane + 32];
        }

        // J: state updates (reads all finished above; no extra sync needed here)
        for (int it = 0; it < HDn; it++) {
            int e = it, j = tid;
            float acc = 0.f;
#pragma unroll 8
            for (int i = 0; i < Cn; i++) acc += seta[i] * sxk[i * TSx + e] * gZ1[i * DFFn + j];
            W1g[e * DFFn + j] -= acc;
        }
        {
            int j = tid;  // 256 == DFF
            float acc = 0.f;
#pragma unroll 8
            for (int i = 0; i < Cn; i++) acc += seta[i] * gZ1[i * DFFn + j];
            b1g[j] -= acc;
        }
        for (int idx = tid; idx < DFFn * HDn; idx += 256) {
            int f = idx >> 6, j = idx & 63;
            float acc = 0.f;
#pragma unroll 8
            for (int i = 0; i < Cn; i++) acc += seta[i] * X2[i * DFFn + f] * sgZ2[i * TSx + j];
            W2g[f * HDn + j] -= acc;
        }
        if (tid < HDn) {
            int j = tid;
            float acc = 0.f;
#pragma unroll 8
            for (int i = 0; i < Cn; i++) acc += seta[i] * sgZ2[i * TSx + j];
            b2g[j] -= acc;
        }
        __syncthreads();
    }
}

// ---------------------------------------------------------------------------
// Launch
// ---------------------------------------------------------------------------
extern "C" void kernel_launch(void* const* d_in, const int* in_sizes, int n_in,
                              void* d_out, int out_size)
{
    const float* x       = (const float*)d_in[0];
    const float* ln1_w   = (const float*)d_in[1];
    const float* ln1_b   = (const float*)d_in[2];
    const float* attn_wq = (const float*)d_in[3];
    const float* attn_wk = (const float*)d_in[4];
    const float* attn_wv = (const float*)d_in[5];
    const float* attn_wo = (const float*)d_in[6];
    const float* wq_w    = (const float*)d_in[7];
    const float* wq_b    = (const float*)d_in[8];
    const float* wk_w    = (const float*)d_in[9];
    const float* wk_b    = (const float*)d_in[10];
    const float* wv_w    = (const float*)d_in[11];
    const float* wv_b    = (const float*)d_in[12];
    const float* wo_w    = (const float*)d_in[13];
    const float* wo_b    = (const float*)d_in[14];
    const float* W1      = (const float*)d_in[15];
    const float* b1      = (const float*)d_in[16];
    const float* W2      = (const float*)d_in[17];
    const float* b2      = (const float*)d_in[18];
    const float* ttt_nw  = (const float*)d_in[19];
    const float* ttt_nb  = (const float*)d_in[20];
    const float* lr_w    = (const float*)d_in[21];
    const float* lr_b    = (const float*)d_in[22];
    const float* pn_w    = (const float*)d_in[23];
    const float* pn_b    = (const float*)d_in[24];
    const float* gate_a  = (const float*)d_in[25];
    float* out = (float*)d_out;

    float *p_h, *p_q, *p_k, *p_v, *p_o, *p_x1, *p_lr;
    float *p_W1s, *p_b1s, *p_W2s, *p_b2s, *p_Z1, *p_X2, *p_gZ1, *p_X2b;
    cudaGetSymbolAddress((void**)&p_h,  g_h);
    cudaGetSymbolAddress((void**)&p_q,  g_q);
    cudaGetSymbolAddress((void**)&p_k,  g_k);
    cudaGetSymbolAddress((void**)&p_v,  g_v);
    cudaGetSymbolAddress((void**)&p_o,  g_o);
    cudaGetSymbolAddress((void**)&p_x1, g_x1);
    cudaGetSymbolAddress((void**)&p_lr, g_lr);
    cudaGetSymbolAddress((void**)&p_W1s, g_W1s);
    cudaGetSymbolAddress((void**)&p_b1s, g_b1s);
    cudaGetSymbolAddress((void**)&p_W2s, g_W2s);
    cudaGetSymbolAddress((void**)&p_b2s, g_b2s);
    cudaGetSymbolAddress((void**)&p_Z1,  g_Z1t);
    cudaGetSymbolAddress((void**)&p_X2,  g_X2t);
    cudaGetSymbolAddress((void**)&p_gZ1, g_gZ1t);
    cudaGetSymbolAddress((void**)&p_X2b, g_X2bt);

    cudaFuncSetAttribute(ttt_scan_kernel,
                         cudaFuncAttributeMaxDynamicSharedMemorySize, SCAN_SMEM);

    const int M = Bn * Sn;           // 4096
    dim3 ggrid(Dn / 64, M / 128);    // (16, 32)
    int nwarp_grid = (Bn * Sn * Hn) / 8;  // 8192 blocks of 256 threads (8 warps)

    // 1) LN1
    ln_kernel<<<M, 256>>>(x, ln1_w, ln1_b, p_h);
    // 2-4) q, k, v
    gemm_nt_kernel<<<ggrid, 256>>>(p_h, attn_wq, p_q, M, Dn, Dn, nullptr, nullptr, nullptr);
    gemm_nt_kernel<<<ggrid, 256>>>(p_h, attn_wk, p_k, M, Dn, Dn, nullptr, nullptr, nullptr);
    gemm_nt_kernel<<<ggrid, 256>>>(p_h, attn_wv, p_v, M, Dn, Dn, nullptr, nullptr, nullptr);
    // 5) attention
    attn_kernel<<<nwarp_grid, 256>>>(p_q, p_k, p_v, p_o);
    // 6) x1 = x + o @ wo^T
    gemm_nt_kernel<<<ggrid, 256>>>(p_o, attn_wo, p_x1, M, Dn, Dn, nullptr, x, nullptr);
    // 7-9) XQ, XK, XV (reuse q/k/v buffers)
    gemm_nt_kernel<<<ggrid, 256>>>(p_x1, wq_w, p_q, M, Dn, Dn, wq_b, nullptr, nullptr);
    gemm_nt_kernel<<<ggrid, 256>>>(p_x1, wk_w, p_k, M, Dn, Dn, wk_b, nullptr, nullptr);
    gemm_nt_kernel<<<ggrid, 256>>>(p_x1, wv_w, p_v, M, Dn, Dn, wv_b, nullptr, nullptr);
    // 10) normalize XQ/XK, build XV
    prep_kernel<<<nwarp_grid, 256>>>(p_q, p_k, p_v, ttt_nw, ttt_nb);
    // 11) learning rates
    lr_kernel<<<nwarp_grid, 256>>>(p_x1, lr_w, lr_b, p_lr);
    // 12) TTT scan (ttt_out into p_o)
    ttt_scan_kernel<<<Bn * Hn, 256, SCAN_SMEM>>>(
        p_q, p_k, p_v, p_lr, W1, b1, W2, b2, ttt_nw, ttt_nb,
        p_W1s, p_b1s, p_W2s, p_b2s, p_Z1, p_X2, p_gZ1, p_X2b, p_o);
    // 13) post-LN (into p_h)
    ln_kernel<<<M, 256>>>(p_o, pn_w, pn_b, p_h);
    // 14) out = residual + tanh(gate) * (LN @ wo_w^T + wo_b)
    gemm_nt_kernel<<<ggrid, 256>>>(p_h, wo_w, out, M, Dn, Dn, wo_b, p_x1, gate_a);
}

// round 3
// speedup vs baseline: 6.8072x; 6.7757x over previous
#include <cuda_runtime.h>
#include <math.h>

#define Bn 4
#define Sn 1024
#define Dn 1024
#define Hn 16
#define HDn 64
#define Cn 64
#define NCn 16
#define DFFn 256
#define EPSc 1e-6f
#define BSD (Bn*Sn*Dn)

__device__ float g_h [BSD];
__device__ float g_q [BSD];
__device__ float g_k [BSD];
__device__ float g_v [BSD];
__device__ float g_o [BSD];
__device__ float g_x1[BSD];
__device__ float g_lr[Bn*Hn*Sn];
__device__ float g_W1s [Bn*Hn*16384];
__device__ float g_W2s [Bn*Hn*16384];
__device__ float g_W2Ts[Bn*Hn*16384];
__device__ float g_X2  [Bn*Hn*16384];
__device__ float g_gZ1 [Bn*Hn*16384];
__device__ float g_X2b [Bn*Hn*16384];

__device__ __forceinline__ float warpsum(float v) {
#pragma unroll
    for (int o = 16; o > 0; o >>= 1) v += __shfl_xor_sync(0xffffffffu, v, o);
    return v;
}
__device__ __forceinline__ float hsum16(float v) {
#pragma unroll
    for (int o = 8; o > 0; o >>= 1) v += __shfl_xor_sync(0xffffffffu, v, o);
    return v;
}
__device__ __forceinline__ float hmax16(float v) {
#pragma unroll
    for (int o = 8; o > 0; o >>= 1) v = fmaxf(v, __shfl_xor_sync(0xffffffffu, v, o));
    return v;
}
__device__ __forceinline__ float blocksum256(float v) {
    __shared__ float red[8];
    int lane = threadIdx.x & 31, w = threadIdx.x >> 5;
    v = warpsum(v);
    if (lane == 0) red[w] = v;
    __syncthreads();
    float r = (lane < 8) ? red[lane] : 0.f;
    r = warpsum(r);
    __syncthreads();
    return r;
}
__device__ __forceinline__ float tanh_fast(float x) {
    float e = __expf(2.f * x);
    return 1.f - __fdividef(2.f, e + 1.f);
}

// ---------------- LayerNorm rows of 1024 ----------------
__global__ __launch_bounds__(256) void ln_kernel(
    const float* __restrict__ x, const float* __restrict__ g,
    const float* __restrict__ b, float* __restrict__ y)
{
    int row = blockIdx.x, tid = threadIdx.x;
    const float* xr = x + (size_t)row * Dn;
    float v[4]; float s = 0.f;
#pragma unroll
    for (int i = 0; i < 4; i++) { v[i] = xr[tid + 256 * i]; s += v[i]; }
    s = blocksum256(s);
    float mu = s * (1.f / Dn), ss = 0.f;
#pragma unroll
    for (int i = 0; i < 4; i++) { float d = v[i] - mu; ss += d * d; }
    ss = blocksum256(ss);
    float rstd = rsqrtf(ss * (1.f / Dn) + EPSc);
    float* yr = y + (size_t)row * Dn;
#pragma unroll
    for (int i = 0; i < 4; i++) {
        int c = tid + 256 * i;
        yr[c] = (v[i] - mu) * rstd * g[c] + b[c];
    }
}

// ---------------- GEMM C = A@B^T (+bias)(+res)(gate) ----------------
__global__ __launch_bounds__(256) void gemm_nt_kernel(
    const float* __restrict__ A, const float* __restrict__ B, float* __restrict__ C,
    int M, int N, int K,
    const float* __restrict__ bias, const float* __restrict__ res,
    const float* __restrict__ gate)
{
    const int BM = 128, BN = 64, BK = 16;
    __shared__ float As[BK][BM];
    __shared__ float Bs[BK][BN];
    int bm = blockIdx.y * BM, bn = blockIdx.x * BN;
    int t = threadIdx.x, tx = t & 15, ty = t >> 4;
    float acc[8][4];
#pragma unroll
    for (int i = 0; i < 8; i++)
#pragma unroll
        for (int j = 0; j < 4; j++) acc[i][j] = 0.f;
    int ar = t >> 1, akc = (t & 1) * 8;
    int br = t >> 2, bkc = (t & 3) * 4;
    const float* Ab = A + (size_t)(bm + ar) * K + akc;
    const float* Bb = B + (size_t)(bn + br) * K + bkc;
    for (int k0 = 0; k0 < K; k0 += BK) {
        float4 a0 = *(const float4*)(Ab + k0);
        float4 a1 = *(const float4*)(Ab + k0 + 4);
        As[akc+0][ar]=a0.x; As[akc+1][ar]=a0.y; As[akc+2][ar]=a0.z; As[akc+3][ar]=a0.w;
        As[akc+4][ar]=a1.x; As[akc+5][ar]=a1.y; As[akc+6][ar]=a1.z; As[akc+7][ar]=a1.w;
        float4 b0 = *(const float4*)(Bb + k0);
        Bs[bkc+0][br]=b0.x; Bs[bkc+1][br]=b0.y; Bs[bkc+2][br]=b0.z; Bs[bkc+3][br]=b0.w;
        __syncthreads();
#pragma unroll
        for (int kk = 0; kk < BK; kk++) {
            float ra[8], rb[4];
#pragma unroll
            for (int i = 0; i < 8; i++) ra[i] = As[kk][ty * 8 + i];
#pragma unroll
            for (int j = 0; j < 4; j++) rb[j] = Bs[kk][tx * 4 + j];
#pragma unroll
            for (int i = 0; i < 8; i++)
#pragma unroll
                for (int j = 0; j < 4; j++) acc[i][j] += ra[i] * rb[j];
        }
        __syncthreads();
    }
#pragma unroll
    for (int i = 0; i < 8; i++) {
        int m = bm + ty * 8 + i;
#pragma unroll
        for (int j = 0; j < 4; j++) {
            int n = bn + tx * 4 + j;
            float val = acc[i][j];
            if (bias) val += bias[n];
            if (gate)     val = res[(size_t)m * N + n] + tanhf(gate[n]) * val;
            else if (res) val = res[(size_t)m * N + n] + val;
            C[(size_t)m * N + n] = val;
        }
    }
}

// ---------------- Flash attention: block=(qtile, bh) ----------------
#define AQ 68
#define AK 65
#define AP 65
#define ATT_SMEM ((64*AQ + 64*AK + 64*64 + 64*AP) * 4)

__global__ __launch_bounds__(256) void attn_flash_kernel(
    const float* __restrict__ q, const float* __restrict__ k,
    const float* __restrict__ v, float* __restrict__ o)
{
    extern __shared__ float sm[];
    float* Qs = sm;
    float* Ks = Qs + 64 * AQ;
    float* Vs = Ks + 64 * AK;
    float* Ps = Vs + 64 * 64;

    int qt = blockIdx.x, bh = blockIdx.y;
    int b = bh >> 4, h = bh & 15;
    int tid = threadIdx.x, tx = tid & 15, ty = tid >> 4;
    size_t base = ((size_t)b * Sn) * Dn + h * HDn;

    for (int idx = tid; idx < 4096; idx += 256) {
        int r = idx >> 6, e = idx & 63;
        Qs[r * AQ + e] = q[base + (size_t)(qt * 64 + r) * Dn + e] * 0.125f;
    }
    float m[4], l[4], oa[4][4];
#pragma unroll
    for (int u = 0; u < 4; u++) {
        m[u] = -1e30f; l[u] = 0.f;
#pragma unroll
        for (int vv = 0; vv < 4; vv++) oa[u][vv] = 0.f;
    }
    __syncthreads();

    for (int kt = 0; kt <= qt; kt++) {
        for (int idx = tid; idx < 4096; idx += 256) {
            int r = idx >> 6, e = idx & 63;
            size_t g = base + (size_t)(kt * 64 + r) * Dn + e;
            Ks[r * AK + e] = k[g];
            Vs[r * 64 + e] = v[g];
        }
        __syncthreads();

        float acc[4][4];
#pragma unroll
        for (int u = 0; u < 4; u++)
#pragma unroll
            for (int vv = 0; vv < 4; vv++) acc[u][vv] = 0.f;
#pragma unroll 2
        for (int e0 = 0; e0 < 64; e0 += 4) {
            float4 qa[4];
#pragma unroll
            for (int u = 0; u < 4; u++) qa[u] = *(const float4*)(Qs + (ty*4+u)*AQ + e0);
#pragma unroll
            for (int vv = 0; vv < 4; vv++) {
                const float* kr = Ks + (tx*4+vv)*AK + e0;
                float k0 = kr[0], k1 = kr[1], k2 = kr[2], k3 = kr[3];
#pragma unroll
                for (int u = 0; u < 4; u++)
                    acc[u][vv] += qa[u].x*k0 + qa[u].y*k1 + qa[u].z*k2 + qa[u].w*k3;
            }
        }
        bool diag = (kt == qt);
#pragma unroll
        for (int u = 0; u < 4; u++) {
            int r = ty * 4 + u;
            float mx = -1e30f;
#pragma unroll
            for (int vv = 0; vv < 4; vv++) {
                int c = tx * 4 + vv;
                if (diag && c > r) acc[u][vv] = -1e30f;
                mx = fmaxf(mx, acc[u][vv]);
            }
            mx = hmax16(mx);
            float nm = fmaxf(m[u], mx);
            float corr = __expf(m[u] - nm);
            float ps = 0.f;
#pragma unroll
            for (int vv = 0; vv < 4; vv++) {
                float p = __expf(acc[u][vv] - nm);
                Ps[r * AP + tx * 4 + vv] = p;
                ps += p;
            }
            ps = hsum16(ps);
            l[u] = l[u] * corr + ps;
            m[u] = nm;
#pragma unroll
            for (int vv = 0; vv < 4; vv++) oa[u][vv] *= corr;
        }
        __syncthreads();
#pragma unroll 4
        for (int kc = 0; kc < 64; kc++) {
            float4 v4 = *(const float4*)(Vs + kc * 64 + tx * 4);
#pragma unroll
            for (int u = 0; u < 4; u++) {
                float p = Ps[(ty * 4 + u) * AP + kc];
                oa[u][0] += p * v4.x; oa[u][1] += p * v4.y;
                oa[u][2] += p * v4.z; oa[u][3] += p * v4.w;
            }
        }
        __syncthreads();
    }
#pragma unroll
    for (int u = 0; u < 4; u++) {
        float inv = __fdividef(1.f, l[u]);
        size_t g = base + (size_t)(qt * 64 + ty * 4 + u) * Dn + tx * 4;
        *(float4*)(o + g) = make_float4(oa[u][0]*inv, oa[u][1]*inv, oa[u][2]*inv, oa[u][3]*inv);
    }
}

// ---------------- prep & lr ----------------
__global__ __launch_bounds__(256) void prep_kernel(
    float* __restrict__ XQ, float* __restrict__ XK, float* __restrict__ XV,
    const float* __restrict__ nw, const float* __restrict__ nb)
{
    int w = (blockIdx.x * blockDim.x + threadIdx.x) >> 5;
    if (w >= Bn * Sn * Hn) return;
    int lane = threadIdx.x & 31;
    int h = w & 15, bs = w >> 4;
    size_t base = (size_t)bs * Dn + h * HDn;
    float q0 = XQ[base + lane], q1 = XQ[base + lane + 32];
    float qi = 1.f / fmaxf(sqrtf(warpsum(q0*q0 + q1*q1)), 1e-12f);
    XQ[base + lane] = q0 * qi; XQ[base + lane + 32] = q1 * qi;
    float k0 = XK[base + lane], k1 = XK[base + lane + 32];
    float ki = 1.f / fmaxf(sqrtf(warpsum(k0*k0 + k1*k1)), 1e-12f);
    k0 *= ki; k1 *= ki;
    XK[base + lane] = k0; XK[base + lane + 32] = k1;
    float v0 = XV[base + lane], v1 = XV[base + lane + 32];
    float mu = warpsum(v0 + v1) * (1.f / 64.f);
    float d0 = v0 - mu, d1 = v1 - mu;
    float var = warpsum(d0*d0 + d1*d1) * (1.f / 64.f);
    float rstd = rsqrtf(var + EPSc);
    XV[base + lane]      = nw[h*64+lane]    * d0 * rstd + nb[h*64+lane]    + k0;
    XV[base + lane + 32] = nw[h*64+lane+32] * d1 * rstd + nb[h*64+lane+32] + k1;
}

__global__ __launch_bounds__(256) void lr_kernel(
    const float* __restrict__ x1, const float* __restrict__ lrw,
    const float* __restrict__ lrb, float* __restrict__ lro)
{
    int w = (blockIdx.x * blockDim.x + threadIdx.x) >> 5;
    if (w >= Bn * Sn * Hn) return;
    int lane = threadIdx.x & 31;
    int h = w & 15, bs = w >> 4;
    int b = bs >> 10, s = bs & (Sn - 1);
    const float* xr = x1 + (size_t)bs * Dn;
    const float* wr = lrw + h * Dn;
    float acc = 0.f;
    for (int c = lane; c < Dn; c += 32) acc += xr[c] * wr[c];
    acc = warpsum(acc);
    if (lane == 0)
        lro[(size_t)(b * Hn + h) * Sn + s] = 1.f / (1.f + __expf(-(acc + lrb[h])));
}

// ---------------- TTT scan, register tiled ----------------
#define TP 65
#define SCAN_SMEM ((5*64*TP + 256 + 64 + 64) * 4)

__global__ __launch_bounds__(256) void ttt_scan_kernel(
    const float* __restrict__ XQ, const float* __restrict__ XK, const float* __restrict__ XV,
    const float* __restrict__ lr,
    const float* __restrict__ W1i, const float* __restrict__ b1i,
    const float* __restrict__ W2i, const float* __restrict__ b2i,
    const float* __restrict__ nw,  const float* __restrict__ nb,
    float* __restrict__ W1G, float* __restrict__ W2G, float* __restrict__ W2TG,
    float* __restrict__ X2G, float* __restrict__ gZ1G, float* __restrict__ X2bG,
    float* __restrict__ outp)
{
    extern __shared__ float sm[];
    float* sxq  = sm;
    float* sxk  = sxq + 64 * TP;
    float* sxv  = sxk + 64 * TP;   // later Z2b
    float* ssc  = sxv + 64 * TP;   // Z2, then coef
    float* sgZ2 = ssc + 64 * TP;
    float* b1sm = sgZ2 + 64 * TP;  // 256
    float* b2sm = b1sm + 256;      // 64
    float* seta = b2sm + 64;       // 64

    int bh = blockIdx.x, b = bh >> 4, h = bh & 15;
    int tid = threadIdx.x, w = tid >> 5, l = tid & 31;
    int tx = tid & 15, ty = tid >> 4;
    float* W1r  = W1G  + (size_t)bh * 16384;
    float* W2r  = W2G  + (size_t)bh * 16384;
    float* W2Tr = W2TG + (size_t)bh * 16384;
    float* X2r  = X2G  + (size_t)bh * 16384;
    float* gZ1r = gZ1G + (size_t)bh * 16384;
    float* X2br = X2bG + (size_t)bh * 16384;
    const float* nwh = nw + h * 64;
    const float* nbh = nb + h * 64;

    for (int idx = tid; idx < 16384; idx += 256) {
        W1r[idx] = W1i[(size_t)h * 16384 + idx];
        W2r[idx] = W2i[(size_t)h * 16384 + idx];
        int e = idx >> 8, f = idx & 255;
        W2Tr[idx] = W2i[(size_t)h * 16384 + f * 64 + e];
    }
    if (tid < 256) b1sm[tid] = b1i[h * 256 + tid];
    if (tid < 64)  b2sm[tid] = b2i[h * 64 + tid];
    __syncthreads();

    for (int n = 0; n < NCn; n++) {
        size_t tokbase = (size_t)b * Sn + n * Cn;
        for (int idx = tid; idx < 4096; idx += 256) {
            int i = idx >> 6, e = idx & 63;
            size_t g = (tokbase + i) * Dn + h * 64 + e;
            sxq[i * TP + e] = XQ[g];
            sxk[i * TP + e] = XK[g];
            sxv[i * TP + e] = XV[g];
        }
        if (tid < 64) seta[tid] = lr[(size_t)bh * Sn + n * 64 + tid] * (1.f / 64.f);
        __syncthreads();

        // A: Z1 = xk@W1 + b1 -> X2, gb(gelu')
        {
            float acc[8][8];
#pragma unroll
            for (int u = 0; u < 8; u++)
#pragma unroll
                for (int v = 0; v < 8; v++) acc[u][v] = b1sm[l * 8 + v];
#pragma unroll 2
            for (int e = 0; e < 64; e++) {
                float a[8];
#pragma unroll
                for (int u = 0; u < 8; u++) a[u] = sxk[(w * 8 + u) * TP + e];
                float4 w0 = *(const float4*)(W1r + e * 256 + l * 8);
                float4 w1 = *(const float4*)(W1r + e * 256 + l * 8 + 4);
                float wv[8] = {w0.x,w0.y,w0.z,w0.w,w1.x,w1.y,w1.z,w1.w};
#pragma unroll
                for (int u = 0; u < 8; u++)
#pragma unroll
                    for (int v = 0; v < 8; v++) acc[u][v] += a[u] * wv[v];
            }
#pragma unroll
            for (int u = 0; u < 8; u++) {
                int row = w * 8 + u;
                float x2v[8], gbv[8];
#pragma unroll
                for (int v = 0; v < 8; v++) {
                    float z = acc[u][v];
                    float t = tanh_fast(0.79788456f * (z + 0.044715f * z * z * z));
                    x2v[v] = 0.5f * z * (1.f + t);
                    gbv[v] = 0.5f * z * (1.f - t * t) * (0.79788456f + 0.1070322243f * z * z)
                           + 0.5f * (1.f + t);
                }
                float4* xp = (float4*)(X2r + row * 256 + l * 8);
                xp[0] = make_float4(x2v[0],x2v[1],x2v[2],x2v[3]);
                xp[1] = make_float4(x2v[4],x2v[5],x2v[6],x2v[7]);
                float4* gp = (float4*)(gZ1r + row * 256 + l * 8);
                gp[0] = make_float4(gbv[0],gbv[1],gbv[2],gbv[3]);
                gp[1] = make_float4(gbv[4],gbv[5],gbv[6],gbv[7]);
            }
        }
        __syncthreads();

        // B: Z2 = X2@W2 + b2 -> ssc
        {
            float acc[4][4];
#pragma unroll
            for (int u = 0; u < 4; u++)
#pragma unroll
                for (int v = 0; v < 4; v++) acc[u][v] = b2sm[tx * 4 + v];
#pragma unroll 2
            for (int f0 = 0; f0 < 256; f0 += 4) {
                float4 a4[4], b4[4];
#pragma unroll
                for (int u = 0; u < 4; u++) a4[u] = *(const float4*)(X2r + (ty*4+u)*256 + f0);
#pragma unroll
                for (int d = 0; d < 4; d++) b4[d] = *(const float4*)(W2r + (f0+d)*64 + tx*4);
#pragma unroll
                for (int u = 0; u < 4; u++) {
                    acc[u][0] += a4[u].x*b4[0].x + a4[u].y*b4[1].x + a4[u].z*b4[2].x + a4[u].w*b4[3].x;
                    acc[u][1] += a4[u].x*b4[0].y + a4[u].y*b4[1].y + a4[u].z*b4[2].y + a4[u].w*b4[3].y;
                    acc[u][2] += a4[u].x*b4[0].z + a4[u].y*b4[1].z + a4[u].z*b4[2].z + a4[u].w*b4[3].z;
                    acc[u][3] += a4[u].x*b4[0].w + a4[u].y*b4[1].w + a4[u].z*b4[2].w + a4[u].w*b4[3].w;
                }
            }
#pragma unroll
            for (int u = 0; u < 4; u++)
#pragma unroll
                for (int v = 0; v < 4; v++) ssc[(ty*4+u)*TP + tx*4+v] = acc[u][v];
        }
        __syncthreads();

        // C: gZ2 = ln_l2_bwd(Z2, xv-xk)
        for (int i = w; i < 64; i += 8) {
            float z0 = ssc[i*TP + l], z1 = ssc[i*TP + l + 32];
            float mu = warpsum(z0 + z1) * (1.f/64.f);
            float d0 = z0 - mu, d1 = z1 - mu;
            float var = warpsum(d0*d0 + d1*d1) * (1.f/64.f);
            float rstd = rsqrtf(var + EPSc);
            float xh0 = d0 * rstd, xh1 = d1 * rstd;
            float g0 = nwh[l], g1 = nwh[l+32];
            float t0 = sxv[i*TP + l] - sxk[i*TP + l];
            float t1 = sxv[i*TP + l + 32] - sxk[i*TP + l + 32];
            float gh0 = (g0*xh0 + nbh[l]    - t0) * g0;
            float gh1 = (g1*xh1 + nbh[l+32] - t1) * g1;
            float sgh = warpsum(gh0 + gh1);
            float sgx = warpsum(gh0*xh0 + gh1*xh1);
            float cc = rstd * (1.f/64.f);
            sgZ2[i*TP + l]      = (64.f*gh0 - sgh - xh0*sgx) * cc;
            sgZ2[i*TP + l + 32] = (64.f*gh1 - sgh - xh1*sgx) * cc;
        }
        __syncthreads();

        // D: gZ1 = (gZ2 @ W2^T) * gb  (in-place on gZ1r)
        {
            float acc[8][8];
#pragma unroll
            for (int u = 0; u < 8; u++)
#pragma unroll
                for (int v = 0; v < 8; v++) acc[u][v] = 0.f;
#pragma unroll 2
            for (int e = 0; e < 64; e++) {
                float a[8];
#pragma unroll
                for (int u = 0; u < 8; u++) a[u] = sgZ2[(w*8+u)*TP + e];
                float4 w0 = *(const float4*)(W2Tr + e*256 + l*8);
                float4 w1 = *(const float4*)(W2Tr + e*256 + l*8 + 4);
                float wv[8] = {w0.x,w0.y,w0.z,w0.w,w1.x,w1.y,w1.z,w1.w};
#pragma unroll
                for (int u = 0; u < 8; u++)
#pragma unroll
                    for (int v = 0; v < 8; v++) acc[u][v] += a[u] * wv[v];
            }
#pragma unroll
            for (int u = 0; u < 8; u++) {
                int row = w * 8 + u;
                float4* gp = (float4*)(gZ1r + row * 256 + l * 8);
                float4 g0 = gp[0], g1 = gp[1];
                gp[0] = make_float4(acc[u][0]*g0.x, acc[u][1]*g0.y, acc[u][2]*g0.z, acc[u][3]*g0.w);
                gp[1] = make_float4(acc[u][4]*g1.x, acc[u][5]*g1.y, acc[u][6]*g1.z, acc[u][7]*g1.w);
            }
        }
        __syncthreads();

        // E: coef1 = eta[k]*(tril(xq@xk^T)+1) -> ssc
        {
            float acc[4][4];
#pragma unroll
            for (int u = 0; u < 4; u++)
#pragma unroll
                for (int v = 0; v < 4; v++) acc[u][v] = 0.f;
            if (tx * 4 <= ty * 4 + 3) {
#pragma unroll 4
                for (int e = 0; e < 64; e++) {
                    float a[4], bb[4];
#pragma unroll
                    for (int u = 0; u < 4; u++) a[u]  = sxq[(ty*4+u)*TP + e];
#pragma unroll
                    for (int v = 0; v < 4; v++) bb[v] = sxk[(tx*4+v)*TP + e];
#pragma unroll
                    for (int u = 0; u < 4; u++)
#pragma unroll
                        for (int v = 0; v < 4; v++) acc[u][v] += a[u] * bb[v];
                }
            }
#pragma unroll
            for (int u = 0; u < 4; u++) {
                int i = ty * 4 + u;
#pragma unroll
                for (int v = 0; v < 4; v++) {
                    int kk = tx * 4 + v;
                    ssc[i*TP + kk] = (kk <= i) ? seta[kk] * (acc[u][v] + 1.f) : 0.f;
                }
            }
        }
        __syncthreads();

        // F: Z1b = xq@W1 + b1 - coef1@gZ1 ; X2b = gelu
        {
            float acc[8][8];
#pragma unroll
            for (int u = 0; u < 8; u++)
#pragma unroll
                for (int v = 0; v < 8; v++) acc[u][v] = b1sm[l * 8 + v];
#pragma unroll 2
            for (int e = 0; e < 64; e++) {
                float a[8];
#pragma unroll
                for (int u = 0; u < 8; u++) a[u] = sxq[(w*8+u)*TP + e];
                float4 w0 = *(const float4*)(W1r + e*256 + l*8);
                float4 w1 = *(const float4*)(W1r + e*256 + l*8 + 4);
                float wv[8] = {w0.x,w0.y,w0.z,w0.w,w1.x,w1.y,w1.z,w1.w};
#pragma unroll
                for (int u = 0; u < 8; u++)
#pragma unroll
                    for (int v = 0; v < 8; v++) acc[u][v] += a[u] * wv[v];
            }
#pragma unroll 2
            for (int k2 = 0; k2 < 64; k2++) {
                float c[8];
#pragma unroll
                for (int u = 0; u < 8; u++) c[u] = ssc[(w*8+u)*TP + k2];
                float4 g0 = *(const float4*)(gZ1r + k2*256 + l*8);
                float4 g1 = *(const float4*)(gZ1r + k2*256 + l*8 + 4);
                float gv[8] = {g0.x,g0.y,g0.z,g0.w,g1.x,g1.y,g1.z,g1.w};
#pragma unroll
                for (int u = 0; u < 8; u++)
#pragma unroll
                    for (int v = 0; v < 8; v++) acc[u][v] -= c[u] * gv[v];
            }
#pragma unroll
            for (int u = 0; u < 8; u++) {
                int row = w * 8 + u;
                float xv2[8];
#pragma unroll
                for (int v = 0; v < 8; v++) {
                    float z = acc[u][v];
                    float t = tanh_fast(0.79788456f * (z + 0.044715f * z * z * z));
                    xv2[v] = 0.5f * z * (1.f + t);
                }
                float4* xp = (float4*)(X2br + row * 256 + l * 8);
                xp[0] = make_float4(xv2[0],xv2[1],xv2[2],xv2[3]);
                xp[1] = make_float4(xv2[4],xv2[5],xv2[6],xv2[7]);
            }
        }
        __syncthreads();

        // G: coef2 = eta[j]*(tril(X2b@X2^T)+1) -> ssc
        {
            float acc[4][4];
#pragma unroll
            for (int u = 0; u < 4; u++)
#pragma unroll
                for (int v = 0; v < 4; v++) acc[u][v] = 0.f;
            if (tx * 4 <= ty * 4 + 3) {
#pragma unroll 2
                for (int f0 = 0; f0 < 256; f0 += 4) {
                    float4 a4[4], b4[4];
#pragma unroll
                    for (int u = 0; u < 4; u++) a4[u] = *(const float4*)(X2br + (ty*4+u)*256 + f0);
#pragma unroll
                    for (int v = 0; v < 4; v++) b4[v] = *(const float4*)(X2r + (tx*4+v)*256 + f0);
#pragma unroll
                    for (int u = 0; u < 4; u++)
#pragma unroll
                        for (int v = 0; v < 4; v++)
                            acc[u][v] += a4[u].x*b4[v].x + a4[u].y*b4[v].y
                                       + a4[u].z*b4[v].z + a4[u].w*b4[v].w;
                }
            }
#pragma unroll
            for (int u = 0; u < 4; u++) {
                int i = ty * 4 + u;
#pragma unroll
                for (int v = 0; v < 4; v++) {
                    int j = tx * 4 + v;
                    ssc[i*TP + j] = (j <= i) ? seta[j] * (acc[u][v] + 1.f) : 0.f;
                }
            }
        }
        __syncthreads();

        // H: Z2b = X2b@W2 + b2 - coef2@gZ2 -> sxv
        {
            float acc[4][4];
#pragma unroll
            for (int u = 0; u < 4; u++)
#pragma unroll
                for (int v = 0; v < 4; v++) acc[u][v] = b2sm[tx * 4 + v];
#pragma unroll 2
            for (int f0 = 0; f0 < 256; f0 += 4) {
                float4 a4[4], b4[4];
#pragma unroll
                for (int u = 0; u < 4; u++) a4[u] = *(const float4*)(X2br + (ty*4+u)*256 + f0);
#pragma unroll
                for (int d = 0; d < 4; d++) b4[d] = *(const float4*)(W2r + (f0+d)*64 + tx*4);
#pragma unroll
                for (int u = 0; u < 4; u++) {
                    acc[u][0] += a4[u].x*b4[0].x + a4[u].y*b4[1].x + a4[u].z*b4[2].x + a4[u].w*b4[3].x;
                    acc[u][1] += a4[u].x*b4[0].y + a4[u].y*b4[1].y + a4[u].z*b4[2].y + a4[u].w*b4[3].y;
                    acc[u][2] += a4[u].x*b4[0].z + a4[u].y*b4[1].z + a4[u].z*b4[2].z + a4[u].w*b4[3].z;
                    acc[u][3] += a4[u].x*b4[0].w + a4[u].y*b4[1].w + a4[u].z*b4[2].w + a4[u].w*b4[3].w;
                }
            }
#pragma unroll 4
            for (int k2 = 0; k2 < 64; k2++) {
                float c[4];
#pragma unroll
                for (int u = 0; u < 4; u++) c[u] = ssc[(ty*4+u)*TP + k2];
#pragma unroll
                for (int v = 0; v < 4; v++) {
                    float gv = sgZ2[k2*TP + tx*4+v];
#pragma unroll
                    for (int u = 0; u < 4; u++) acc[u][v] -= c[u] * gv;
                }
            }
#pragma unroll
            for (int u = 0; u < 4; u++)
#pragma unroll
                for (int v = 0; v < 4; v++) sxv[(ty*4+u)*TP + tx*4+v] = acc[u][v];
        }
        __syncthreads();

        // I: out = xq + LN(Z2b)
        for (int i = w; i < 64; i += 8) {
            float z0 = sxv[i*TP + l], z1 = sxv[i*TP + l + 32];
            float mu = warpsum(z0 + z1) * (1.f/64.f);
            float d0 = z0 - mu, d1 = z1 - mu;
            float var = warpsum(d0*d0 + d1*d1) * (1.f/64.f);
            float rstd = rsqrtf(var + EPSc);
            size_t g = (tokbase + i) * Dn + h * 64;
            outp[g + l]      = sxq[i*TP + l]      + nwh[l]    * d0 * rstd + nbh[l];
            outp[g + l + 32] = sxq[i*TP + l + 32] + nwh[l+32] * d1 * rstd + nbh[l+32];
        }

        // J1: W1 -= (eta*xk)^T @ gZ1
        {
            float acc[8][8];
#pragma unroll
            for (int u = 0; u < 8; u++)
#pragma unroll
                for (int v = 0; v < 8; v++) acc[u][v] = 0.f;
#pragma unroll 2
            for (int i = 0; i < 64; i++) {
                float et = seta[i];
                float a[8];
#pragma unroll
                for (int u = 0; u < 8; u++) a[u] = et * sxk[i*TP + w*8+u];
                float4 g0 = *(const float4*)(gZ1r + i*256 + l*8);
                float4 g1 = *(const float4*)(gZ1r + i*256 + l*8 + 4);
                float gv[8] = {g0.x,g0.y,g0.z,g0.w,g1.x,g1.y,g1.z,g1.w};
#pragma unroll
                for (int u = 0; u < 8; u++)
#pragma unroll
                    for (int v = 0; v < 8; v++) acc[u][v] += a[u] * gv[v];
            }
#pragma unroll
            for (int u = 0; u < 8; u++) {
                int e = w * 8 + u;
                float4* wp = (float4*)(W1r + e*256 + l*8);
                float4 o0 = wp[0], o1 = wp[1];
                wp[0] = make_float4(o0.x-acc[u][0], o0.y-acc[u][1], o0.z-acc[u][2], o0.w-acc[u][3]);
                wp[1] = make_float4(o1.x-acc[u][4], o1.y-acc[u][5], o1.z-acc[u][6], o1.w-acc[u][7]);
            }
        }
        // J2: b1
        {
            float acc = 0.f;
#pragma unroll 8
            for (int i = 0; i < 64; i++) acc += seta[i] * gZ1r[i*256 + tid];
            b1sm[tid] -= acc;
        }
        // J3: W2 and W2T
        {
            int jt = tid & 7, ft = tid >> 3;
            float acc[8][8];
#pragma unroll
            for (int u = 0; u < 8; u++)
#pragma unroll
                for (int v = 0; v < 8; v++) acc[u][v] = 0.f;
#pragma unroll 2
            for (int i = 0; i < 64; i++) {
                float et = seta[i];
                float4 x0 = *(const float4*)(X2r + i*256 + ft*8);
                float4 x1 = *(const float4*)(X2r + i*256 + ft*8 + 4);
                float a[8] = {et*x0.x,et*x0.y,et*x0.z,et*x0.w,et*x1.x,et*x1.y,et*x1.z,et*x1.w};
                float gv[8];
#pragma unroll
                for (int v = 0; v < 8; v++) gv[v] = sgZ2[i*TP + jt*8+v];
#pragma unroll
                for (int u = 0; u < 8; u++)
#pragma unroll
                    for (int v = 0; v < 8; v++) acc[u][v] += a[u] * gv[v];
            }
#pragma unroll
            for (int u = 0; u < 8; u++) {
                int f = ft * 8 + u;
#pragma unroll
                for (int v = 0; v < 8; v++) {
                    int j = jt * 8 + v;
                    W2r[f*64 + j]  -= acc[u][v];
                    W2Tr[j*256 + f] -= acc[u][v];
                }
            }
        }
        // J4: b2
        if (tid < 64) {
            float acc = 0.f;
#pragma unroll 8
            for (int i = 0; i < 64; i++) acc += seta[i] * sgZ2[i*TP + tid];
            b2sm[tid] -= acc;
        }
        __syncthreads();
    }
}

// ---------------- Launch ----------------
extern "C" void kernel_launch(void* const* d_in, const int* in_sizes, int n_in,
                              void* d_out, int out_size)
{
    const float* x       = (const float*)d_in[0];
    const float* ln1_w   = (const float*)d_in[1];
    const float* ln1_b   = (const float*)d_in[2];
    const float* attn_wq = (const float*)d_in[3];
    const float* attn_wk = (const float*)d_in[4];
    const float* attn_wv = (const float*)d_in[5];
    const float* attn_wo = (const float*)d_in[6];
    const float* wq_w    = (const float*)d_in[7];
    const float* wq_b    = (const float*)d_in[8];
    const float* wk_w    = (const float*)d_in[9];
    const float* wk_b    = (const float*)d_in[10];
    const float* wv_w    = (const float*)d_in[11];
    const float* wv_b    = (const float*)d_in[12];
    const float* wo_w    = (const float*)d_in[13];
    const float* wo_b    = (const float*)d_in[14];
    const float* W1      = (const float*)d_in[15];
    const float* b1      = (const float*)d_in[16];
    const float* W2      = (const float*)d_in[17];
    const float* b2      = (const float*)d_in[18];
    const float* ttt_nw  = (const float*)d_in[19];
    const float* ttt_nb  = (const float*)d_in[20];
    const float* lr_w    = (const float*)d_in[21];
    const float* lr_b    = (const float*)d_in[22];
    const float* pn_w    = (const float*)d_in[23];
    const float* pn_b    = (const float*)d_in[24];
    const float* gate_a  = (const float*)d_in[25];
    float* out = (float*)d_out;

    float *p_h,*p_q,*p_k,*p_v,*p_o,*p_x1,*p_lr,*p_W1,*p_W2,*p_W2T,*p_X2,*p_gZ1,*p_X2b;
    cudaGetSymbolAddress((void**)&p_h,  g_h);
    cudaGetSymbolAddress((void**)&p_q,  g_q);
    cudaGetSymbolAddress((void**)&p_k,  g_k);
    cudaGetSymbolAddress((void**)&p_v,  g_v);
    cudaGetSymbolAddress((void**)&p_o,  g_o);
    cudaGetSymbolAddress((void**)&p_x1, g_x1);
    cudaGetSymbolAddress((void**)&p_lr, g_lr);
    cudaGetSymbolAddress((void**)&p_W1, g_W1s);
    cudaGetSymbolAddress((void**)&p_W2, g_W2s);
    cudaGetSymbolAddress((void**)&p_W2T,g_W2Ts);
    cudaGetSymbolAddress((void**)&p_X2, g_X2);
    cudaGetSymbolAddress((void**)&p_gZ1,g_gZ1);
    cudaGetSymbolAddress((void**)&p_X2b,g_X2b);

    cudaFuncSetAttribute(ttt_scan_kernel,   cudaFuncAttributeMaxDynamicSharedMemorySize, SCAN_SMEM);
    cudaFuncSetAttribute(attn_flash_kernel, cudaFuncAttributeMaxDynamicSharedMemorySize, ATT_SMEM);

    const int M = Bn * Sn;
    dim3 ggrid(Dn / 64, M / 128);
    int nwarp_grid = (Bn * Sn * Hn) / 8;

    ln_kernel<<<M, 256>>>(x, ln1_w, ln1_b, p_h);
    gemm_nt_kernel<<<ggrid, 256>>>(p_h, attn_wq, p_q, M, Dn, Dn, nullptr, nullptr, nullptr);
    gemm_nt_kernel<<<ggrid, 256>>>(p_h, attn_wk, p_k, M, Dn, Dn, nullptr, nullptr, nullptr);
    gemm_nt_kernel<<<ggrid, 256>>>(p_h, attn_wv, p_v, M, Dn, Dn, nullptr, nullptr, nullptr);
    attn_flash_kernel<<<dim3(16, 64), 256, ATT_SMEM>>>(p_q, p_k, p_v, p_o);
    gemm_nt_kernel<<<ggrid, 256>>>(p_o, attn_wo, p_x1, M, Dn, Dn, nullptr, x, nullptr);
    gemm_nt_kernel<<<ggrid, 256>>>(p_x1, wq_w, p_q, M, Dn, Dn, wq_b, nullptr, nullptr);
    gemm_nt_kernel<<<ggrid, 256>>>(p_x1, wk_w, p_k, M, Dn, Dn, wk_b, nullptr, nullptr);
    gemm_nt_kernel<<<ggrid, 256>>>(p_x1, wv_w, p_v, M, Dn, Dn, wv_b, nullptr, nullptr);
    prep_kernel<<<nwarp_grid, 256>>>(p_q, p_k, p_v, ttt_nw, ttt_nb);
    lr_kernel<<<nwarp_grid, 256>>>(p_x1, lr_w, lr_b, p_lr);
    ttt_scan_kernel<<<Bn * Hn, 256, SCAN_SMEM>>>(
        p_q, p_k, p_v, p_lr, W1, b1, W2, b2, ttt_nw, ttt_nb,
        p_W1, p_W2, p_W2T, p_X2, p_gZ1, p_X2b, p_o);
    ln_kernel<<<M, 256>>>(p_o, pn_w, pn_b, p_h);
    gemm_nt_kernel<<<ggrid, 256>>>(p_h, wo_w, out, M, Dn, Dn, wo_b, p_x1, gate_a);
}

// round 4
// speedup vs baseline: 7.0365x; 1.0337x over previous
#include <cuda_runtime.h>
#include <math.h>

#define Bn 4
#define Sn 1024
#define Dn 1024
#define Hn 16
#define HDn 64
#define Cn 64
#define NCn 16
#define DFFn 256
#define EPSc 1e-6f
#define BSD (Bn*Sn*Dn)

__device__ float g_h [BSD];
__device__ float g_q [BSD];
__device__ float g_k [BSD];
__device__ float g_v [BSD];
__device__ float g_o [BSD];
__device__ float g_x1[BSD];
__device__ float g_lr[Bn*Hn*Sn];
__device__ float g_W1s [Bn*Hn*16384];
__device__ float g_W2s [Bn*Hn*16384];
__device__ float g_W2Ts[Bn*Hn*16384];
__device__ float g_X2  [Bn*Hn*16384];
__device__ float g_gZ1 [Bn*Hn*16384];
__device__ float g_X2b [Bn*Hn*16384];

__device__ __forceinline__ float warpsum(float v) {
#pragma unroll
    for (int o = 16; o > 0; o >>= 1) v += __shfl_xor_sync(0xffffffffu, v, o);
    return v;
}
__device__ __forceinline__ float hsum16(float v) {
#pragma unroll
    for (int o = 8; o > 0; o >>= 1) v += __shfl_xor_sync(0xffffffffu, v, o);
    return v;
}
__device__ __forceinline__ float hmax16(float v) {
#pragma unroll
    for (int o = 8; o > 0; o >>= 1) v = fmaxf(v, __shfl_xor_sync(0xffffffffu, v, o));
    return v;
}
__device__ __forceinline__ float blocksum256(float v) {
    __shared__ float red[8];
    int lane = threadIdx.x & 31, w = threadIdx.x >> 5;
    v = warpsum(v);
    if (lane == 0) red[w] = v;
    __syncthreads();
    float r = (lane < 8) ? red[lane] : 0.f;
    r = warpsum(r);
    __syncthreads();
    return r;
}
__device__ __forceinline__ float tanh_fast(float x) {
    float e = __expf(2.f * x);
    return 1.f - __fdividef(2.f, e + 1.f);
}

// ---------------- LayerNorm rows of 1024 ----------------
__global__ __launch_bounds__(256) void ln_kernel(
    const float* __restrict__ x, const float* __restrict__ g,
    const float* __restrict__ b, float* __restrict__ y)
{
    int row = blockIdx.x, tid = threadIdx.x;
    const float* xr = x + (size_t)row * Dn;
    float v[4]; float s = 0.f;
#pragma unroll
    for (int i = 0; i < 4; i++) { v[i] = xr[tid + 256 * i]; s += v[i]; }
    s = blocksum256(s);
    float mu = s * (1.f / Dn), ss = 0.f;
#pragma unroll
    for (int i = 0; i < 4; i++) { float d = v[i] - mu; ss += d * d; }
    ss = blocksum256(ss);
    float rstd = rsqrtf(ss * (1.f / Dn) + EPSc);
    float* yr = y + (size_t)row * Dn;
#pragma unroll
    for (int i = 0; i < 4; i++) {
        int c = tid + 256 * i;
        yr[c] = (v[i] - mu) * rstd * g[c] + b[c];
    }
}

// ---------------- GEMM C = A@B^T (+bias)(+res)(gate) ----------------
// BM=BN=128, BK=16, 256 threads, 8x8 per thread, float4 LDS, reg prefetch
__global__ __launch_bounds__(256) void gemm_nt_kernel(
    const float* __restrict__ A, const float* __restrict__ B, float* __restrict__ C,
    int M, int N, int K,
    const float* __restrict__ bias, const float* __restrict__ res,
    const float* __restrict__ gate)
{
    const int BM = 128, BN = 128, BK = 16;
    __shared__ float As[BK][BM];
    __shared__ float Bs[BK][BN];
    int bm = blockIdx.y * BM, bn = blockIdx.x * BN;
    int t = threadIdx.x, tx = t & 15, ty = t >> 4;
    float acc[8][8];
#pragma unroll
    for (int i = 0; i < 8; i++)
#pragma unroll
        for (int j = 0; j < 8; j++) acc[i][j] = 0.f;

    int r128 = t >> 1, kc = (t & 1) * 8;
    const float* Ab = A + (size_t)(bm + r128) * K + kc;
    const float* Bb = B + (size_t)(bn + r128) * K + kc;

    float4 a0 = *(const float4*)(Ab);
    float4 a1 = *(const float4*)(Ab + 4);
    float4 b0 = *(const float4*)(Bb);
    float4 b1 = *(const float4*)(Bb + 4);

    for (int k0 = 0; k0 < K; k0 += BK) {
        As[kc+0][r128]=a0.x; As[kc+1][r128]=a0.y; As[kc+2][r128]=a0.z; As[kc+3][r128]=a0.w;
        As[kc+4][r128]=a1.x; As[kc+5][r128]=a1.y; As[kc+6][r128]=a1.z; As[kc+7][r128]=a1.w;
        Bs[kc+0][r128]=b0.x; Bs[kc+1][r128]=b0.y; Bs[kc+2][r128]=b0.z; Bs[kc+3][r128]=b0.w;
        Bs[kc+4][r128]=b1.x; Bs[kc+5][r128]=b1.y; Bs[kc+6][r128]=b1.z; Bs[kc+7][r128]=b1.w;
        __syncthreads();
        if (k0 + BK < K) {
            a0 = *(const float4*)(Ab + k0 + BK);
            a1 = *(const float4*)(Ab + k0 + BK + 4);
            b0 = *(const float4*)(Bb + k0 + BK);
            b1 = *(const float4*)(Bb + k0 + BK + 4);
        }
#pragma unroll
        for (int kk = 0; kk < BK; kk++) {
            float4 ra0 = *(const float4*)(&As[kk][ty * 8]);
            float4 ra1 = *(const float4*)(&As[kk][ty * 8 + 4]);
            float4 rb0 = *(const float4*)(&Bs[kk][tx * 8]);
            float4 rb1 = *(const float4*)(&Bs[kk][tx * 8 + 4]);
            float ra[8] = {ra0.x,ra0.y,ra0.z,ra0.w,ra1.x,ra1.y,ra1.z,ra1.w};
            float rb[8] = {rb0.x,rb0.y,rb0.z,rb0.w,rb1.x,rb1.y,rb1.z,rb1.w};
#pragma unroll
            for (int i = 0; i < 8; i++)
#pragma unroll
                for (int j = 0; j < 8; j++) acc[i][j] += ra[i] * rb[j];
        }
        __syncthreads();
    }

    int n0 = bn + tx * 8;
    float bsv[8] = {0,0,0,0,0,0,0,0};
    if (bias) {
        float4 t0 = *(const float4*)(bias + n0);
        float4 t1 = *(const float4*)(bias + n0 + 4);
        bsv[0]=t0.x; bsv[1]=t0.y; bsv[2]=t0.z; bsv[3]=t0.w;
        bsv[4]=t1.x; bsv[5]=t1.y; bsv[6]=t1.z; bsv[7]=t1.w;
    }
    float gv[8];
    if (gate) {
        float4 t0 = *(const float4*)(gate + n0);
        float4 t1 = *(const float4*)(gate + n0 + 4);
        gv[0]=tanhf(t0.x); gv[1]=tanhf(t0.y); gv[2]=tanhf(t0.z); gv[3]=tanhf(t0.w);
        gv[4]=tanhf(t1.x); gv[5]=tanhf(t1.y); gv[6]=tanhf(t1.z); gv[7]=tanhf(t1.w);
    }
#pragma unroll
    for (int i = 0; i < 8; i++) {
        int m = bm + ty * 8 + i;
        float val[8];
#pragma unroll
        for (int j = 0; j < 8; j++) val[j] = acc[i][j] + bsv[j];
        if (gate) {
            float4 r0 = *(const float4*)(res + (size_t)m * N + n0);
            float4 r1 = *(const float4*)(res + (size_t)m * N + n0 + 4);
            val[0]=r0.x+gv[0]*val[0]; val[1]=r0.y+gv[1]*val[1];
            val[2]=r0.z+gv[2]*val[2]; val[3]=r0.w+gv[3]*val[3];
            val[4]=r1.x+gv[4]*val[4]; val[5]=r1.y+gv[5]*val[5];
            val[6]=r1.z+gv[6]*val[6]; val[7]=r1.w+gv[7]*val[7];
        } else if (res) {
            float4 r0 = *(const float4*)(res + (size_t)m * N + n0);
            float4 r1 = *(const float4*)(res + (size_t)m * N + n0 + 4);
            val[0]+=r0.x; val[1]+=r0.y; val[2]+=r0.z; val[3]+=r0.w;
            val[4]+=r1.x; val[5]+=r1.y; val[6]+=r1.z; val[7]+=r1.w;
        }
        *(float4*)(C + (size_t)m * N + n0)     = make_float4(val[0],val[1],val[2],val[3]);
        *(float4*)(C + (size_t)m * N + n0 + 4) = make_float4(val[4],val[5],val[6],val[7]);
    }
}

// ---------------- Flash attention: block=(qtile, bh) ----------------
#define AQ 68
#define AK 68
#define AP 65
#define ATT_SMEM ((64*AQ + 64*AK + 64*64 + 64*AP) * 4)

__global__ __launch_bounds__(256) void attn_flash_kernel(
    const float* __restrict__ q, const float* __restrict__ k,
    const float* __restrict__ v, float* __restrict__ o)
{
    extern __shared__ float sm[];
    float* Qs = sm;
    float* Ks = Qs + 64 * AQ;
    float* Vs = Ks + 64 * AK;
    float* Ps = Vs + 64 * 64;

    int qt = blockIdx.x, bh = blockIdx.y;
    int b = bh >> 4, h = bh & 15;
    int tid = threadIdx.x, tx = tid & 15, ty = tid >> 4;
    size_t base = ((size_t)b * Sn) * Dn + h * HDn;

    for (int idx = tid; idx < 4096; idx += 256) {
        int r = idx >> 6, e = idx & 63;
        Qs[r * AQ + e] = q[base + (size_t)(qt * 64 + r) * Dn + e] * 0.125f;
    }
    float m[4], l[4], oa[4][4];
#pragma unroll
    for (int u = 0; u < 4; u++) {
        m[u] = -1e30f; l[u] = 0.f;
#pragma unroll
        for (int vv = 0; vv < 4; vv++) oa[u][vv] = 0.f;
    }
    __syncthreads();

    for (int kt = 0; kt <= qt; kt++) {
        for (int idx = tid; idx < 4096; idx += 256) {
            int r = idx >> 6, e = idx & 63;
            size_t g = base + (size_t)(kt * 64 + r) * Dn + e;
            Ks[r * AK + e] = k[g];
            Vs[r * 64 + e] = v[g];
        }
        __syncthreads();

        float acc[4][4];
#pragma unroll
        for (int u = 0; u < 4; u++)
#pragma unroll
            for (int vv = 0; vv < 4; vv++) acc[u][vv] = 0.f;
#pragma unroll 2
        for (int e0 = 0; e0 < 64; e0 += 4) {
            float4 qa[4], ka[4];
#pragma unroll
            for (int u = 0; u < 4; u++)  qa[u] = *(const float4*)(Qs + (ty*4+u)*AQ + e0);
#pragma unroll
            for (int vv = 0; vv < 4; vv++) ka[vv] = *(const float4*)(Ks + (tx*4+vv)*AK + e0);
#pragma unroll
            for (int u = 0; u < 4; u++)
#pragma unroll
                for (int vv = 0; vv < 4; vv++)
                    acc[u][vv] += qa[u].x*ka[vv].x + qa[u].y*ka[vv].y
                                + qa[u].z*ka[vv].z + qa[u].w*ka[vv].w;
        }
        bool diag = (kt == qt);
#pragma unroll
        for (int u = 0; u < 4; u++) {
            int r = ty * 4 + u;
            float mx = -1e30f;
#pragma unroll
            for (int vv = 0; vv < 4; vv++) {
                int c = tx * 4 + vv;
                if (diag && c > r) acc[u][vv] = -1e30f;
                mx = fmaxf(mx, acc[u][vv]);
            }
            mx = hmax16(mx);
            float nm = fmaxf(m[u], mx);
            float corr = __expf(m[u] - nm);
            float ps = 0.f;
#pragma unroll
            for (int vv = 0; vv < 4; vv++) {
                float p = __expf(acc[u][vv] - nm);
                Ps[r * AP + tx * 4 + vv] = p;
                ps += p;
            }
            ps = hsum16(ps);
            l[u] = l[u] * corr + ps;
            m[u] = nm;
#pragma unroll
            for (int vv = 0; vv < 4; vv++) oa[u][vv] *= corr;
        }
        __syncthreads();
#pragma unroll 4
        for (int kc = 0; kc < 64; kc++) {
            float4 v4 = *(const float4*)(Vs + kc * 64 + tx * 4);
#pragma unroll
            for (int u = 0; u < 4; u++) {
                float p = Ps[(ty * 4 + u) * AP + kc];
                oa[u][0] += p * v4.x; oa[u][1] += p * v4.y;
                oa[u][2] += p * v4.z; oa[u][3] += p * v4.w;
            }
        }
        __syncthreads();
    }
#pragma unroll
    for (int u = 0; u < 4; u++) {
        float inv = __fdividef(1.f, l[u]);
        size_t g = base + (size_t)(qt * 64 + ty * 4 + u) * Dn + tx * 4;
        *(float4*)(o + g) = make_float4(oa[u][0]*inv, oa[u][1]*inv, oa[u][2]*inv, oa[u][3]*inv);
    }
}

// ---------------- prep & lr ----------------
__global__ __launch_bounds__(256) void prep_kernel(
    float* __restrict__ XQ, float* __restrict__ XK, float* __restrict__ XV,
    const float* __restrict__ nw, const float* __restrict__ nb)
{
    int w = (blockIdx.x * blockDim.x + threadIdx.x) >> 5;
    if (w >= Bn * Sn * Hn) return;
    int lane = threadIdx.x & 31;
    int h = w & 15, bs = w >> 4;
    size_t base = (size_t)bs * Dn + h * HDn;
    float q0 = XQ[base + lane], q1 = XQ[base + lane + 32];
    float qi = 1.f / fmaxf(sqrtf(warpsum(q0*q0 + q1*q1)), 1e-12f);
    XQ[base + lane] = q0 * qi; XQ[base + lane + 32] = q1 * qi;
    float k0 = XK[base + lane], k1 = XK[base + lane + 32];
    float ki = 1.f / fmaxf(sqrtf(warpsum(k0*k0 + k1*k1)), 1e-12f);
    k0 *= ki; k1 *= ki;
    XK[base + lane] = k0; XK[base + lane + 32] = k1;
    float v0 = XV[base + lane], v1 = XV[base + lane + 32];
    float mu = warpsum(v0 + v1) * (1.f / 64.f);
    float d0 = v0 - mu, d1 = v1 - mu;
    float var = warpsum(d0*d0 + d1*d1) * (1.f / 64.f);
    float rstd = rsqrtf(var + EPSc);
    XV[base + lane]      = nw[h*64+lane]    * d0 * rstd + nb[h*64+lane]    + k0;
    XV[base + lane + 32] = nw[h*64+lane+32] * d1 * rstd + nb[h*64+lane+32] + k1;
}

__global__ __launch_bounds__(256) void lr_kernel(
    const float* __restrict__ x1, const float* __restrict__ lrw,
    const float* __restrict__ lrb, float* __restrict__ lro)
{
    int w = (blockIdx.x * blockDim.x + threadIdx.x) >> 5;
    if (w >= Bn * Sn * Hn) return;
    int lane = threadIdx.x & 31;
    int h = w & 15, bs = w >> 4;
    int b = bs >> 10, s = bs & (Sn - 1);
    const float* xr = x1 + (size_t)bs * Dn;
    const float* wr = lrw + h * Dn;
    float acc = 0.f;
    for (int c = lane; c < Dn; c += 32) acc += xr[c] * wr[c];
    acc = warpsum(acc);
    if (lane == 0)
        lro[(size_t)(b * Hn + h) * Sn + s] = 1.f / (1.f + __expf(-(acc + lrb[h])));
}

// ---------------- TTT scan, register tiled ----------------
#define TP 65
#define SCAN_SMEM ((5*64*TP + 256 + 64 + 64) * 4)

__global__ __launch_bounds__(256) void ttt_scan_kernel(
    const float* __restrict__ XQ, const float* __restrict__ XK, const float* __restrict__ XV,
    const float* __restrict__ lr,
    const float* __restrict__ W1i, const float* __restrict__ b1i,
    const float* __restrict__ W2i, const float* __restrict__ b2i,
    const float* __restrict__ nw,  const float* __restrict__ nb,
    float* __restrict__ W1G, float* __restrict__ W2G, float* __restrict__ W2TG,
    float* __restrict__ X2G, float* __restrict__ gZ1G, float* __restrict__ X2bG,
    float* __restrict__ outp)
{
    extern __shared__ float sm[];
    float* sxq  = sm;
    float* sxk  = sxq + 64 * TP;
    float* sxv  = sxk + 64 * TP;   // later Z2b
    float* ssc  = sxv + 64 * TP;   // Z2, then coef
    float* sgZ2 = ssc + 64 * TP;
    float* b1sm = sgZ2 + 64 * TP;  // 256
    float* b2sm = b1sm + 256;      // 64
    float* seta = b2sm + 64;       // 64

    int bh = blockIdx.x, b = bh >> 4, h = bh & 15;
    int tid = threadIdx.x, w = tid >> 5, l = tid & 31;
    int tx = tid & 15, ty = tid >> 4;
    float* W1r  = W1G  + (size_t)bh * 16384;
    float* W2r  = W2G  + (size_t)bh * 16384;
    float* W2Tr = W2TG + (size_t)bh * 16384;
    float* X2r  = X2G  + (size_t)bh * 16384;
    float* gZ1r = gZ1G + (size_t)bh * 16384;
    float* X2br = X2bG + (size_t)bh * 16384;
    const float* nwh = nw + h * 64;
    const float* nbh = nb + h * 64;

    for (int idx = tid; idx < 16384; idx += 256) {
        W1r[idx] = W1i[(size_t)h * 16384 + idx];
        W2r[idx] = W2i[(size_t)h * 16384 + idx];
        int e = idx >> 8, f = idx & 255;
        W2Tr[idx] = W2i[(size_t)h * 16384 + f * 64 + e];
    }
    if (tid < 256) b1sm[tid] = b1i[h * 256 + tid];
    if (tid < 64)  b2sm[tid] = b2i[h * 64 + tid];
    __syncthreads();

    for (int n = 0; n < NCn; n++) {
        size_t tokbase = (size_t)b * Sn + n * Cn;
        for (int idx = tid; idx < 4096; idx += 256) {
            int i = idx >> 6, e = idx & 63;
            size_t g = (tokbase + i) * Dn + h * 64 + e;
            sxq[i * TP + e] = XQ[g];
            sxk[i * TP + e] = XK[g];
            sxv[i * TP + e] = XV[g];
        }
        if (tid < 64) seta[tid] = lr[(size_t)bh * Sn + n * 64 + tid] * (1.f / 64.f);
        __syncthreads();

        // A: Z1 = xk@W1 + b1 -> X2, gb(gelu')
        {
            float acc[8][8];
#pragma unroll
            for (int u = 0; u < 8; u++)
#pragma unroll
                for (int v = 0; v < 8; v++) acc[u][v] = b1sm[l * 8 + v];
#pragma unroll 2
            for (int e = 0; e < 64; e++) {
                float a[8];
#pragma unroll
                for (int u = 0; u < 8; u++) a[u] = sxk[(w * 8 + u) * TP + e];
                float4 w0 = *(const float4*)(W1r + e * 256 + l * 8);
                float4 w1 = *(const float4*)(W1r + e * 256 + l * 8 + 4);
                float wv[8] = {w0.x,w0.y,w0.z,w0.w,w1.x,w1.y,w1.z,w1.w};
#pragma unroll
                for (int u = 0; u < 8; u++)
#pragma unroll
                    for (int v = 0; v < 8; v++) acc[u][v] += a[u] * wv[v];
            }
#pragma unroll
            for (int u = 0; u < 8; u++) {
                int row = w * 8 + u;
                float x2v[8], gbv[8];
#pragma unroll
                for (int v = 0; v < 8; v++) {
                    float z = acc[u][v];
                    float t = tanh_fast(0.79788456f * (z + 0.044715f * z * z * z));
                    x2v[v] = 0.5f * z * (1.f + t);
                    gbv[v] = 0.5f * z * (1.f - t * t) * (0.79788456f + 0.1070322243f * z * z)
                           + 0.5f * (1.f + t);
                }
                float4* xp = (float4*)(X2r + row * 256 + l * 8);
                xp[0] = make_float4(x2v[0],x2v[1],x2v[2],x2v[3]);
                xp[1] = make_float4(x2v[4],x2v[5],x2v[6],x2v[7]);
                float4* gp = (float4*)(gZ1r + row * 256 + l * 8);
                gp[0] = make_float4(gbv[0],gbv[1],gbv[2],gbv[3]);
                gp[1] = make_float4(gbv[4],gbv[5],gbv[6],gbv[7]);
            }
        }
        __syncthreads();

        // B: Z2 = X2@W2 + b2 -> ssc
        {
            float acc[4][4];
#pragma unroll
            for (int u = 0; u < 4; u++)
#pragma unroll
                for (int v = 0; v < 4; v++) acc[u][v] = b2sm[tx * 4 + v];
#pragma unroll 2
            for (int f0 = 0; f0 < 256; f0 += 4) {
                float4 a4[4], b4[4];
#pragma unroll
                for (int u = 0; u < 4; u++) a4[u] = *(const float4*)(X2r + (ty*4+u)*256 + f0);
#pragma unroll
                for (int d = 0; d < 4; d++) b4[d] = *(const float4*)(W2r + (f0+d)*64 + tx*4);
#pragma unroll
                for (int u = 0; u < 4; u++) {
                    acc[u][0] += a4[u].x*b4[0].x + a4[u].y*b4[1].x + a4[u].z*b4[2].x + a4[u].w*b4[3].x;
                    acc[u][1] += a4[u].x*b4[0].y + a4[u].y*b4[1].y + a4[u].z*b4[2].y + a4[u].w*b4[3].y;
                    acc[u][2] += a4[u].x*b4[0].z + a4[u].y*b4[1].z + a4[u].z*b4[2].z + a4[u].w*b4[3].z;
                    acc[u][3] += a4[u].x*b4[0].w + a4[u].y*b4[1].w + a4[u].z*b4[2].w + a4[u].w*b4[3].w;
                }
            }
#pragma unroll
            for (int u = 0; u < 4; u++)
#pragma unroll
                for (int v = 0; v < 4; v++) ssc[(ty*4+u)*TP + tx*4+v] = acc[u][v];
        }
        __syncthreads();

        // C: gZ2 = ln_l2_bwd(Z2, xv-xk)
        for (int i = w; i < 64; i += 8) {
            float z0 = ssc[i*TP + l], z1 = ssc[i*TP + l + 32];
            float mu = warpsum(z0 + z1) * (1.f/64.f);
            float d0 = z0 - mu, d1 = z1 - mu;
            float var = warpsum(d0*d0 + d1*d1) * (1.f/64.f);
            float rstd = rsqrtf(var + EPSc);
            float xh0 = d0 * rstd, xh1 = d1 * rstd;
            float g0 = nwh[l], g1 = nwh[l+32];
            float t0 = sxv[i*TP + l] - sxk[i*TP + l];
            float t1 = sxv[i*TP + l + 32] - sxk[i*TP + l + 32];
            float gh0 = (g0*xh0 + nbh[l]    - t0) * g0;
            float gh1 = (g1*xh1 + nbh[l+32] - t1) * g1;
            float sgh = warpsum(gh0 + gh1);
            float sgx = warpsum(gh0*xh0 + gh1*xh1);
            float cc = rstd * (1.f/64.f);
            sgZ2[i*TP + l]      = (64.f*gh0 - sgh - xh0*sgx) * cc;
            sgZ2[i*TP + l + 32] = (64.f*gh1 - sgh - xh1*sgx) * cc;
        }
        __syncthreads();

        // D: gZ1 = (gZ2 @ W2^T) * gb  (in-place on gZ1r)
        {
            float acc[8][8];
#pragma unroll
            for (int u = 0; u < 8; u++)
#pragma unroll
                for (int v = 0; v < 8; v++) acc[u][v] = 0.f;
#pragma unroll 2
            for (int e = 0; e < 64; e++) {
                float a[8];
#pragma unroll
                for (int u = 0; u < 8; u++) a[u] = sgZ2[(w*8+u)*TP + e];
                float4 w0 = *(const float4*)(W2Tr + e*256 + l*8);
                float4 w1 = *(const float4*)(W2Tr + e*256 + l*8 + 4);
                float wv[8] = {w0.x,w0.y,w0.z,w0.w,w1.x,w1.y,w1.z,w1.w};
#pragma unroll
                for (int u = 0; u < 8; u++)
#pragma unroll
                    for (int v = 0; v < 8; v++) acc[u][v] += a[u] * wv[v];
            }
#pragma unroll
            for (int u = 0; u < 8; u++) {
                int row = w * 8 + u;
                float4* gp = (float4*)(gZ1r + row * 256 + l * 8);
                float4 g0 = gp[0], g1 = gp[1];
                gp[0] = make_float4(acc[u][0]*g0.x, acc[u][1]*g0.y, acc[u][2]*g0.z, acc[u][3]*g0.w);
                gp[1] = make_float4(acc[u][4]*g1.x, acc[u][5]*g1.y, acc[u][6]*g1.z, acc[u][7]*g1.w);
            }
        }
        __syncthreads();

        // E: coef1 = eta[k]*(tril(xq@xk^T)+1) -> ssc
        {
            float acc[4][4];
#pragma unroll
            for (int u = 0; u < 4; u++)
#pragma unroll
                for (int v = 0; v < 4; v++) acc[u][v] = 0.f;
            if (tx * 4 <= ty * 4 + 3) {
#pragma unroll 4
                for (int e = 0; e < 64; e++) {
                    float a[4], bb[4];
#pragma unroll
                    for (int u = 0; u < 4; u++) a[u]  = sxq[(ty*4+u)*TP + e];
#pragma unroll
                    for (int v = 0; v < 4; v++) bb[v] = sxk[(tx*4+v)*TP + e];
#pragma unroll
                    for (int u = 0; u < 4; u++)
#pragma unroll
                        for (int v = 0; v < 4; v++) acc[u][v] += a[u] * bb[v];
                }
            }
#pragma unroll
            for (int u = 0; u < 4; u++) {
                int i = ty * 4 + u;
#pragma unroll
                for (int v = 0; v < 4; v++) {
                    int kk = tx * 4 + v;
                    ssc[i*TP + kk] = (kk <= i) ? seta[kk] * (acc[u][v] + 1.f) : 0.f;
                }
            }
        }
        __syncthreads();

        // F: Z1b = xq@W1 + b1 - coef1@gZ1 ; X2b = gelu
        {
            float acc[8][8];
#pragma unroll
            for (int u = 0; u < 8; u++)
#pragma unroll
                for (int v = 0; v < 8; v++) acc[u][v] = b1sm[l * 8 + v];
#pragma unroll 2
            for (int e = 0; e < 64; e++) {
                float a[8];
#pragma unroll
                for (int u = 0; u < 8; u++) a[u] = sxq[(w*8+u)*TP + e];
                float4 w0 = *(const float4*)(W1r + e*256 + l*8);
                float4 w1 = *(const float4*)(W1r + e*256 + l*8 + 4);
                float wv[8] = {w0.x,w0.y,w0.z,w0.w,w1.x,w1.y,w1.z,w1.w};
#pragma unroll
                for (int u = 0; u < 8; u++)
#pragma unroll
                    for (int v = 0; v < 8; v++) acc[u][v] += a[u] * wv[v];
            }
#pragma unroll 2
            for (int k2 = 0; k2 < 64; k2++) {
                float c[8];
#pragma unroll
                for (int u = 0; u < 8; u++) c[u] = ssc[(w*8+u)*TP + k2];
                float4 g0 = *(const float4*)(gZ1r + k2*256 + l*8);
                float4 g1 = *(const float4*)(gZ1r + k2*256 + l*8 + 4);
                float gv[8] = {g0.x,g0.y,g0.z,g0.w,g1.x,g1.y,g1.z,g1.w};
#pragma unroll
                for (int u = 0; u < 8; u++)
#pragma unroll
                    for (int v = 0; v < 8; v++) acc[u][v] -= c[u] * gv[v];
            }
#pragma unroll
            for (int u = 0; u < 8; u++) {
                int row = w * 8 + u;
                float xv2[8];
#pragma unroll
                for (int v = 0; v < 8; v++) {
                    float z = acc[u][v];
                    float t = tanh_fast(0.79788456f * (z + 0.044715f * z * z * z));
                    xv2[v] = 0.5f * z * (1.f + t);
                }
                float4* xp = (float4*)(X2br + row * 256 + l * 8);
                xp[0] = make_float4(xv2[0],xv2[1],xv2[2],xv2[3]);
                xp[1] = make_float4(xv2[4],xv2[5],xv2[6],xv2[7]);
            }
        }
        __syncthreads();

        // G: coef2 = eta[j]*(tril(X2b@X2^T)+1) -> ssc
        {
            float acc[4][4];
#pragma unroll
            for (int u = 0; u < 4; u++)
#pragma unroll
                for (int v = 0; v < 4; v++) acc[u][v] = 0.f;
            if (tx * 4 <= ty * 4 + 3) {
#pragma unroll 2
                for (int f0 = 0; f0 < 256; f0 += 4) {
                    float4 a4[4], b4[4];
#pragma unroll
                    for (int u = 0; u < 4; u++) a4[u] = *(const float4*)(X2br + (ty*4+u)*256 + f0);
#pragma unroll
                    for (int v = 0; v < 4; v++) b4[v] = *(const float4*)(X2r + (tx*4+v)*256 + f0);
#pragma unroll
                    for (int u = 0; u < 4; u++)
#pragma unroll
                        for (int v = 0; v < 4; v++)
                            acc[u][v] += a4[u].x*b4[v].x + a4[u].y*b4[v].y
                                       + a4[u].z*b4[v].z + a4[u].w*b4[v].w;
                }
            }
#pragma unroll
            for (int u = 0; u < 4; u++) {
                int i = ty * 4 + u;
#pragma unroll
                for (int v = 0; v < 4; v++) {
                    int j = tx * 4 + v;
                    ssc[i*TP + j] = (j <= i) ? seta[j] * (acc[u][v] + 1.f) : 0.f;
                }
            }
        }
        __syncthreads();

        // H: Z2b = X2b@W2 + b2 - coef2@gZ2 -> sxv
        {
            float acc[4][4];
#pragma unroll
            for (int u = 0; u < 4; u++)
#pragma unroll
                for (int v = 0; v < 4; v++) acc[u][v] = b2sm[tx * 4 + v];
#pragma unroll 2
            for (int f0 = 0; f0 < 256; f0 += 4) {
                float4 a4[4], b4[4];
#pragma unroll
                for (int u = 0; u < 4; u++) a4[u] = *(const float4*)(X2br + (ty*4+u)*256 + f0);
#pragma unroll
                for (int d = 0; d < 4; d++) b4[d] = *(const float4*)(W2r + (f0+d)*64 + tx*4);
#pragma unroll
                for (int u = 0; u < 4; u++) {
                    acc[u][0] += a4[u].x*b4[0].x + a4[u].y*b4[1].x + a4[u].z*b4[2].x + a4[u].w*b4[3].x;
                    acc[u][1] += a4[u].x*b4[0].y + a4[u].y*b4[1].y + a4[u].z*b4[2].y + a4[u].w*b4[3].y;
                    acc[u][2] += a4[u].x*b4[0].z + a4[u].y*b4[1].z + a4[u].z*b4[2].z + a4[u].w*b4[3].z;
                    acc[u][3] += a4[u].x*b4[0].w + a4[u].y*b4[1].w + a4[u].z*b4[2].w + a4[u].w*b4[3].w;
                }
            }
#pragma unroll 4
            for (int k2 = 0; k2 < 64; k2++) {
                float c[4];
#pragma unroll
                for (int u = 0; u < 4; u++) c[u] = ssc[(ty*4+u)*TP + k2];
#pragma unroll
                for (int v = 0; v < 4; v++) {
                    float gv = sgZ2[k2*TP + tx*4+v];
#pragma unroll
                    for (int u = 0; u < 4; u++) acc[u][v] -= c[u] * gv;
                }
            }
#pragma unroll
            for (int u = 0; u < 4; u++)
#pragma unroll
                for (int v = 0; v < 4; v++) sxv[(ty*4+u)*TP + tx*4+v] = acc[u][v];
        }
        __syncthreads();

        // I: out = xq + LN(Z2b)
        for (int i = w; i < 64; i += 8) {
            float z0 = sxv[i*TP + l], z1 = sxv[i*TP + l + 32];
            float mu = warpsum(z0 + z1) * (1.f/64.f);
            float d0 = z0 - mu, d1 = z1 - mu;
            float var = warpsum(d0*d0 + d1*d1) * (1.f/64.f);
            float rstd = rsqrtf(var + EPSc);
            size_t g = (tokbase + i) * Dn + h * 64;
            outp[g + l]      = sxq[i*TP + l]      + nwh[l]    * d0 * rstd + nbh[l];
            outp[g + l + 32] = sxq[i*TP + l + 32] + nwh[l+32] * d1 * rstd + nbh[l+32];
        }

        // J1: W1 -= (eta*xk)^T @ gZ1
        {
            float acc[8][8];
#pragma unroll
            for (int u = 0; u < 8; u++)
#pragma unroll
                for (int v = 0; v < 8; v++) acc[u][v] = 0.f;
#pragma unroll 2
            for (int i = 0; i < 64; i++) {
                float et = seta[i];
                float a[8];
#pragma unroll
                for (int u = 0; u < 8; u++) a[u] = et * sxk[i*TP + w*8+u];
                float4 g0 = *(const float4*)(gZ1r + i*256 + l*8);
                float4 g1 = *(const float4*)(gZ1r + i*256 + l*8 + 4);
                float gv[8] = {g0.x,g0.y,g0.z,g0.w,g1.x,g1.y,g1.z,g1.w};
#pragma unroll
                for (int u = 0; u < 8; u++)
#pragma unroll
                    for (int v = 0; v < 8; v++) acc[u][v] += a[u] * gv[v];
            }
#pragma unroll
            for (int u = 0; u < 8; u++) {
                int e = w * 8 + u;
                float4* wp = (float4*)(W1r + e*256 + l*8);
                float4 o0 = wp[0], o1 = wp[1];
                wp[0] = make_float4(o0.x-acc[u][0], o0.y-acc[u][1], o0.z-acc[u][2], o0.w-acc[u][3]);
                wp[1] = make_float4(o1.x-acc[u][4], o1.y-acc[u][5], o1.z-acc[u][6], o1.w-acc[u][7]);
            }
        }
        // J2: b1
        {
            float acc = 0.f;
#pragma unroll 8
            for (int i = 0; i < 64; i++) acc += seta[i] * gZ1r[i*256 + tid];
            b1sm[tid] -= acc;
        }
        // J3: W2 and W2T
        {
            int jt = tid & 7, ft = tid >> 3;
            float acc[8][8];
#pragma unroll
            for (int u = 0; u < 8; u++)
#pragma unroll
                for (int v = 0; v < 8; v++) acc[u][v] = 0.f;
#pragma unroll 2
            for (int i = 0; i < 64; i++) {
                float et = seta[i];
                float4 x0 = *(const float4*)(X2r + i*256 + ft*8);
                float4 x1 = *(const float4*)(X2r + i*256 + ft*8 + 4);
                float a[8] = {et*x0.x,et*x0.y,et*x0.z,et*x0.w,et*x1.x,et*x1.y,et*x1.z,et*x1.w};
                float gv[8];
#pragma unroll
                for (int v = 0; v < 8; v++) gv[v] = sgZ2[i*TP + jt*8+v];
#pragma unroll
                for (int u = 0; u < 8; u++)
#pragma unroll
                    for (int v = 0; v < 8; v++) acc[u][v] += a[u] * gv[v];
            }
#pragma unroll
            for (int u = 0; u < 8; u++) {
                int f = ft * 8 + u;
#pragma unroll
                for (int v = 0; v < 8; v++) {
                    int j = jt * 8 + v;
                    W2r[f*64 + j]  -= acc[u][v];
                    W2Tr[j*256 + f] -= acc[u][v];
                }
            }
        }
        // J4: b2
        if (tid < 64) {
            float acc = 0.f;
#pragma unroll 8
            for (int i = 0; i < 64; i++) acc += seta[i] * sgZ2[i*TP + tid];
            b2sm[tid] -= acc;
        }
        __syncthreads();
    }
}

// ---------------- Launch ----------------
extern "C" void kernel_launch(void* const* d_in, const int* in_sizes, int n_in,
                              void* d_out, int out_size)
{
    const float* x       = (const float*)d_in[0];
    const float* ln1_w   = (const float*)d_in[1];
    const float* ln1_b   = (const float*)d_in[2];
    const float* attn_wq = (const float*)d_in[3];
    const float* attn_wk = (const float*)d_in[4];
    const float* attn_wv = (const float*)d_in[5];
    const float* attn_wo = (const float*)d_in[6];
    const float* wq_w    = (const float*)d_in[7];
    const float* wq_b    = (const float*)d_in[8];
    const float* wk_w    = (const float*)d_in[9];
    const float* wk_b    = (const float*)d_in[10];
    const float* wv_w    = (const float*)d_in[11];
    const float* wv_b    = (const float*)d_in[12];
    const float* wo_w    = (const float*)d_in[13];
    const float* wo_b    = (const float*)d_in[14];
    const float* W1      = (const float*)d_in[15];
    const float* b1      = (const float*)d_in[16];
    const float* W2      = (const float*)d_in[17];
    const float* b2      = (const float*)d_in[18];
    const float* ttt_nw  = (const float*)d_in[19];
    const float* ttt_nb  = (const float*)d_in[20];
    const float* lr_w    = (const float*)d_in[21];
    const float* lr_b    = (const float*)d_in[22];
    const float* pn_w    = (const float*)d_in[23];
    const float* pn_b    = (const float*)d_in[24];
    const float* gate_a  = (const float*)d_in[25];
    float* out = (float*)d_out;

    float *p_h,*p_q,*p_k,*p_v,*p_o,*p_x1,*p_lr,*p_W1,*p_W2,*p_W2T,*p_X2,*p_gZ1,*p_X2b;
    cudaGetSymbolAddress((void**)&p_h,  g_h);
    cudaGetSymbolAddress((void**)&p_q,  g_q);
    cudaGetSymbolAddress((void**)&p_k,  g_k);
    cudaGetSymbolAddress((void**)&p_v,  g_v);
    cudaGetSymbolAddress((void**)&p_o,  g_o);
    cudaGetSymbolAddress((void**)&p_x1, g_x1);
    cudaGetSymbolAddress((void**)&p_lr, g_lr);
    cudaGetSymbolAddress((void**)&p_W1, g_W1s);
    cudaGetSymbolAddress((void**)&p_W2, g_W2s);
    cudaGetSymbolAddress((void**)&p_W2T,g_W2Ts);
    cudaGetSymbolAddress((void**)&p_X2, g_X2);
    cudaGetSymbolAddress((void**)&p_gZ1,g_gZ1);
    cudaGetSymbolAddress((void**)&p_X2b,g_X2b);

    cudaFuncSetAttribute(ttt_scan_kernel,   cudaFuncAttributeMaxDynamicSharedMemorySize, SCAN_SMEM);
    cudaFuncSetAttribute(attn_flash_kernel, cudaFuncAttributeMaxDynamicSharedMemorySize, ATT_SMEM);

    const int M = Bn * Sn;
    dim3 ggrid(Dn / 128, M / 128);   // (8, 32)
    int nwarp_grid = (Bn * Sn * Hn) / 8;

    ln_kernel<<<M, 256>>>(x, ln1_w, ln1_b, p_h);
    gemm_nt_kernel<<<ggrid, 256>>>(p_h, attn_wq, p_q, M, Dn, Dn, nullptr, nullptr, nullptr);
    gemm_nt_kernel<<<ggrid, 256>>>(p_h, attn_wk, p_k, M, Dn, Dn, nullptr, nullptr, nullptr);
    gemm_nt_kernel<<<ggrid, 256>>>(p_h, attn_wv, p_v, M, Dn, Dn, nullptr, nullptr, nullptr);
    attn_flash_kernel<<<dim3(16, 64), 256, ATT_SMEM>>>(p_q, p_k, p_v, p_o);
    gemm_nt_kernel<<<ggrid, 256>>>(p_o, attn_wo, p_x1, M, Dn, Dn, nullptr, x, nullptr);
    gemm_nt_kernel<<<ggrid, 256>>>(p_x1, wq_w, p_q, M, Dn, Dn, wq_b, nullptr, nullptr);
    gemm_nt_kernel<<<ggrid, 256>>>(p_x1, wk_w, p_k, M, Dn, Dn, wk_b, nullptr, nullptr);
    gemm_nt_kernel<<<ggrid, 256>>>(p_x1, wv_w, p_v, M, Dn, Dn, wv_b, nullptr, nullptr);
    prep_kernel<<<nwarp_grid, 256>>>(p_q, p_k, p_v, ttt_nw, ttt_nb);
    lr_kernel<<<nwarp_grid, 256>>>(p_x1, lr_w, lr_b, p_lr);
    ttt_scan_kernel<<<Bn * Hn, 256, SCAN_SMEM>>>(
        p_q, p_k, p_v, p_lr, W1, b1, W2, b2, ttt_nw, ttt_nb,
        p_W1, p_W2, p_W2T, p_X2, p_gZ1, p_X2b, p_o);
    ln_kernel<<<M, 256>>>(p_o, pn_w, pn_b, p_h);
    gemm_nt_kernel<<<ggrid, 256>>>(p_h, wo_w, out, M, Dn, Dn, wo_b, p_x1, gate_a);
}

// round 5
// speedup vs baseline: 7.3871x; 1.0498x over previous
#include <cuda_runtime.h>
#include <math.h>

#define Bn 4
#define Sn 1024
#define Dn 1024
#define Hn 16
#define HDn 64
#define Cn 64
#define NCn 16
#define DFFn 256
#define EPSc 1e-6f
#define BSD (Bn*Sn*Dn)

__device__ float g_h [BSD];
__device__ float g_q [BSD];
__device__ float g_k [BSD];
__device__ float g_v [BSD];
__device__ float g_o [BSD];
__device__ float g_x1[BSD];
__device__ float g_lr[Bn*Hn*Sn];
__device__ float g_W1s [Bn*Hn*16384];
__device__ float g_W2s [Bn*Hn*16384];
__device__ float g_W2Ts[Bn*Hn*16384];
__device__ float g_X2  [Bn*Hn*16384];
__device__ float g_gZ1 [Bn*Hn*16384];
__device__ float g_X2b [Bn*Hn*16384];

__device__ __forceinline__ float warpsum(float v) {
#pragma unroll
    for (int o = 16; o > 0; o >>= 1) v += __shfl_xor_sync(0xffffffffu, v, o);
    return v;
}
__device__ __forceinline__ float hsum16(float v) {
#pragma unroll
    for (int o = 8; o > 0; o >>= 1) v += __shfl_xor_sync(0xffffffffu, v, o);
    return v;
}
__device__ __forceinline__ float hmax16(float v) {
#pragma unroll
    for (int o = 8; o > 0; o >>= 1) v = fmaxf(v, __shfl_xor_sync(0xffffffffu, v, o));
    return v;
}
__device__ __forceinline__ float blocksum256(float v) {
    __shared__ float red[8];
    int lane = threadIdx.x & 31, w = threadIdx.x >> 5;
    v = warpsum(v);
    if (lane == 0) red[w] = v;
    __syncthreads();
    float r = (lane < 8) ? red[lane] : 0.f;
    r = warpsum(r);
    __syncthreads();
    return r;
}
__device__ __forceinline__ float tanh_fast(float x) {
    float e = __expf(2.f * x);
    return 1.f - __fdividef(2.f, e + 1.f);
}

// ---------------- LayerNorm rows of 1024 ----------------
__global__ __launch_bounds__(256) void ln_kernel(
    const float* __restrict__ x, const float* __restrict__ g,
    const float* __restrict__ b, float* __restrict__ y)
{
    int row = blockIdx.x, tid = threadIdx.x;
    const float* xr = x + (size_t)row * Dn;
    float v[4]; float s = 0.f;
#pragma unroll
    for (int i = 0; i < 4; i++) { v[i] = xr[tid + 256 * i]; s += v[i]; }
    s = blocksum256(s);
    float mu = s * (1.f / Dn), ss = 0.f;
#pragma unroll
    for (int i = 0; i < 4; i++) { float d = v[i] - mu; ss += d * d; }
    ss = blocksum256(ss);
    float rstd = rsqrtf(ss * (1.f / Dn) + EPSc);
    float* yr = y + (size_t)row * Dn;
#pragma unroll
    for (int i = 0; i < 4; i++) {
        int c = tid + 256 * i;
        yr[c] = (v[i] - mu) * rstd * g[c] + b[c];
    }
}

// ---------------- GEMM core: C = A@B^T (+bias)(+res)(gate) ----------------
// M=4096,N=1024,K=1024 fixed. BM=BN=128,BK=16, 256 thr, 8x8 split 4+4.
__device__ __forceinline__ void gemm_core(
    const float* __restrict__ A, const float* __restrict__ B, float* __restrict__ C,
    const float* __restrict__ bias, const float* __restrict__ res,
    const float* __restrict__ gate, int bm, int bn)
{
    const int N = 1024, K = 1024, BK = 16;
    __shared__ float As[BK][128];
    __shared__ float Bs[BK][128];
    int t = threadIdx.x, tx = t & 15, ty = t >> 4;
    float acc[8][8];
#pragma unroll
    for (int i = 0; i < 8; i++)
#pragma unroll
        for (int j = 0; j < 8; j++) acc[i][j] = 0.f;

    int r128 = t >> 1, kc = (t & 1) * 8;
    const float* Ab = A + (size_t)(bm + r128) * K + kc;
    const float* Bb = B + (size_t)(bn + r128) * K + kc;
    float4 a0 = *(const float4*)(Ab);
    float4 a1 = *(const float4*)(Ab + 4);
    float4 b0 = *(const float4*)(Bb);
    float4 b1 = *(const float4*)(Bb + 4);

    for (int k0 = 0; k0 < K; k0 += BK) {
        As[kc+0][r128]=a0.x; As[kc+1][r128]=a0.y; As[kc+2][r128]=a0.z; As[kc+3][r128]=a0.w;
        As[kc+4][r128]=a1.x; As[kc+5][r128]=a1.y; As[kc+6][r128]=a1.z; As[kc+7][r128]=a1.w;
        Bs[kc+0][r128]=b0.x; Bs[kc+1][r128]=b0.y; Bs[kc+2][r128]=b0.z; Bs[kc+3][r128]=b0.w;
        Bs[kc+4][r128]=b1.x; Bs[kc+5][r128]=b1.y; Bs[kc+6][r128]=b1.z; Bs[kc+7][r128]=b1.w;
        __syncthreads();
        if (k0 + BK < K) {
            a0 = *(const float4*)(Ab + k0 + BK);
            a1 = *(const float4*)(Ab + k0 + BK + 4);
            b0 = *(const float4*)(Bb + k0 + BK);
            b1 = *(const float4*)(Bb + k0 + BK + 4);
        }
#pragma unroll
        for (int kk = 0; kk < BK; kk++) {
            float4 ra0 = *(const float4*)(&As[kk][ty * 4]);
            float4 ra1 = *(const float4*)(&As[kk][64 + ty * 4]);
            float4 rb0 = *(const float4*)(&Bs[kk][tx * 4]);
            float4 rb1 = *(const float4*)(&Bs[kk][64 + tx * 4]);
            float ra[8] = {ra0.x,ra0.y,ra0.z,ra0.w,ra1.x,ra1.y,ra1.z,ra1.w};
            float rb[8] = {rb0.x,rb0.y,rb0.z,rb0.w,rb1.x,rb1.y,rb1.z,rb1.w};
#pragma unroll
            for (int i = 0; i < 8; i++)
#pragma unroll
                for (int j = 0; j < 8; j++) acc[i][j] += ra[i] * rb[j];
        }
        __syncthreads();
    }

    int na = bn + tx * 4, nb2 = bn + 64 + tx * 4;
    float bsv[8] = {0,0,0,0,0,0,0,0};
    if (bias) {
        float4 t0 = *(const float4*)(bias + na);
        float4 t1 = *(const float4*)(bias + nb2);
        bsv[0]=t0.x; bsv[1]=t0.y; bsv[2]=t0.z; bsv[3]=t0.w;
        bsv[4]=t1.x; bsv[5]=t1.y; bsv[6]=t1.z; bsv[7]=t1.w;
    }
    float gv[8];
    if (gate) {
        float4 t0 = *(const float4*)(gate + na);
        float4 t1 = *(const float4*)(gate + nb2);
        gv[0]=tanhf(t0.x); gv[1]=tanhf(t0.y); gv[2]=tanhf(t0.z); gv[3]=tanhf(t0.w);
        gv[4]=tanhf(t1.x); gv[5]=tanhf(t1.y); gv[6]=tanhf(t1.z); gv[7]=tanhf(t1.w);
    }
#pragma unroll
    for (int i = 0; i < 8; i++) {
        int m = (i < 4) ? (bm + ty * 4 + i) : (bm + 64 + ty * 4 + i - 4);
        float val[8];
#pragma unroll
        for (int j = 0; j < 8; j++) val[j] = acc[i][j] + bsv[j];
        if (gate) {
            float4 r0 = *(const float4*)(res + (size_t)m * N + na);
            float4 r1 = *(const float4*)(res + (size_t)m * N + nb2);
            val[0]=r0.x+gv[0]*val[0]; val[1]=r0.y+gv[1]*val[1];
            val[2]=r0.z+gv[2]*val[2]; val[3]=r0.w+gv[3]*val[3];
            val[4]=r1.x+gv[4]*val[4]; val[5]=r1.y+gv[5]*val[5];
            val[6]=r1.z+gv[6]*val[6]; val[7]=r1.w+gv[7]*val[7];
        } else if (res) {
            float4 r0 = *(const float4*)(res + (size_t)m * N + na);
            float4 r1 = *(const float4*)(res + (size_t)m * N + nb2);
            val[0]+=r0.x; val[1]+=r0.y; val[2]+=r0.z; val[3]+=r0.w;
            val[4]+=r1.x; val[5]+=r1.y; val[6]+=r1.z; val[7]+=r1.w;
        }
        *(float4*)(C + (size_t)m * N + na)  = make_float4(val[0],val[1],val[2],val[3]);
        *(float4*)(C + (size_t)m * N + nb2) = make_float4(val[4],val[5],val[6],val[7]);
    }
}

__global__ __launch_bounds__(256) void gemm_nt_kernel(
    const float* __restrict__ A, const float* __restrict__ B, float* __restrict__ C,
    const float* __restrict__ bias, const float* __restrict__ res,
    const float* __restrict__ gate)
{
    gemm_core(A, B, C, bias, res, gate, blockIdx.y * 128, blockIdx.x * 128);
}

__global__ __launch_bounds__(256) void gemm3_nt_kernel(
    const float* __restrict__ A,
    const float* __restrict__ B0, const float* __restrict__ B1, const float* __restrict__ B2,
    float* __restrict__ C0, float* __restrict__ C1, float* __restrict__ C2,
    const float* __restrict__ b0, const float* __restrict__ b1, const float* __restrict__ b2)
{
    const float* B; float* C; const float* bias;
    if (blockIdx.z == 0)      { B = B0; C = C0; bias = b0; }
    else if (blockIdx.z == 1) { B = B1; C = C1; bias = b1; }
    else                      { B = B2; C = C2; bias = b2; }
    gemm_core(A, B, C, bias, nullptr, nullptr, blockIdx.y * 128, blockIdx.x * 128);
}

// ---------------- Flash attention ----------------
#define AQ 68
#define AK 68
#define AP 65
#define ATT_SMEM ((64*AQ + 64*AK + 64*64 + 64*AP) * 4)

__global__ __launch_bounds__(256) void attn_flash_kernel(
    const float* __restrict__ q, const float* __restrict__ k,
    const float* __restrict__ v, float* __restrict__ o)
{
    extern __shared__ float sm[];
    float* Qs = sm;
    float* Ks = Qs + 64 * AQ;
    float* Vs = Ks + 64 * AK;
    float* Ps = Vs + 64 * 64;

    int qt = blockIdx.x, bh = blockIdx.y;
    int b = bh >> 4, h = bh & 15;
    int tid = threadIdx.x, tx = tid & 15, ty = tid >> 4;
    size_t base = ((size_t)b * Sn) * Dn + h * HDn;

    for (int idx = tid; idx < 4096; idx += 256) {
        int r = idx >> 6, e = idx & 63;
        Qs[r * AQ + e] = q[base + (size_t)(qt * 64 + r) * Dn + e] * 0.125f;
    }
    float m[4], l[4], oa[4][4];
#pragma unroll
    for (int u = 0; u < 4; u++) {
        m[u] = -1e30f; l[u] = 0.f;
#pragma unroll
        for (int vv = 0; vv < 4; vv++) oa[u][vv] = 0.f;
    }
    __syncthreads();

    for (int kt = 0; kt <= qt; kt++) {
        for (int idx = tid; idx < 4096; idx += 256) {
            int r = idx >> 6, e = idx & 63;
            size_t g = base + (size_t)(kt * 64 + r) * Dn + e;
            Ks[r * AK + e] = k[g];
            Vs[r * 64 + e] = v[g];
        }
        __syncthreads();

        float acc[4][4];
#pragma unroll
        for (int u = 0; u < 4; u++)
#pragma unroll
            for (int vv = 0; vv < 4; vv++) acc[u][vv] = 0.f;
#pragma unroll 2
        for (int e0 = 0; e0 < 64; e0 += 4) {
            float4 qa[4], ka[4];
#pragma unroll
            for (int u = 0; u < 4; u++)  qa[u] = *(const float4*)(Qs + (ty*4+u)*AQ + e0);
#pragma unroll
            for (int vv = 0; vv < 4; vv++) ka[vv] = *(const float4*)(Ks + (tx*4+vv)*AK + e0);
#pragma unroll
            for (int u = 0; u < 4; u++)
#pragma unroll
                for (int vv = 0; vv < 4; vv++)
                    acc[u][vv] += qa[u].x*ka[vv].x + qa[u].y*ka[vv].y
                                + qa[u].z*ka[vv].z + qa[u].w*ka[vv].w;
        }
        bool diag = (kt == qt);
#pragma unroll
        for (int u = 0; u < 4; u++) {
            int r = ty * 4 + u;
            float mx = -1e30f;
#pragma unroll
            for (int vv = 0; vv < 4; vv++) {
                int c = tx * 4 + vv;
                if (diag && c > r) acc[u][vv] = -1e30f;
                mx = fmaxf(mx, acc[u][vv]);
            }
            mx = hmax16(mx);
            float nm = fmaxf(m[u], mx);
            float corr = __expf(m[u] - nm);
            float ps = 0.f;
#pragma unroll
            for (int vv = 0; vv < 4; vv++) {
                float p = __expf(acc[u][vv] - nm);
                Ps[r * AP + tx * 4 + vv] = p;
                ps += p;
            }
            ps = hsum16(ps);
            l[u] = l[u] * corr + ps;
            m[u] = nm;
#pragma unroll
            for (int vv = 0; vv < 4; vv++) oa[u][vv] *= corr;
        }
        __syncthreads();
#pragma unroll 4
        for (int kc = 0; kc < 64; kc++) {
            float4 v4 = *(const float4*)(Vs + kc * 64 + tx * 4);
#pragma unroll
            for (int u = 0; u < 4; u++) {
                float p = Ps[(ty * 4 + u) * AP + kc];
                oa[u][0] += p * v4.x; oa[u][1] += p * v4.y;
                oa[u][2] += p * v4.z; oa[u][3] += p * v4.w;
            }
        }
        __syncthreads();
    }
#pragma unroll
    for (int u = 0; u < 4; u++) {
        float inv = __fdividef(1.f, l[u]);
        size_t g = base + (size_t)(qt * 64 + ty * 4 + u) * Dn + tx * 4;
        *(float4*)(o + g) = make_float4(oa[u][0]*inv, oa[u][1]*inv, oa[u][2]*inv, oa[u][3]*inv);
    }
}

// ---------------- prep & lr ----------------
__global__ __launch_bounds__(256) void prep_kernel(
    float* __restrict__ XQ, float* __restrict__ XK, float* __restrict__ XV,
    const float* __restrict__ nw, const float* __restrict__ nb)
{
    int w = (blockIdx.x * blockDim.x + threadIdx.x) >> 5;
    if (w >= Bn * Sn * Hn) return;
    int lane = threadIdx.x & 31;
    int h = w & 15, bs = w >> 4;
    size_t base = (size_t)bs * Dn + h * HDn;
    float q0 = XQ[base + lane], q1 = XQ[base + lane + 32];
    float qi = 1.f / fmaxf(sqrtf(warpsum(q0*q0 + q1*q1)), 1e-12f);
    XQ[base + lane] = q0 * qi; XQ[base + lane + 32] = q1 * qi;
    float k0 = XK[base + lane], k1 = XK[base + lane + 32];
    float ki = 1.f / fmaxf(sqrtf(warpsum(k0*k0 + k1*k1)), 1e-12f);
    k0 *= ki; k1 *= ki;
    XK[base + lane] = k0; XK[base + lane + 32] = k1;
    float v0 = XV[base + lane], v1 = XV[base + lane + 32];
    float mu = warpsum(v0 + v1) * (1.f / 64.f);
    float d0 = v0 - mu, d1 = v1 - mu;
    float var = warpsum(d0*d0 + d1*d1) * (1.f / 64.f);
    float rstd = rsqrtf(var + EPSc);
    XV[base + lane]      = nw[h*64+lane]    * d0 * rstd + nb[h*64+lane]    + k0;
    XV[base + lane + 32] = nw[h*64+lane+32] * d1 * rstd + nb[h*64+lane+32] + k1;
}

__global__ __launch_bounds__(256) void lr_kernel(
    const float* __restrict__ x1, const float* __restrict__ lrw,
    const float* __restrict__ lrb, float* __restrict__ lro)
{
    int w = (blockIdx.x * blockDim.x + threadIdx.x) >> 5;
    if (w >= Bn * Sn * Hn) return;
    int lane = threadIdx.x & 31;
    int h = w & 15, bs = w >> 4;
    int b = bs >> 10, s = bs & (Sn - 1);
    const float* xr = x1 + (size_t)bs * Dn;
    const float* wr = lrw + h * Dn;
    float acc = 0.f;
    for (int c = lane; c < Dn; c += 32) acc += xr[c] * wr[c];
    acc = warpsum(acc);
    if (lane == 0)
        lro[(size_t)(b * Hn + h) * Sn + s] = 1.f / (1.f + __expf(-(acc + lrb[h])));
}

// ---------------- TTT scan, 512 threads ----------------
#define TP 65
#define PS 68
#define SCAN_SMEM ((3*64*TP + 2*64*PS + 256 + 64 + 64) * 4)

__global__ __launch_bounds__(512) void ttt_scan_kernel(
    const float* __restrict__ XQ, const float* __restrict__ XK, const float* __restrict__ XV,
    const float* __restrict__ lr,
    const float* __restrict__ W1i, const float* __restrict__ b1i,
    const float* __restrict__ W2i, const float* __restrict__ b2i,
    const float* __restrict__ nw,  const float* __restrict__ nb,
    float* __restrict__ W1G, float* __restrict__ W2G, float* __restrict__ W2TG,
    float* __restrict__ X2G, float* __restrict__ gZ1G, float* __restrict__ X2bG,
    float* __restrict__ outp)
{
    extern __shared__ float sm[];
    float* sxq  = sm;                 // 64*TP
    float* sxk  = sxq + 64 * TP;
    float* sxv  = sxk + 64 * TP;      // later Z2b
    float* ssc  = sxv + 64 * TP;      // Z2 / coef, stride PS
    float* sgZ2 = ssc + 64 * PS;      // stride PS
    float* b1sm = sgZ2 + 64 * PS;     // 256
    float* b2sm = b1sm + 256;         // 64
    float* seta = b2sm + 64;          // 64

    int bh = blockIdx.x, b = bh >> 4, h = bh & 15;
    int tid = threadIdx.x, w = tid >> 5, l = tid & 31;
    int ty2 = tid >> 4, tx2 = tid & 15;   // 32 x 16
    int ft = tid >> 3, jt = tid & 7;      // 64 x 8
    float* W1r  = W1G  + (size_t)bh * 16384;
    float* W2r  = W2G  + (size_t)bh * 16384;
    float* W2Tr = W2TG + (size_t)bh * 16384;
    float* X2r  = X2G  + (size_t)bh * 16384;
    float* gZ1r = gZ1G + (size_t)bh * 16384;
    float* X2br = X2bG + (size_t)bh * 16384;
    const float* nwh = nw + h * 64;
    const float* nbh = nb + h * 64;

    for (int idx = tid; idx < 16384; idx += 512) {
        W1r[idx] = W1i[(size_t)h * 16384 + idx];
        W2r[idx] = W2i[(size_t)h * 16384 + idx];
        int e = idx >> 8, f = idx & 255;
        W2Tr[idx] = W2i[(size_t)h * 16384 + f * 64 + e];
    }
    if (tid < 256) b1sm[tid] = b1i[h * 256 + tid];
    if (tid < 64)  b2sm[tid] = b2i[h * 64 + tid];
    __syncthreads();

    for (int n = 0; n < NCn; n++) {
        size_t tokbase = (size_t)b * Sn + n * Cn;
        for (int idx = tid; idx < 4096; idx += 512) {
            int i = idx >> 6, e = idx & 63;
            size_t g = (tokbase + i) * Dn + h * 64 + e;
            sxq[i * TP + e] = XQ[g];
            sxk[i * TP + e] = XK[g];
            sxv[i * TP + e] = XV[g];
        }
        if (tid < 64) seta[tid] = lr[(size_t)bh * Sn + n * 64 + tid] * (1.f / 64.f);
        __syncthreads();

        // A: Z1 = xk@W1 + b1 -> X2, gZ1=gelu'
        {
            float acc[4][8];
#pragma unroll
            for (int u = 0; u < 4; u++)
#pragma unroll
                for (int v = 0; v < 8; v++) acc[u][v] = b1sm[l * 8 + v];
#pragma unroll 4
            for (int e = 0; e < 64; e++) {
                float a[4];
#pragma unroll
                for (int u = 0; u < 4; u++) a[u] = sxk[(w * 4 + u) * TP + e];
                float4 w0 = *(const float4*)(W1r + e * 256 + l * 8);
                float4 w1 = *(const float4*)(W1r + e * 256 + l * 8 + 4);
                float wv[8] = {w0.x,w0.y,w0.z,w0.w,w1.x,w1.y,w1.z,w1.w};
#pragma unroll
                for (int u = 0; u < 4; u++)
#pragma unroll
                    for (int v = 0; v < 8; v++) acc[u][v] += a[u] * wv[v];
            }
#pragma unroll
            for (int u = 0; u < 4; u++) {
                int row = w * 4 + u;
                float x2v[8], gbv[8];
#pragma unroll
                for (int v = 0; v < 8; v++) {
                    float z = acc[u][v];
                    float t = tanh_fast(0.79788456f * (z + 0.044715f * z * z * z));
                    x2v[v] = 0.5f * z * (1.f + t);
                    gbv[v] = 0.5f * z * (1.f - t * t) * (0.79788456f + 0.1070322243f * z * z)
                           + 0.5f * (1.f + t);
                }
                float4* xp = (float4*)(X2r + row * 256 + l * 8);
                xp[0] = make_float4(x2v[0],x2v[1],x2v[2],x2v[3]);
                xp[1] = make_float4(x2v[4],x2v[5],x2v[6],x2v[7]);
                float4* gp = (float4*)(gZ1r + row * 256 + l * 8);
                gp[0] = make_float4(gbv[0],gbv[1],gbv[2],gbv[3]);
                gp[1] = make_float4(gbv[4],gbv[5],gbv[6],gbv[7]);
            }
        }
        __syncthreads();

        // B: Z2 = X2@W2 + b2 -> ssc
        {
            float acc[2][4];
#pragma unroll
            for (int u = 0; u < 2; u++)
#pragma unroll
                for (int v = 0; v < 4; v++) acc[u][v] = b2sm[tx2 * 4 + v];
#pragma unroll 4
            for (int f0 = 0; f0 < 256; f0 += 4) {
                float4 a4[2], b4[4];
#pragma unroll
                for (int u = 0; u < 2; u++) a4[u] = *(const float4*)(X2r + (ty2*2+u)*256 + f0);
#pragma unroll
                for (int d = 0; d < 4; d++) b4[d] = *(const float4*)(W2r + (f0+d)*64 + tx2*4);
#pragma unroll
                for (int u = 0; u < 2; u++) {
                    acc[u][0] += a4[u].x*b4[0].x + a4[u].y*b4[1].x + a4[u].z*b4[2].x + a4[u].w*b4[3].x;
                    acc[u][1] += a4[u].x*b4[0].y + a4[u].y*b4[1].y + a4[u].z*b4[2].y + a4[u].w*b4[3].y;
                    acc[u][2] += a4[u].x*b4[0].z + a4[u].y*b4[1].z + a4[u].z*b4[2].z + a4[u].w*b4[3].z;
                    acc[u][3] += a4[u].x*b4[0].w + a4[u].y*b4[1].w + a4[u].z*b4[2].w + a4[u].w*b4[3].w;
                }
            }
#pragma unroll
            for (int u = 0; u < 2; u++)
#pragma unroll
                for (int v = 0; v < 4; v++) ssc[(ty2*2+u)*PS + tx2*4+v] = acc[u][v];
        }
        __syncthreads();

        // C: gZ2 = ln_l2_bwd(Z2, xv-xk)
        for (int i = w; i < 64; i += 16) {
            float z0 = ssc[i*PS + l], z1 = ssc[i*PS + l + 32];
            float mu = warpsum(z0 + z1) * (1.f/64.f);
            float d0 = z0 - mu, d1 = z1 - mu;
            float var = warpsum(d0*d0 + d1*d1) * (1.f/64.f);
            float rstd = rsqrtf(var + EPSc);
            float xh0 = d0 * rstd, xh1 = d1 * rstd;
            float g0 = nwh[l], g1 = nwh[l+32];
            float t0 = sxv[i*TP + l] - sxk[i*TP + l];
            float t1 = sxv[i*TP + l + 32] - sxk[i*TP + l + 32];
            float gh0 = (g0*xh0 + nbh[l]    - t0) * g0;
            float gh1 = (g1*xh1 + nbh[l+32] - t1) * g1;
            float sgh = warpsum(gh0 + gh1);
            float sgx = warpsum(gh0*xh0 + gh1*xh1);
            float cc = rstd * (1.f/64.f);
            sgZ2[i*PS + l]      = (64.f*gh0 - sgh - xh0*sgx) * cc;
            sgZ2[i*PS + l + 32] = (64.f*gh1 - sgh - xh1*sgx) * cc;
        }
        __syncthreads();

        // D: gZ1 = (gZ2 @ W2^T) * gb
        {
            float acc[4][8];
#pragma unroll
            for (int u = 0; u < 4; u++)
#pragma unroll
                for (int v = 0; v < 8; v++) acc[u][v] = 0.f;
#pragma unroll 4
            for (int e = 0; e < 64; e++) {
                float a[4];
#pragma unroll
                for (int u = 0; u < 4; u++) a[u] = sgZ2[(w*4+u)*PS + e];
                float4 w0 = *(const float4*)(W2Tr + e*256 + l*8);
                float4 w1 = *(const float4*)(W2Tr + e*256 + l*8 + 4);
                float wv[8] = {w0.x,w0.y,w0.z,w0.w,w1.x,w1.y,w1.z,w1.w};
#pragma unroll
                for (int u = 0; u < 4; u++)
#pragma unroll
                    for (int v = 0; v < 8; v++) acc[u][v] += a[u] * wv[v];
            }
#pragma unroll
            for (int u = 0; u < 4; u++) {
                int row = w * 4 + u;
                float4* gp = (float4*)(gZ1r + row * 256 + l * 8);
                float4 g0 = gp[0], g1 = gp[1];
                gp[0] = make_float4(acc[u][0]*g0.x, acc[u][1]*g0.y, acc[u][2]*g0.z, acc[u][3]*g0.w);
                gp[1] = make_float4(acc[u][4]*g1.x, acc[u][5]*g1.y, acc[u][6]*g1.z, acc[u][7]*g1.w);
            }
        }
        __syncthreads();

        // E: coef1 = eta[k]*(tril(xq@xk^T)+1) -> ssc
        {
            float acc[2][4];
#pragma unroll
            for (int u = 0; u < 2; u++)
#pragma unroll
                for (int v = 0; v < 4; v++) acc[u][v] = 0.f;
            if (tx2 * 4 <= ty2 * 2 + 1) {
#pragma unroll 4
                for (int e = 0; e < 64; e++) {
                    float a[2], bb[4];
#pragma unroll
                    for (int u = 0; u < 2; u++) a[u]  = sxq[(ty2*2+u)*TP + e];
#pragma unroll
                    for (int v = 0; v < 4; v++) bb[v] = sxk[(tx2*4+v)*TP + e];
#pragma unroll
                    for (int u = 0; u < 2; u++)
#pragma unroll
                        for (int v = 0; v < 4; v++) acc[u][v] += a[u] * bb[v];
                }
            }
#pragma unroll
            for (int u = 0; u < 2; u++) {
                int i = ty2 * 2 + u;
#pragma unroll
                for (int v = 0; v < 4; v++) {
                    int kk = tx2 * 4 + v;
                    ssc[i*PS + kk] = (kk <= i) ? seta[kk] * (acc[u][v] + 1.f) : 0.f;
                }
            }
        }
        __syncthreads();

        // F: Z1b = xq@W1 + b1 - coef1@gZ1 ; X2b = gelu
        {
            float acc[4][8];
#pragma unroll
            for (int u = 0; u < 4; u++)
#pragma unroll
                for (int v = 0; v < 8; v++) acc[u][v] = b1sm[l * 8 + v];
#pragma unroll 4
            for (int e = 0; e < 64; e++) {
                float a[4];
#pragma unroll
                for (int u = 0; u < 4; u++) a[u] = sxq[(w*4+u)*TP + e];
                float4 w0 = *(const float4*)(W1r + e*256 + l*8);
                float4 w1 = *(const float4*)(W1r + e*256 + l*8 + 4);
                float wv[8] = {w0.x,w0.y,w0.z,w0.w,w1.x,w1.y,w1.z,w1.w};
#pragma unroll
                for (int u = 0; u < 4; u++)
#pragma unroll
                    for (int v = 0; v < 8; v++) acc[u][v] += a[u] * wv[v];
            }
#pragma unroll 4
            for (int k2 = 0; k2 < 64; k2++) {
                float c[4];
#pragma unroll
                for (int u = 0; u < 4; u++) c[u] = ssc[(w*4+u)*PS + k2];
                float4 g0 = *(const float4*)(gZ1r + k2*256 + l*8);
                float4 g1 = *(const float4*)(gZ1r + k2*256 + l*8 + 4);
                float gv[8] = {g0.x,g0.y,g0.z,g0.w,g1.x,g1.y,g1.z,g1.w};
#pragma unroll
                for (int u = 0; u < 4; u++)
#pragma unroll
                    for (int v = 0; v < 8; v++) acc[u][v] -= c[u] * gv[v];
            }
#pragma unroll
            for (int u = 0; u < 4; u++) {
                int row = w * 4 + u;
                float xv2[8];
#pragma unroll
                for (int v = 0; v < 8; v++) {
                    float z = acc[u][v];
                    float t = tanh_fast(0.79788456f * (z + 0.044715f * z * z * z));
                    xv2[v] = 0.5f * z * (1.f + t);
                }
                float4* xp = (float4*)(X2br + row * 256 + l * 8);
                xp[0] = make_float4(xv2[0],xv2[1],xv2[2],xv2[3]);
                xp[1] = make_float4(xv2[4],xv2[5],xv2[6],xv2[7]);
            }
        }
        __syncthreads();

        // G: coef2 = eta[j]*(tril(X2b@X2^T)+1) -> ssc
        {
            float acc[2][4];
#pragma unroll
            for (int u = 0; u < 2; u++)
#pragma unroll
                for (int v = 0; v < 4; v++) acc[u][v] = 0.f;
            if (tx2 * 4 <= ty2 * 2 + 1) {
#pragma unroll 2
                for (int f0 = 0; f0 < 256; f0 += 4) {
                    float4 a4[2], b4[4];
#pragma unroll
                    for (int u = 0; u < 2; u++) a4[u] = *(const float4*)(X2br + (ty2*2+u)*256 + f0);
#pragma unroll
                    for (int v = 0; v < 4; v++) b4[v] = *(const float4*)(X2r + (tx2*4+v)*256 + f0);
#pragma unroll
                    for (int u = 0; u < 2; u++)
#pragma unroll
                        for (int v = 0; v < 4; v++)
                            acc[u][v] += a4[u].x*b4[v].x + a4[u].y*b4[v].y
                                       + a4[u].z*b4[v].z + a4[u].w*b4[v].w;
                }
            }
#pragma unroll
            for (int u = 0; u < 2; u++) {
                int i = ty2 * 2 + u;
#pragma unroll
                for (int v = 0; v < 4; v++) {
                    int j = tx2 * 4 + v;
                    ssc[i*PS + j] = (j <= i) ? seta[j] * (acc[u][v] + 1.f) : 0.f;
                }
            }
        }
        __syncthreads();

        // H: Z2b = X2b@W2 + b2 - coef2@gZ2 -> sxv
        {
            float acc[2][4];
#pragma unroll
            for (int u = 0; u < 2; u++)
#pragma unroll
                for (int v = 0; v < 4; v++) acc[u][v] = b2sm[tx2 * 4 + v];
#pragma unroll 4
            for (int f0 = 0; f0 < 256; f0 += 4) {
                float4 a4[2], b4[4];
#pragma unroll
                for (int u = 0; u < 2; u++) a4[u] = *(const float4*)(X2br + (ty2*2+u)*256 + f0);
#pragma unroll
                for (int d = 0; d < 4; d++) b4[d] = *(const float4*)(W2r + (f0+d)*64 + tx2*4);
#pragma unroll
                for (int u = 0; u < 2; u++) {
                    acc[u][0] += a4[u].x*b4[0].x + a4[u].y*b4[1].x + a4[u].z*b4[2].x + a4[u].w*b4[3].x;
                    acc[u][1] += a4[u].x*b4[0].y + a4[u].y*b4[1].y + a4[u].z*b4[2].y + a4[u].w*b4[3].y;
                    acc[u][2] += a4[u].x*b4[0].z + a4[u].y*b4[1].z + a4[u].z*b4[2].z + a4[u].w*b4[3].z;
                    acc[u][3] += a4[u].x*b4[0].w + a4[u].y*b4[1].w + a4[u].z*b4[2].w + a4[u].w*b4[3].w;
                }
            }
#pragma unroll 4
            for (int k2 = 0; k2 < 64; k2++) {
                float c[2];
                c[0] = ssc[(ty2*2)*PS + k2];
                c[1] = ssc[(ty2*2+1)*PS + k2];
                float4 gv4 = *(const float4*)(sgZ2 + k2*PS + tx2*4);
                float gv[4] = {gv4.x, gv4.y, gv4.z, gv4.w};
#pragma unroll
                for (int u = 0; u < 2; u++)
#pragma unroll
                    for (int v = 0; v < 4; v++) acc[u][v] -= c[u] * gv[v];
            }
#pragma unroll
            for (int u = 0; u < 2; u++)
#pragma unroll
                for (int v = 0; v < 4; v++) sxv[(ty2*2+u)*TP + tx2*4+v] = acc[u][v];
        }
        __syncthreads();

        // I: out = xq + LN(Z2b)
        for (int i = w; i < 64; i += 16) {
            float z0 = sxv[i*TP + l], z1 = sxv[i*TP + l + 32];
            float mu = warpsum(z0 + z1) * (1.f/64.f);
            float d0 = z0 - mu, d1 = z1 - mu;
            float var = warpsum(d0*d0 + d1*d1) * (1.f/64.f);
            float rstd = rsqrtf(var + EPSc);
            size_t g = (tokbase + i) * Dn + h * 64;
            outp[g + l]      = sxq[i*TP + l]      + nwh[l]    * d0 * rstd + nbh[l];
            outp[g + l + 32] = sxq[i*TP + l + 32] + nwh[l+32] * d1 * rstd + nbh[l+32];
        }

        // J1: W1 -= (eta*xk)^T @ gZ1
        {
            float acc[4][8];
#pragma unroll
            for (int u = 0; u < 4; u++)
#pragma unroll
                for (int v = 0; v < 8; v++) acc[u][v] = 0.f;
#pragma unroll 4
            for (int i = 0; i < 64; i++) {
                float et = seta[i];
                float a[4];
#pragma unroll
                for (int u = 0; u < 4; u++) a[u] = et * sxk[i*TP + w*4+u];
                float4 g0 = *(const float4*)(gZ1r + i*256 + l*8);
                float4 g1 = *(const float4*)(gZ1r + i*256 + l*8 + 4);
                float gv[8] = {g0.x,g0.y,g0.z,g0.w,g1.x,g1.y,g1.z,g1.w};
#pragma unroll
                for (int u = 0; u < 4; u++)
#pragma unroll
                    for (int v = 0; v < 8; v++) acc[u][v] += a[u] * gv[v];
            }
#pragma unroll
            for (int u = 0; u < 4; u++) {
                int e = w * 4 + u;
                float4* wp = (float4*)(W1r + e*256 + l*8);
                float4 o0 = wp[0], o1 = wp[1];
                wp[0] = make_float4(o0.x-acc[u][0], o0.y-acc[u][1], o0.z-acc[u][2], o0.w-acc[u][3]);
                wp[1] = make_float4(o1.x-acc[u][4], o1.y-acc[u][5], o1.z-acc[u][6], o1.w-acc[u][7]);
            }
        }
        // J2: b1
        if (tid < 256) {
            float acc = 0.f;
#pragma unroll 8
            for (int i = 0; i < 64; i++) acc += seta[i] * gZ1r[i*256 + tid];
            b1sm[tid] -= acc;
        }
        // J3: W2 and W2T
        {
            float acc[4][8];
#pragma unroll
            for (int u = 0; u < 4; u++)
#pragma unroll
                for (int v = 0; v < 8; v++) acc[u][v] = 0.f;
#pragma unroll 4
            for (int i = 0; i < 64; i++) {
                float et = seta[i];
                float4 x0 = *(const float4*)(X2r + i*256 + ft*4);
                float a[4] = {et*x0.x, et*x0.y, et*x0.z, et*x0.w};
                float4 gv0 = *(const float4*)(sgZ2 + i*PS + jt*8);
                float4 gv1 = *(const float4*)(sgZ2 + i*PS + jt*8 + 4);
                float gv[8] = {gv0.x,gv0.y,gv0.z,gv0.w,gv1.x,gv1.y,gv1.z,gv1.w};
#pragma unroll
                for (int u = 0; u < 4; u++)
#pragma unroll
                    for (int v = 0; v < 8; v++) acc[u][v] += a[u] * gv[v];
            }
#pragma unroll
            for (int u = 0; u < 4; u++) {
                int f = ft * 4 + u;
                float4* wp0 = (float4*)(W2r + f*64 + jt*8);
                float4* wp1 = (float4*)(W2r + f*64 + jt*8 + 4);
                float4 o0 = wp0[0], o1 = wp1[0];
                wp0[0] = make_float4(o0.x-acc[u][0], o0.y-acc[u][1], o0.z-acc[u][2], o0.w-acc[u][3]);
                wp1[0] = make_float4(o1.x-acc[u][4], o1.y-acc[u][5], o1.z-acc[u][6], o1.w-acc[u][7]);
#pragma unroll
                for (int v = 0; v < 8; v++)
                    W2Tr[(jt*8+v)*256 + f] -= acc[u][v];
            }
        }
        // J4: b2
        if (tid < 64) {
            float acc = 0.f;
#pragma unroll 8
            for (int i = 0; i < 64; i++) acc += seta[i] * sgZ2[i*PS + tid];
            b2sm[tid] -= acc;
        }
        __syncthreads();
    }
}

// ---------------- Launch ----------------
extern "C" void kernel_launch(void* const* d_in, const int* in_sizes, int n_in,
                              void* d_out, int out_size)
{
    const float* x       = (const float*)d_in[0];
    const float* ln1_w   = (const float*)d_in[1];
    const float* ln1_b   = (const float*)d_in[2];
    const float* attn_wq = (const float*)d_in[3];
    const float* attn_wk = (const float*)d_in[4];
    const float* attn_wv = (const float*)d_in[5];
    const float* attn_wo = (const float*)d_in[6];
    const float* wq_w    = (const float*)d_in[7];
    const float* wq_b    = (const float*)d_in[8];
    const float* wk_w    = (const float*)d_in[9];
    const float* wk_b    = (const float*)d_in[10];
    const float* wv_w    = (const float*)d_in[11];
    const float* wv_b    = (const float*)d_in[12];
    const float* wo_w    = (const float*)d_in[13];
    const float* wo_b    = (const float*)d_in[14];
    const float* W1      = (const float*)d_in[15];
    const float* b1      = (const float*)d_in[16];
    const float* W2      = (const float*)d_in[17];
    const float* b2      = (const float*)d_in[18];
    const float* ttt_nw  = (const float*)d_in[19];
    const float* ttt_nb  = (const float*)d_in[20];
    const float* lr_w    = (const float*)d_in[21];
    const float* lr_b    = (const float*)d_in[22];
    const float* pn_w    = (const float*)d_in[23];
    const float* pn_b    = (const float*)d_in[24];
    const float* gate_a  = (const float*)d_in[25];
    float* out = (float*)d_out;

    float *p_h,*p_q,*p_k,*p_v,*p_o,*p_x1,*p_lr,*p_W1,*p_W2,*p_W2T,*p_X2,*p_gZ1,*p_X2b;
    cudaGetSymbolAddress((void**)&p_h,  g_h);
    cudaGetSymbolAddress((void**)&p_q,  g_q);
    cudaGetSymbolAddress((void**)&p_k,  g_k);
    cudaGetSymbolAddress((void**)&p_v,  g_v);
    cudaGetSymbolAddress((void**)&p_o,  g_o);
    cudaGetSymbolAddress((void**)&p_x1, g_x1);
    cudaGetSymbolAddress((void**)&p_lr, g_lr);
    cudaGetSymbolAddress((void**)&p_W1, g_W1s);
    cudaGetSymbolAddress((void**)&p_W2, g_W2s);
    cudaGetSymbolAddress((void**)&p_W2T,g_W2Ts);
    cudaGetSymbolAddress((void**)&p_X2, g_X2);
    cudaGetSymbolAddress((void**)&p_gZ1,g_gZ1);
    cudaGetSymbolAddress((void**)&p_X2b,g_X2b);

    cudaFuncSetAttribute(ttt_scan_kernel,   cudaFuncAttributeMaxDynamicSharedMemorySize, SCAN_SMEM);
    cudaFuncSetAttribute(attn_flash_kernel, cudaFuncAttributeMaxDynamicSharedMemorySize, ATT_SMEM);

    const int M = Bn * Sn;
    dim3 ggrid(Dn / 128, M / 128);          // (8, 32)
    dim3 ggrid3(Dn / 128, M / 128, 3);      // fused triples
    int nwarp_grid = (Bn * Sn * Hn) / 8;

    ln_kernel<<<M, 256>>>(x, ln1_w, ln1_b, p_h);
    gemm3_nt_kernel<<<ggrid3, 256>>>(p_h, attn_wq, attn_wk, attn_wv,
                                     p_q, p_k, p_v, nullptr, nullptr, nullptr);
    attn_flash_kernel<<<dim3(16, 64), 256, ATT_SMEM>>>(p_q, p_k, p_v, p_o);
    gemm_nt_kernel<<<ggrid, 256>>>(p_o, attn_wo, p_x1, nullptr, x, nullptr);
    gemm3_nt_kernel<<<ggrid3, 256>>>(p_x1, wq_w, wk_w, wv_w,
                                     p_q, p_k, p_v, wq_b, wk_b, wv_b);
    prep_kernel<<<nwarp_grid, 256>>>(p_q, p_k, p_v, ttt_nw, ttt_nb);
    lr_kernel<<<nwarp_grid, 256>>>(p_x1, lr_w, lr_b, p_lr);
    ttt_scan_kernel<<<Bn * Hn, 512, SCAN_SMEM>>>(
        p_q, p_k, p_v, p_lr, W1, b1, W2, b2, ttt_nw, ttt_nb,
        p_W1, p_W2, p_W2T, p_X2, p_gZ1, p_X2b, p_o);
    ln_kernel<<<M, 256>>>(p_o, pn_w, pn_b, p_h);
    gemm_nt_kernel<<<ggrid, 256>>>(p_h, wo_w, out, wo_b, p_x1, gate_a);
}

// round 6
// speedup vs baseline: 7.6159x; 1.0310x over previous
#include <cuda_runtime.h>
#include <math.h>

#define Bn 4
#define Sn 1024
#define Dn 1024
#define Hn 16
#define HDn 64
#define Cn 64
#define NCn 16
#define DFFn 256
#define EPSc 1e-6f
#define BSD (Bn*Sn*Dn)

typedef unsigned long long u64;
__device__ __forceinline__ u64 f2pack(float lo, float hi) {
    u64 r; asm("mov.b64 %0, {%1, %2};" : "=l"(r) : "f"(lo), "f"(hi)); return r;
}
__device__ __forceinline__ void f2unpack(u64 p, float& lo, float& hi) {
    asm("mov.b64 {%0, %1}, %2;" : "=f"(lo), "=f"(hi) : "l"(p));
}
__device__ __forceinline__ u64 ffma2(u64 a, u64 b, u64 c) {
    u64 d; asm("fma.rn.f32x2 %0, %1, %2, %3;" : "=l"(d) : "l"(a), "l"(b), "l"(c)); return d;
}
__device__ __forceinline__ void f4tou2(float4 f, u64& p0, u64& p1) {
    p0 = f2pack(f.x, f.y); p1 = f2pack(f.z, f.w);
}

__device__ float g_h [BSD];
__device__ float g_q [BSD];
__device__ float g_k [BSD];
__device__ float g_v [BSD];
__device__ float g_o [BSD];
__device__ float g_x1[BSD];
__device__ float g_lr[Bn*Hn*Sn];
__device__ float g_W1s [Bn*Hn*16384];
__device__ float g_W2s [Bn*Hn*16384];
__device__ float g_W2Ts[Bn*Hn*16384];
__device__ float g_X2  [Bn*Hn*16384];
__device__ float g_gZ1 [Bn*Hn*16384];
__device__ float g_X2b [Bn*Hn*16384];

__device__ __forceinline__ float warpsum(float v) {
#pragma unroll
    for (int o = 16; o > 0; o >>= 1) v += __shfl_xor_sync(0xffffffffu, v, o);
    return v;
}
__device__ __forceinline__ float hsum16(float v) {
#pragma unroll
    for (int o = 8; o > 0; o >>= 1) v += __shfl_xor_sync(0xffffffffu, v, o);
    return v;
}
__device__ __forceinline__ float hmax16(float v) {
#pragma unroll
    for (int o = 8; o > 0; o >>= 1) v = fmaxf(v, __shfl_xor_sync(0xffffffffu, v, o));
    return v;
}
__device__ __forceinline__ float blocksum256(float v) {
    __shared__ float red[8];
    int lane = threadIdx.x & 31, w = threadIdx.x >> 5;
    v = warpsum(v);
    if (lane == 0) red[w] = v;
    __syncthreads();
    float r = (lane < 8) ? red[lane] : 0.f;
    r = warpsum(r);
    __syncthreads();
    return r;
}
__device__ __forceinline__ float tanh_fast(float x) {
    float e = __expf(2.f * x);
    return 1.f - __fdividef(2.f, e + 1.f);
}

// ---------------- LayerNorm rows of 1024 ----------------
__global__ __launch_bounds__(256) void ln_kernel(
    const float* __restrict__ x, const float* __restrict__ g,
    const float* __restrict__ b, float* __restrict__ y)
{
    int row = blockIdx.x, tid = threadIdx.x;
    const float* xr = x + (size_t)row * Dn;
    float v[4]; float s = 0.f;
#pragma unroll
    for (int i = 0; i < 4; i++) { v[i] = xr[tid + 256 * i]; s += v[i]; }
    s = blocksum256(s);
    float mu = s * (1.f / Dn), ss = 0.f;
#pragma unroll
    for (int i = 0; i < 4; i++) { float d = v[i] - mu; ss += d * d; }
    ss = blocksum256(ss);
    float rstd = rsqrtf(ss * (1.f / Dn) + EPSc);
    float* yr = y + (size_t)row * Dn;
#pragma unroll
    for (int i = 0; i < 4; i++) {
        int c = tid + 256 * i;
        yr[c] = (v[i] - mu) * rstd * g[c] + b[c];
    }
}

// ---------------- GEMM core: C = A@B^T, FFMA2 inner ----------------
__device__ __forceinline__ void gemm_core(
    const float* __restrict__ A, const float* __restrict__ B, float* __restrict__ C,
    const float* __restrict__ bias, const float* __restrict__ res,
    const float* __restrict__ gate, int bm, int bn)
{
    const int N = 1024, K = 1024, BK = 16;
    __shared__ float As[BK][128];
    __shared__ float Bs[BK][128];
    int t = threadIdx.x, tx = t & 15, ty = t >> 4;
    u64 acc2[8][4];
#pragma unroll
    for (int i = 0; i < 8; i++)
#pragma unroll
        for (int j = 0; j < 4; j++) acc2[i][j] = 0ULL;

    int r128 = t >> 1, kc = (t & 1) * 8;
    const float* Ab = A + (size_t)(bm + r128) * K + kc;
    const float* Bb = B + (size_t)(bn + r128) * K + kc;
    float4 a0 = *(const float4*)(Ab);
    float4 a1 = *(const float4*)(Ab + 4);
    float4 b0 = *(const float4*)(Bb);
    float4 b1 = *(const float4*)(Bb + 4);

    for (int k0 = 0; k0 < K; k0 += BK) {
        As[kc+0][r128]=a0.x; As[kc+1][r128]=a0.y; As[kc+2][r128]=a0.z; As[kc+3][r128]=a0.w;
        As[kc+4][r128]=a1.x; As[kc+5][r128]=a1.y; As[kc+6][r128]=a1.z; As[kc+7][r128]=a1.w;
        Bs[kc+0][r128]=b0.x; Bs[kc+1][r128]=b0.y; Bs[kc+2][r128]=b0.z; Bs[kc+3][r128]=b0.w;
        Bs[kc+4][r128]=b1.x; Bs[kc+5][r128]=b1.y; Bs[kc+6][r128]=b1.z; Bs[kc+7][r128]=b1.w;
        __syncthreads();
        if (k0 + BK < K) {
            a0 = *(const float4*)(Ab + k0 + BK);
            a1 = *(const float4*)(Ab + k0 + BK + 4);
            b0 = *(const float4*)(Bb + k0 + BK);
            b1 = *(const float4*)(Bb + k0 + BK + 4);
        }
#pragma unroll
        for (int kk = 0; kk < BK; kk++) {
            float4 ra0 = *(const float4*)(&As[kk][ty * 4]);
            float4 ra1 = *(const float4*)(&As[kk][64 + ty * 4]);
            float4 rb0 = *(const float4*)(&Bs[kk][tx * 4]);
            float4 rb1 = *(const float4*)(&Bs[kk][64 + tx * 4]);
            u64 rb2[4];
            f4tou2(rb0, rb2[0], rb2[1]);
            f4tou2(rb1, rb2[2], rb2[3]);
            float ra[8] = {ra0.x,ra0.y,ra0.z,ra0.w,ra1.x,ra1.y,ra1.z,ra1.w};
#pragma unroll
            for (int i = 0; i < 8; i++) {
                u64 a2 = f2pack(ra[i], ra[i]);
#pragma unroll
                for (int j = 0; j < 4; j++) acc2[i][j] = ffma2(a2, rb2[j], acc2[i][j]);
            }
        }
        __syncthreads();
    }

    int na = bn + tx * 4, nb2 = bn + 64 + tx * 4;
    float bsv[8] = {0,0,0,0,0,0,0,0};
    if (bias) {
        float4 t0 = *(const float4*)(bias + na);
        float4 t1 = *(const float4*)(bias + nb2);
        bsv[0]=t0.x; bsv[1]=t0.y; bsv[2]=t0.z; bsv[3]=t0.w;
        bsv[4]=t1.x; bsv[5]=t1.y; bsv[6]=t1.z; bsv[7]=t1.w;
    }
    float gv[8];
    if (gate) {
        float4 t0 = *(const float4*)(gate + na);
        float4 t1 = *(const float4*)(gate + nb2);
        gv[0]=tanhf(t0.x); gv[1]=tanhf(t0.y); gv[2]=tanhf(t0.z); gv[3]=tanhf(t0.w);
        gv[4]=tanhf(t1.x); gv[5]=tanhf(t1.y); gv[6]=tanhf(t1.z); gv[7]=tanhf(t1.w);
    }
#pragma unroll
    for (int i = 0; i < 8; i++) {
        int m = (i < 4) ? (bm + ty * 4 + i) : (bm + 64 + ty * 4 + i - 4);
        float val[8];
#pragma unroll
        for (int j = 0; j < 4; j++) f2unpack(acc2[i][j], val[2*j], val[2*j+1]);
#pragma unroll
        for (int j = 0; j < 8; j++) val[j] += bsv[j];
        if (gate) {
            float4 r0 = *(const float4*)(res + (size_t)m * N + na);
            float4 r1 = *(const float4*)(res + (size_t)m * N + nb2);
            val[0]=r0.x+gv[0]*val[0]; val[1]=r0.y+gv[1]*val[1];
            val[2]=r0.z+gv[2]*val[2]; val[3]=r0.w+gv[3]*val[3];
            val[4]=r1.x+gv[4]*val[4]; val[5]=r1.y+gv[5]*val[5];
            val[6]=r1.z+gv[6]*val[6]; val[7]=r1.w+gv[7]*val[7];
        } else if (res) {
            float4 r0 = *(const float4*)(res + (size_t)m * N + na);
            float4 r1 = *(const float4*)(res + (size_t)m * N + nb2);
            val[0]+=r0.x; val[1]+=r0.y; val[2]+=r0.z; val[3]+=r0.w;
            val[4]+=r1.x; val[5]+=r1.y; val[6]+=r1.z; val[7]+=r1.w;
        }
        *(float4*)(C + (size_t)m * N + na)  = make_float4(val[0],val[1],val[2],val[3]);
        *(float4*)(C + (size_t)m * N + nb2) = make_float4(val[4],val[5],val[6],val[7]);
    }
}

__global__ __launch_bounds__(256) void gemm_nt_kernel(
    const float* __restrict__ A, const float* __restrict__ B, float* __restrict__ C,
    const float* __restrict__ bias, const float* __restrict__ res,
    const float* __restrict__ gate)
{
    gemm_core(A, B, C, bias, res, gate, blockIdx.y * 128, blockIdx.x * 128);
}

__global__ __launch_bounds__(256) void gemm3_nt_kernel(
    const float* __restrict__ A,
    const float* __restrict__ B0, const float* __restrict__ B1, const float* __restrict__ B2,
    float* __restrict__ C0, float* __restrict__ C1, float* __restrict__ C2,
    const float* __restrict__ b0, const float* __restrict__ b1, const float* __restrict__ b2)
{
    const float* B; float* C; const float* bias;
    if (blockIdx.z == 0)      { B = B0; C = C0; bias = b0; }
    else if (blockIdx.z == 1) { B = B1; C = C1; bias = b1; }
    else                      { B = B2; C = C2; bias = b2; }
    gemm_core(A, B, C, bias, nullptr, nullptr, blockIdx.y * 128, blockIdx.x * 128);
}

// ---------------- Flash attention ----------------
#define AQ 68
#define AK 68
#define AP 65
#define ATT_SMEM ((64*AQ + 64*AK + 64*64 + 64*AP) * 4)

__global__ __launch_bounds__(256) void attn_flash_kernel(
    const float* __restrict__ q, const float* __restrict__ k,
    const float* __restrict__ v, float* __restrict__ o)
{
    extern __shared__ float sm[];
    float* Qs = sm;
    float* Ks = Qs + 64 * AQ;
    float* Vs = Ks + 64 * AK;
    float* Ps = Vs + 64 * 64;

    int qt = blockIdx.x, bh = blockIdx.y;
    int b = bh >> 4, h = bh & 15;
    int tid = threadIdx.x, tx = tid & 15, ty = tid >> 4;
    size_t base = ((size_t)b * Sn) * Dn + h * HDn;

    for (int idx = tid; idx < 4096; idx += 256) {
        int r = idx >> 6, e = idx & 63;
        Qs[r * AQ + e] = q[base + (size_t)(qt * 64 + r) * Dn + e] * 0.125f;
    }
    float m[4], l[4];
    u64 oa2[4][2];
#pragma unroll
    for (int u = 0; u < 4; u++) {
        m[u] = -1e30f; l[u] = 0.f;
        oa2[u][0] = 0ULL; oa2[u][1] = 0ULL;
    }
    __syncthreads();

    for (int kt = 0; kt <= qt; kt++) {
        for (int idx = tid; idx < 4096; idx += 256) {
            int r = idx >> 6, e = idx & 63;
            size_t g = base + (size_t)(kt * 64 + r) * Dn + e;
            Ks[r * AK + e] = k[g];
            Vs[r * 64 + e] = v[g];
        }
        __syncthreads();

        // S = Q K^T, e-paired FFMA2 (lo/hi partial sums combined at end)
        u64 s2[4][4];
#pragma unroll
        for (int u = 0; u < 4; u++)
#pragma unroll
            for (int vv = 0; vv < 4; vv++) s2[u][vv] = 0ULL;
#pragma unroll 2
        for (int e0 = 0; e0 < 64; e0 += 4) {
            u64 qa2[4][2], ka2[4][2];
#pragma unroll
            for (int u = 0; u < 4; u++) {
                float4 f = *(const float4*)(Qs + (ty*4+u)*AQ + e0);
                f4tou2(f, qa2[u][0], qa2[u][1]);
            }
#pragma unroll
            for (int vv = 0; vv < 4; vv++) {
                float4 f = *(const float4*)(Ks + (tx*4+vv)*AK + e0);
                f4tou2(f, ka2[vv][0], ka2[vv][1]);
            }
#pragma unroll
            for (int u = 0; u < 4; u++)
#pragma unroll
                for (int vv = 0; vv < 4; vv++) {
                    s2[u][vv] = ffma2(qa2[u][0], ka2[vv][0], s2[u][vv]);
                    s2[u][vv] = ffma2(qa2[u][1], ka2[vv][1], s2[u][vv]);
                }
        }
        float acc[4][4];
#pragma unroll
        for (int u = 0; u < 4; u++)
#pragma unroll
            for (int vv = 0; vv < 4; vv++) {
                float lo, hi; f2unpack(s2[u][vv], lo, hi);
                acc[u][vv] = lo + hi;
            }
        bool diag = (kt == qt);
#pragma unroll
        for (int u = 0; u < 4; u++) {
            int r = ty * 4 + u;
            float mx = -1e30f;
#pragma unroll
            for (int vv = 0; vv < 4; vv++) {
                int c = tx * 4 + vv;
                if (diag && c > r) acc[u][vv] = -1e30f;
                mx = fmaxf(mx, acc[u][vv]);
            }
            mx = hmax16(mx);
            float nm = fmaxf(m[u], mx);
            float corr = __expf(m[u] - nm);
            float ps = 0.f;
#pragma unroll
            for (int vv = 0; vv < 4; vv++) {
                float p = __expf(acc[u][vv] - nm);
                Ps[r * AP + tx * 4 + vv] = p;
                ps += p;
            }
            ps = hsum16(ps);
            l[u] = l[u] * corr + ps;
            m[u] = nm;
            u64 c2 = f2pack(corr, corr);
            u64 z = 0ULL;
            oa2[u][0] = ffma2(oa2[u][0], c2, z);
            oa2[u][1] = ffma2(oa2[u][1], c2, z);
        }
        __syncthreads();
#pragma unroll 4
        for (int kc = 0; kc < 64; kc++) {
            float4 v4 = *(const float4*)(Vs + kc * 64 + tx * 4);
            u64 v2[2];
            f4tou2(v4, v2[0], v2[1]);
#pragma unroll
            for (int u = 0; u < 4; u++) {
                float p = Ps[(ty * 4 + u) * AP + kc];
                u64 p2 = f2pack(p, p);
                oa2[u][0] = ffma2(p2, v2[0], oa2[u][0]);
                oa2[u][1] = ffma2(p2, v2[1], oa2[u][1]);
            }
        }
        __syncthreads();
    }
#pragma unroll
    for (int u = 0; u < 4; u++) {
        float inv = __fdividef(1.f, l[u]);
        float o0, o1, o2, o3;
        f2unpack(oa2[u][0], o0, o1);
        f2unpack(oa2[u][1], o2, o3);
        size_t g = base + (size_t)(qt * 64 + ty * 4 + u) * Dn + tx * 4;
        *(float4*)(o + g) = make_float4(o0*inv, o1*inv, o2*inv, o3*inv);
    }
}

// ---------------- prep & lr ----------------
__global__ __launch_bounds__(256) void prep_kernel(
    float* __restrict__ XQ, float* __restrict__ XK, float* __restrict__ XV,
    const float* __restrict__ nw, const float* __restrict__ nb)
{
    int w = (blockIdx.x * blockDim.x + threadIdx.x) >> 5;
    if (w >= Bn * Sn * Hn) return;
    int lane = threadIdx.x & 31;
    int h = w & 15, bs = w >> 4;
    size_t base = (size_t)bs * Dn + h * HDn;
    float q0 = XQ[base + lane], q1 = XQ[base + lane + 32];
    float qi = 1.f / fmaxf(sqrtf(warpsum(q0*q0 + q1*q1)), 1e-12f);
    XQ[base + lane] = q0 * qi; XQ[base + lane + 32] = q1 * qi;
    float k0 = XK[base + lane], k1 = XK[base + lane + 32];
    float ki = 1.f / fmaxf(sqrtf(warpsum(k0*k0 + k1*k1)), 1e-12f);
    k0 *= ki; k1 *= ki;
    XK[base + lane] = k0; XK[base + lane + 32] = k1;
    float v0 = XV[base + lane], v1 = XV[base + lane + 32];
    float mu = warpsum(v0 + v1) * (1.f / 64.f);
    float d0 = v0 - mu, d1 = v1 - mu;
    float var = warpsum(d0*d0 + d1*d1) * (1.f / 64.f);
    float rstd = rsqrtf(var + EPSc);
    XV[base + lane]      = nw[h*64+lane]    * d0 * rstd + nb[h*64+lane]    + k0;
    XV[base + lane + 32] = nw[h*64+lane+32] * d1 * rstd + nb[h*64+lane+32] + k1;
}

__global__ __launch_bounds__(256) void lr_kernel(
    const float* __restrict__ x1, const float* __restrict__ lrw,
    const float* __restrict__ lrb, float* __restrict__ lro)
{
    int w = (blockIdx.x * blockDim.x + threadIdx.x) >> 5;
    if (w >= Bn * Sn * Hn) return;
    int lane = threadIdx.x & 31;
    int h = w & 15, bs = w >> 4;
    int b = bs >> 10, s = bs & (Sn - 1);
    const float* xr = x1 + (size_t)bs * Dn;
    const float* wr = lrw + h * Dn;
    float acc = 0.f;
    for (int c = lane; c < Dn; c += 32) acc += xr[c] * wr[c];
    acc = warpsum(acc);
    if (lane == 0)
        lro[(size_t)(b * Hn + h) * Sn + s] = 1.f / (1.f + __expf(-(acc + lrb[h])));
}

// ---------------- TTT scan, 512 threads, FFMA2 hot loops ----------------
#define TP 65
#define PS 68
#define SCAN_SMEM ((3*64*TP + 2*64*PS + 256 + 64 + 64) * 4)

__global__ __launch_bounds__(512) void ttt_scan_kernel(
    const float* __restrict__ XQ, const float* __restrict__ XK, const float* __restrict__ XV,
    const float* __restrict__ lr,
    const float* __restrict__ W1i, const float* __restrict__ b1i,
    const float* __restrict__ W2i, const float* __restrict__ b2i,
    const float* __restrict__ nw,  const float* __restrict__ nb,
    float* __restrict__ W1G, float* __restrict__ W2G, float* __restrict__ W2TG,
    float* __restrict__ X2G, float* __restrict__ gZ1G, float* __restrict__ X2bG,
    float* __restrict__ outp)
{
    extern __shared__ float sm[];
    float* sxq  = sm;
    float* sxk  = sxq + 64 * TP;
    float* sxv  = sxk + 64 * TP;
    float* ssc  = sxv + 64 * TP;
    float* sgZ2 = ssc + 64 * PS;
    float* b1sm = sgZ2 + 64 * PS;
    float* b2sm = b1sm + 256;
    float* seta = b2sm + 64;

    int bh = blockIdx.x, b = bh >> 4, h = bh & 15;
    int tid = threadIdx.x, w = tid >> 5, l = tid & 31;
    int ty2 = tid >> 4, tx2 = tid & 15;
    int ft = tid >> 3, jt = tid & 7;
    float* W1r  = W1G  + (size_t)bh * 16384;
    float* W2r  = W2G  + (size_t)bh * 16384;
    float* W2Tr = W2TG + (size_t)bh * 16384;
    float* X2r  = X2G  + (size_t)bh * 16384;
    float* gZ1r = gZ1G + (size_t)bh * 16384;
    float* X2br = X2bG + (size_t)bh * 16384;
    const float* nwh = nw + h * 64;
    const float* nbh = nb + h * 64;

    for (int idx = tid; idx < 16384; idx += 512) {
        W1r[idx] = W1i[(size_t)h * 16384 + idx];
        W2r[idx] = W2i[(size_t)h * 16384 + idx];
        int e = idx >> 8, f = idx & 255;
        W2Tr[idx] = W2i[(size_t)h * 16384 + f * 64 + e];
    }
    if (tid < 256) b1sm[tid] = b1i[h * 256 + tid];
    if (tid < 64)  b2sm[tid] = b2i[h * 64 + tid];
    __syncthreads();

    for (int n = 0; n < NCn; n++) {
        size_t tokbase = (size_t)b * Sn + n * Cn;
        for (int idx = tid; idx < 4096; idx += 512) {
            int i = idx >> 6, e = idx & 63;
            size_t g = (tokbase + i) * Dn + h * 64 + e;
            sxq[i * TP + e] = XQ[g];
            sxk[i * TP + e] = XK[g];
            sxv[i * TP + e] = XV[g];
        }
        if (tid < 64) seta[tid] = lr[(size_t)bh * Sn + n * 64 + tid] * (1.f / 64.f);
        __syncthreads();

        // A: Z1 = xk@W1 + b1 -> X2, gZ1=gelu'   (FFMA2)
        {
            u64 acc2[4][4];
            {
                float4 bb0 = *(const float4*)(b1sm + l * 8);
                float4 bb1 = *(const float4*)(b1sm + l * 8 + 4);
                u64 p0, p1, p2, p3;
                f4tou2(bb0, p0, p1); f4tou2(bb1, p2, p3);
#pragma unroll
                for (int u = 0; u < 4; u++) {
                    acc2[u][0] = p0; acc2[u][1] = p1; acc2[u][2] = p2; acc2[u][3] = p3;
                }
            }
#pragma unroll 4
            for (int e = 0; e < 64; e++) {
                float4 w0 = *(const float4*)(W1r + e * 256 + l * 8);
                float4 w1 = *(const float4*)(W1r + e * 256 + l * 8 + 4);
                u64 w2[4];
                f4tou2(w0, w2[0], w2[1]); f4tou2(w1, w2[2], w2[3]);
#pragma unroll
                for (int u = 0; u < 4; u++) {
                    float a = sxk[(w * 4 + u) * TP + e];
                    u64 a2 = f2pack(a, a);
#pragma unroll
                    for (int p = 0; p < 4; p++) acc2[u][p] = ffma2(a2, w2[p], acc2[u][p]);
                }
            }
#pragma unroll
            for (int u = 0; u < 4; u++) {
                int row = w * 4 + u;
                float zz[8], x2v[8], gbv[8];
#pragma unroll
                for (int p = 0; p < 4; p++) f2unpack(acc2[u][p], zz[2*p], zz[2*p+1]);
#pragma unroll
                for (int v = 0; v < 8; v++) {
                    float z = zz[v];
                    float t = tanh_fast(0.79788456f * (z + 0.044715f * z * z * z));
                    x2v[v] = 0.5f * z * (1.f + t);
                    gbv[v] = 0.5f * z * (1.f - t * t) * (0.79788456f + 0.1070322243f * z * z)
                           + 0.5f * (1.f + t);
                }
                float4* xp = (float4*)(X2r + row * 256 + l * 8);
                xp[0] = make_float4(x2v[0],x2v[1],x2v[2],x2v[3]);
                xp[1] = make_float4(x2v[4],x2v[5],x2v[6],x2v[7]);
                float4* gp = (float4*)(gZ1r + row * 256 + l * 8);
                gp[0] = make_float4(gbv[0],gbv[1],gbv[2],gbv[3]);
                gp[1] = make_float4(gbv[4],gbv[5],gbv[6],gbv[7]);
            }
        }
        __syncthreads();

        // B: Z2 = X2@W2 + b2 -> ssc
        {
            float acc[2][4];
#pragma unroll
            for (int u = 0; u < 2; u++)
#pragma unroll
                for (int v = 0; v < 4; v++) acc[u][v] = b2sm[tx2 * 4 + v];
#pragma unroll 4
            for (int f0 = 0; f0 < 256; f0 += 4) {
                float4 a4[2], b4[4];
#pragma unroll
                for (int u = 0; u < 2; u++) a4[u] = *(const float4*)(X2r + (ty2*2+u)*256 + f0);
#pragma unroll
                for (int d = 0; d < 4; d++) b4[d] = *(const float4*)(W2r + (f0+d)*64 + tx2*4);
#pragma unroll
                for (int u = 0; u < 2; u++) {
                    acc[u][0] += a4[u].x*b4[0].x + a4[u].y*b4[1].x + a4[u].z*b4[2].x + a4[u].w*b4[3].x;
                    acc[u][1] += a4[u].x*b4[0].y + a4[u].y*b4[1].y + a4[u].z*b4[2].y + a4[u].w*b4[3].y;
                    acc[u][2] += a4[u].x*b4[0].z + a4[u].y*b4[1].z + a4[u].z*b4[2].z + a4[u].w*b4[3].z;
                    acc[u][3] += a4[u].x*b4[0].w + a4[u].y*b4[1].w + a4[u].z*b4[2].w + a4[u].w*b4[3].w;
                }
            }
#pragma unroll
            for (int u = 0; u < 2; u++)
#pragma unroll
                for (int v = 0; v < 4; v++) ssc[(ty2*2+u)*PS + tx2*4+v] = acc[u][v];
        }
        __syncthreads();

        // C: gZ2 = ln_l2_bwd(Z2, xv-xk)
        for (int i = w; i < 64; i += 16) {
            float z0 = ssc[i*PS + l], z1 = ssc[i*PS + l + 32];
            float mu = warpsum(z0 + z1) * (1.f/64.f);
            float d0 = z0 - mu, d1 = z1 - mu;
            float var = warpsum(d0*d0 + d1*d1) * (1.f/64.f);
            float rstd = rsqrtf(var + EPSc);
            float xh0 = d0 * rstd, xh1 = d1 * rstd;
            float g0 = nwh[l], g1 = nwh[l+32];
            float t0 = sxv[i*TP + l] - sxk[i*TP + l];
            float t1 = sxv[i*TP + l + 32] - sxk[i*TP + l + 32];
            float gh0 = (g0*xh0 + nbh[l]    - t0) * g0;
            float gh1 = (g1*xh1 + nbh[l+32] - t1) * g1;
            float sgh = warpsum(gh0 + gh1);
            float sgx = warpsum(gh0*xh0 + gh1*xh1);
            float cc = rstd * (1.f/64.f);
            sgZ2[i*PS + l]      = (64.f*gh0 - sgh - xh0*sgx) * cc;
            sgZ2[i*PS + l + 32] = (64.f*gh1 - sgh - xh1*sgx) * cc;
        }
        __syncthreads();

        // D: gZ1 = (gZ2 @ W2^T) * gb   (FFMA2)
        {
            u64 acc2[4][4];
#pragma unroll
            for (int u = 0; u < 4; u++)
#pragma unroll
                for (int p = 0; p < 4; p++) acc2[u][p] = 0ULL;
#pragma unroll 4
            for (int e = 0; e < 64; e++) {
                float4 w0 = *(const float4*)(W2Tr + e*256 + l*8);
                float4 w1 = *(const float4*)(W2Tr + e*256 + l*8 + 4);
                u64 w2[4];
                f4tou2(w0, w2[0], w2[1]); f4tou2(w1, w2[2], w2[3]);
#pragma unroll
                for (int u = 0; u < 4; u++) {
                    float a = sgZ2[(w*4+u)*PS + e];
                    u64 a2 = f2pack(a, a);
#pragma unroll
                    for (int p = 0; p < 4; p++) acc2[u][p] = ffma2(a2, w2[p], acc2[u][p]);
                }
            }
#pragma unroll
            for (int u = 0; u < 4; u++) {
                int row = w * 4 + u;
                float av[8];
#pragma unroll
                for (int p = 0; p < 4; p++) f2unpack(acc2[u][p], av[2*p], av[2*p+1]);
                float4* gp = (float4*)(gZ1r + row * 256 + l * 8);
                float4 g0 = gp[0], g1 = gp[1];
                gp[0] = make_float4(av[0]*g0.x, av[1]*g0.y, av[2]*g0.z, av[3]*g0.w);
                gp[1] = make_float4(av[4]*g1.x, av[5]*g1.y, av[6]*g1.z, av[7]*g1.w);
            }
        }
        __syncthreads();

        // E: coef1 = eta[k]*(tril(xq@xk^T)+1) -> ssc
        {
            float acc[2][4];
#pragma unroll
            for (int u = 0; u < 2; u++)
#pragma unroll
                for (int v = 0; v < 4; v++) acc[u][v] = 0.f;
            if (tx2 * 4 <= ty2 * 2 + 1) {
#pragma unroll 4
                for (int e = 0; e < 64; e++) {
                    float a[2], bb[4];
#pragma unroll
                    for (int u = 0; u < 2; u++) a[u]  = sxq[(ty2*2+u)*TP + e];
#pragma unroll
                    for (int v = 0; v < 4; v++) bb[v] = sxk[(tx2*4+v)*TP + e];
#pragma unroll
                    for (int u = 0; u < 2; u++)
#pragma unroll
                        for (int v = 0; v < 4; v++) acc[u][v] += a[u] * bb[v];
                }
            }
#pragma unroll
            for (int u = 0; u < 2; u++) {
                int i = ty2 * 2 + u;
#pragma unroll
                for (int v = 0; v < 4; v++) {
                    int kk = tx2 * 4 + v;
                    ssc[i*PS + kk] = (kk <= i) ? seta[kk] * (acc[u][v] + 1.f) : 0.f;
                }
            }
        }
        __syncthreads();

        // F: Z1b = xq@W1 + b1 - coef1@gZ1 ; X2b = gelu   (FFMA2)
        {
            u64 acc2[4][4];
            {
                float4 bb0 = *(const float4*)(b1sm + l * 8);
                float4 bb1 = *(const float4*)(b1sm + l * 8 + 4);
                u64 p0, p1, p2, p3;
                f4tou2(bb0, p0, p1); f4tou2(bb1, p2, p3);
#pragma unroll
                for (int u = 0; u < 4; u++) {
                    acc2[u][0] = p0; acc2[u][1] = p1; acc2[u][2] = p2; acc2[u][3] = p3;
                }
            }
#pragma unroll 4
            for (int e = 0; e < 64; e++) {
                float4 w0 = *(const float4*)(W1r + e*256 + l*8);
                float4 w1 = *(const float4*)(W1r + e*256 + l*8 + 4);
                u64 w2[4];
                f4tou2(w0, w2[0], w2[1]); f4tou2(w1, w2[2], w2[3]);
#pragma unroll
                for (int u = 0; u < 4; u++) {
                    float a = sxq[(w*4+u)*TP + e];
                    u64 a2 = f2pack(a, a);
#pragma unroll
                    for (int p = 0; p < 4; p++) acc2[u][p] = ffma2(a2, w2[p], acc2[u][p]);
                }
            }
#pragma unroll 4
            for (int k2 = 0; k2 < 64; k2++) {
                float4 g0 = *(const float4*)(gZ1r + k2*256 + l*8);
                float4 g1 = *(const float4*)(gZ1r + k2*256 + l*8 + 4);
                u64 gv2[4];
                f4tou2(g0, gv2[0], gv2[1]); f4tou2(g1, gv2[2], gv2[3]);
#pragma unroll
                for (int u = 0; u < 4; u++) {
                    float c = -ssc[(w*4+u)*PS + k2];
                    u64 c2 = f2pack(c, c);
#pragma unroll
                    for (int p = 0; p < 4; p++) acc2[u][p] = ffma2(c2, gv2[p], acc2[u][p]);
                }
            }
#pragma unroll
            for (int u = 0; u < 4; u++) {
                int row = w * 4 + u;
                float zz[8], xv2[8];
#pragma unroll
                for (int p = 0; p < 4; p++) f2unpack(acc2[u][p], zz[2*p], zz[2*p+1]);
#pragma unroll
                for (int v = 0; v < 8; v++) {
                    float z = zz[v];
                    float t = tanh_fast(0.79788456f * (z + 0.044715f * z * z * z));
                    xv2[v] = 0.5f * z * (1.f + t);
                }
                float4* xp = (float4*)(X2br + row * 256 + l * 8);
                xp[0] = make_float4(xv2[0],xv2[1],xv2[2],xv2[3]);
                xp[1] = make_float4(xv2[4],xv2[5],xv2[6],xv2[7]);
            }
        }
        __syncthreads();

        // G: coef2 = eta[j]*(tril(X2b@X2^T)+1) -> ssc
        {
            float acc[2][4];
#pragma unroll
            for (int u = 0; u < 2; u++)
#pragma unroll
                for (int v = 0; v < 4; v++) acc[u][v] = 0.f;
            if (tx2 * 4 <= ty2 * 2 + 1) {
#pragma unroll 2
                for (int f0 = 0; f0 < 256; f0 += 4) {
                    float4 a4[2], b4[4];
#pragma unroll
                    for (int u = 0; u < 2; u++) a4[u] = *(const float4*)(X2br + (ty2*2+u)*256 + f0);
#pragma unroll
                    for (int v = 0; v < 4; v++) b4[v] = *(const float4*)(X2r + (tx2*4+v)*256 + f0);
#pragma unroll
                    for (int u = 0; u < 2; u++)
#pragma unroll
                        for (int v = 0; v < 4; v++)
                            acc[u][v] += a4[u].x*b4[v].x + a4[u].y*b4[v].y
                                       + a4[u].z*b4[v].z + a4[u].w*b4[v].w;
                }
            }
#pragma unroll
            for (int u = 0; u < 2; u++) {
                int i = ty2 * 2 + u;
#pragma unroll
                for (int v = 0; v < 4; v++) {
                    int j = tx2 * 4 + v;
                    ssc[i*PS + j] = (j <= i) ? seta[j] * (acc[u][v] + 1.f) : 0.f;
                }
            }
        }
        __syncthreads();

        // H: Z2b = X2b@W2 + b2 - coef2@gZ2 -> sxv
        {
            float acc[2][4];
#pragma unroll
            for (int u = 0; u < 2; u++)
#pragma unroll
                for (int v = 0; v < 4; v++) acc[u][v] = b2sm[tx2 * 4 + v];
#pragma unroll 4
            for (int f0 = 0; f0 < 256; f0 += 4) {
                float4 a4[2], b4[4];
#pragma unroll
                for (int u = 0; u < 2; u++) a4[u] = *(const float4*)(X2br + (ty2*2+u)*256 + f0);
#pragma unroll
                for (int d = 0; d < 4; d++) b4[d] = *(const float4*)(W2r + (f0+d)*64 + tx2*4);
#pragma unroll
                for (int u = 0; u < 2; u++) {
                    acc[u][0] += a4[u].x*b4[0].x + a4[u].y*b4[1].x + a4[u].z*b4[2].x + a4[u].w*b4[3].x;
                    acc[u][1] += a4[u].x*b4[0].y + a4[u].y*b4[1].y + a4[u].z*b4[2].y + a4[u].w*b4[3].y;
                    acc[u][2] += a4[u].x*b4[0].z + a4[u].y*b4[1].z + a4[u].z*b4[2].z + a4[u].w*b4[3].z;
                    acc[u][3] += a4[u].x*b4[0].w + a4[u].y*b4[1].w + a4[u].z*b4[2].w + a4[u].w*b4[3].w;
                }
            }
#pragma unroll 4
            for (int k2 = 0; k2 < 64; k2++) {
                float c[2];
                c[0] = ssc[(ty2*2)*PS + k2];
                c[1] = ssc[(ty2*2+1)*PS + k2];
                float4 gv4 = *(const float4*)(sgZ2 + k2*PS + tx2*4);
                float gv[4] = {gv4.x, gv4.y, gv4.z, gv4.w};
#pragma unroll
                for (int u = 0; u < 2; u++)
#pragma unroll
                    for (int v = 0; v < 4; v++) acc[u][v] -= c[u] * gv[v];
            }
#pragma unroll
            for (int u = 0; u < 2; u++)
#pragma unroll
                for (int v = 0; v < 4; v++) sxv[(ty2*2+u)*TP + tx2*4+v] = acc[u][v];
        }
        __syncthreads();

        // I: out = xq + LN(Z2b)
        for (int i = w; i < 64; i += 16) {
            float z0 = sxv[i*TP + l], z1 = sxv[i*TP + l + 32];
            float mu = warpsum(z0 + z1) * (1.f/64.f);
            float d0 = z0 - mu, d1 = z1 - mu;
            float var = warpsum(d0*d0 + d1*d1) * (1.f/64.f);
            float rstd = rsqrtf(var + EPSc);
            size_t g = (tokbase + i) * Dn + h * 64;
            outp[g + l]      = sxq[i*TP + l]      + nwh[l]    * d0 * rstd + nbh[l];
            outp[g + l + 32] = sxq[i*TP + l + 32] + nwh[l+32] * d1 * rstd + nbh[l+32];
        }

        // J1: W1 -= (eta*xk)^T @ gZ1   (FFMA2)
        {
            u64 acc2[4][4];
#pragma unroll
            for (int u = 0; u < 4; u++)
#pragma unroll
                for (int p = 0; p < 4; p++) acc2[u][p] = 0ULL;
#pragma unroll 4
            for (int i = 0; i < 64; i++) {
                float et = seta[i];
                float4 g0 = *(const float4*)(gZ1r + i*256 + l*8);
                float4 g1 = *(const float4*)(gZ1r + i*256 + l*8 + 4);
                u64 gv2[4];
                f4tou2(g0, gv2[0], gv2[1]); f4tou2(g1, gv2[2], gv2[3]);
#pragma unroll
                for (int u = 0; u < 4; u++) {
                    float a = et * sxk[i*TP + w*4+u];
                    u64 a2 = f2pack(a, a);
#pragma unroll
                    for (int p = 0; p < 4; p++) acc2[u][p] = ffma2(a2, gv2[p], acc2[u][p]);
                }
            }
#pragma unroll
            for (int u = 0; u < 4; u++) {
                int e = w * 4 + u;
                float av[8];
#pragma unroll
                for (int p = 0; p < 4; p++) f2unpack(acc2[u][p], av[2*p], av[2*p+1]);
                float4* wp = (float4*)(W1r + e*256 + l*8);
                float4 o0 = wp[0], o1 = wp[1];
                wp[0] = make_float4(o0.x-av[0], o0.y-av[1], o0.z-av[2], o0.w-av[3]);
                wp[1] = make_float4(o1.x-av[4], o1.y-av[5], o1.z-av[6], o1.w-av[7]);
            }
        }
        // J2: b1
        if (tid < 256) {
            float acc = 0.f;
#pragma unroll 8
            for (int i = 0; i < 64; i++) acc += seta[i] * gZ1r[i*256 + tid];
            b1sm[tid] -= acc;
        }
        // J3: W2 and W2T   (FFMA2)
        {
            u64 acc2[4][4];
#pragma unroll
            for (int u = 0; u < 4; u++)
#pragma unroll
                for (int p = 0; p < 4; p++) acc2[u][p] = 0ULL;
#pragma unroll 4
            for (int i = 0; i < 64; i++) {
                float et = seta[i];
                float4 x0 = *(const float4*)(X2r + i*256 + ft*4);
                float4 gv0 = *(const float4*)(sgZ2 + i*PS + jt*8);
                float4 gv1 = *(const float4*)(sgZ2 + i*PS + jt*8 + 4);
                u64 gv2[4];
                f4tou2(gv0, gv2[0], gv2[1]); f4tou2(gv1, gv2[2], gv2[3]);
                float a[4] = {et*x0.x, et*x0.y, et*x0.z, et*x0.w};
#pragma unroll
                for (int u = 0; u < 4; u++) {
                    u64 a2 = f2pack(a[u], a[u]);
#pragma unroll
                    for (int p = 0; p < 4; p++) acc2[u][p] = ffma2(a2, gv2[p], acc2[u][p]);
                }
            }
#pragma unroll
            for (int u = 0; u < 4; u++) {
                int f = ft * 4 + u;
                float av[8];
#pragma unroll
                for (int p = 0; p < 4; p++) f2unpack(acc2[u][p], av[2*p], av[2*p+1]);
                float4* wp0 = (float4*)(W2r + f*64 + jt*8);
                float4* wp1 = (float4*)(W2r + f*64 + jt*8 + 4);
                float4 o0 = wp0[0], o1 = wp1[0];
                wp0[0] = make_float4(o0.x-av[0], o0.y-av[1], o0.z-av[2], o0.w-av[3]);
                wp1[0] = make_float4(o1.x-av[4], o1.y-av[5], o1.z-av[6], o1.w-av[7]);
#pragma unroll
                for (int v = 0; v < 8; v++)
                    W2Tr[(jt*8+v)*256 + f] -= av[v];
            }
        }
        // J4: b2
        if (tid < 64) {
            float acc = 0.f;
#pragma unroll 8
            for (int i = 0; i < 64; i++) acc += seta[i] * sgZ2[i*PS + tid];
            b2sm[tid] -= acc;
        }
        __syncthreads();
    }
}

// ---------------- Launch ----------------
extern "C" void kernel_launch(void* const* d_in, const int* in_sizes, int n_in,
                              void* d_out, int out_size)
{
    const float* x       = (const float*)d_in[0];
    const float* ln1_w   = (const float*)d_in[1];
    const float* ln1_b   = (const float*)d_in[2];
    const float* attn_wq = (const float*)d_in[3];
    const float* attn_wk = (const float*)d_in[4];
    const float* attn_wv = (const float*)d_in[5];
    const float* attn_wo = (const float*)d_in[6];
    const float* wq_w    = (const float*)d_in[7];
    const float* wq_b    = (const float*)d_in[8];
    const float* wk_w    = (const float*)d_in[9];
    const float* wk_b    = (const float*)d_in[10];
    const float* wv_w    = (const float*)d_in[11];
    const float* wv_b    = (const float*)d_in[12];
    const float* wo_w    = (const float*)d_in[13];
    const float* wo_b    = (const float*)d_in[14];
    const float* W1      = (const float*)d_in[15];
    const float* b1      = (const float*)d_in[16];
    const float* W2      = (const float*)d_in[17];
    const float* b2      = (const float*)d_in[18];
    const float* ttt_nw  = (const float*)d_in[19];
    const float* ttt_nb  = (const float*)d_in[20];
    const float* lr_w    = (const float*)d_in[21];
    const float* lr_b    = (const float*)d_in[22];
    const float* pn_w    = (const float*)d_in[23];
    const float* pn_b    = (const float*)d_in[24];
    const float* gate_a  = (const float*)d_in[25];
    float* out = (float*)d_out;

    float *p_h,*p_q,*p_k,*p_v,*p_o,*p_x1,*p_lr,*p_W1,*p_W2,*p_W2T,*p_X2,*p_gZ1,*p_X2b;
    cudaGetSymbolAddress((void**)&p_h,  g_h);
    cudaGetSymbolAddress((void**)&p_q,  g_q);
    cudaGetSymbolAddress((void**)&p_k,  g_k);
    cudaGetSymbolAddress((void**)&p_v,  g_v);
    cudaGetSymbolAddress((void**)&p_o,  g_o);
    cudaGetSymbolAddress((void**)&p_x1, g_x1);
    cudaGetSymbolAddress((void**)&p_lr, g_lr);
    cudaGetSymbolAddress((void**)&p_W1, g_W1s);
    cudaGetSymbolAddress((void**)&p_W2, g_W2s);
    cudaGetSymbolAddress((void**)&p_W2T,g_W2Ts);
    cudaGetSymbolAddress((void**)&p_X2, g_X2);
    cudaGetSymbolAddress((void**)&p_gZ1,g_gZ1);
    cudaGetSymbolAddress((void**)&p_X2b,g_X2b);

    cudaFuncSetAttribute(ttt_scan_kernel,   cudaFuncAttributeMaxDynamicSharedMemorySize, SCAN_SMEM);
    cudaFuncSetAttribute(attn_flash_kernel, cudaFuncAttributeMaxDynamicSharedMemorySize, ATT_SMEM);

    const int M = Bn * Sn;
    dim3 ggrid(Dn / 128, M / 128);
    dim3 ggrid3(Dn / 128, M / 128, 3);
    int nwarp_grid = (Bn * Sn * Hn) / 8;

    ln_kernel<<<M, 256>>>(x, ln1_w, ln1_b, p_h);
    gemm3_nt_kernel<<<ggrid3, 256>>>(p_h, attn_wq, attn_wk, attn_wv,
                                     p_q, p_k, p_v, nullptr, nullptr, nullptr);
    attn_flash_kernel<<<dim3(16, 64), 256, ATT_SMEM>>>(p_q, p_k, p_v, p_o);
    gemm_nt_kernel<<<ggrid, 256>>>(p_o, attn_wo, p_x1, nullptr, x, nullptr);
    gemm3_nt_kernel<<<ggrid3, 256>>>(p_x1, wq_w, wk_w, wv_w,
                                     p_q, p_k, p_v, wq_b, wk_b, wv_b);
    prep_kernel<<<nwarp_grid, 256>>>(p_q, p_k, p_v, ttt_nw, ttt_nb);
    lr_kernel<<<nwarp_grid, 256>>>(p_x1, lr_w, lr_b, p_lr);
    ttt_scan_kernel<<<Bn * Hn, 512, SCAN_SMEM>>>(
        p_q, p_k, p_v, p_lr, W1, b1, W2, b2, ttt_nw, ttt_nb,
        p_W1, p_W2, p_W2T, p_X2, p_gZ1, p_X2b, p_o);
    ln_kernel<<<M, 256>>>(p_o, pn_w, pn_b, p_h);
    gemm_nt_kernel<<<ggrid, 256>>>(p_h, wo_w, out, wo_b, p_x1, gate_a);
}

// round 7
// speedup vs baseline: 8.8973x; 1.1683x over previous
#include <cuda_runtime.h>
#include <math.h>

#define Bn 4
#define Sn 1024
#define Dn 1024
#define Hn 16
#define HDn 64
#define Cn 64
#define NCn 16
#define DFFn 256
#define EPSc 1e-6f
#define BSD (Bn*Sn*Dn)

typedef unsigned long long u64;
__device__ __forceinline__ u64 f2pack(float lo, float hi) {
    u64 r; asm("mov.b64 %0, {%1, %2};" : "=l"(r) : "f"(lo), "f"(hi)); return r;
}
__device__ __forceinline__ void f2unpack(u64 p, float& lo, float& hi) {
    asm("mov.b64 {%0, %1}, %2;" : "=f"(lo), "=f"(hi) : "l"(p));
}
__device__ __forceinline__ u64 ffma2(u64 a, u64 b, u64 c) {
    u64 d; asm("fma.rn.f32x2 %0, %1, %2, %3;" : "=l"(d) : "l"(a), "l"(b), "l"(c)); return d;
}
__device__ __forceinline__ void f4tou2(float4 f, u64& p0, u64& p1) {
    p0 = f2pack(f.x, f.y); p1 = f2pack(f.z, f.w);
}
__device__ __forceinline__ unsigned f2tf32(float f) {
    unsigned r; asm("cvt.rna.tf32.f32 %0, %1;" : "=r"(r) : "f"(f)); return r;
}
__device__ __forceinline__ void mma_tf32(float* c, const unsigned* a, const unsigned* b) {
    asm volatile("mma.sync.aligned.m16n8k8.row.col.f32.tf32.tf32.f32 "
        "{%0,%1,%2,%3}, {%4,%5,%6,%7}, {%8,%9}, {%0,%1,%2,%3};"
        : "+f"(c[0]), "+f"(c[1]), "+f"(c[2]), "+f"(c[3])
        : "r"(a[0]), "r"(a[1]), "r"(a[2]), "r"(a[3]), "r"(b[0]), "r"(b[1]));
}

__device__ float g_h [BSD];
__device__ float g_q [BSD];
__device__ float g_k [BSD];
__device__ float g_v [BSD];
__device__ float g_o [BSD];
__device__ float g_x1[BSD];
__device__ float g_lr[Bn*Hn*Sn];
__device__ float g_W1s [Bn*Hn*16384];
__device__ float g_W2s [Bn*Hn*16384];
__device__ float g_W2Ts[Bn*Hn*16384];
__device__ float g_X2  [Bn*Hn*16384];
__device__ float g_gZ1 [Bn*Hn*16384];
__device__ float g_X2b [Bn*Hn*16384];

__device__ __forceinline__ float warpsum(float v) {
#pragma unroll
    for (int o = 16; o > 0; o >>= 1) v += __shfl_xor_sync(0xffffffffu, v, o);
    return v;
}
__device__ __forceinline__ float hsum16(float v) {
#pragma unroll
    for (int o = 8; o > 0; o >>= 1) v += __shfl_xor_sync(0xffffffffu, v, o);
    return v;
}
__device__ __forceinline__ float hmax16(float v) {
#pragma unroll
    for (int o = 8; o > 0; o >>= 1) v = fmaxf(v, __shfl_xor_sync(0xffffffffu, v, o));
    return v;
}
__device__ __forceinline__ float blocksum256(float v) {
    __shared__ float red[8];
    int lane = threadIdx.x & 31, w = threadIdx.x >> 5;
    v = warpsum(v);
    if (lane == 0) red[w] = v;
    __syncthreads();
    float r = (lane < 8) ? red[lane] : 0.f;
    r = warpsum(r);
    __syncthreads();
    return r;
}
__device__ __forceinline__ float tanh_fast(float x) {
    float e = __expf(2.f * x);
    return 1.f - __fdividef(2.f, e + 1.f);
}

// ---------------- LayerNorm rows of 1024 ----------------
__global__ __launch_bounds__(256) void ln_kernel(
    const float* __restrict__ x, const float* __restrict__ g,
    const float* __restrict__ b, float* __restrict__ y)
{
    int row = blockIdx.x, tid = threadIdx.x;
    const float* xr = x + (size_t)row * Dn;
    float v[4]; float s = 0.f;
#pragma unroll
    for (int i = 0; i < 4; i++) { v[i] = xr[tid + 256 * i]; s += v[i]; }
    s = blocksum256(s);
    float mu = s * (1.f / Dn), ss = 0.f;
#pragma unroll
    for (int i = 0; i < 4; i++) { float d = v[i] - mu; ss += d * d; }
    ss = blocksum256(ss);
    float rstd = rsqrtf(ss * (1.f / Dn) + EPSc);
    float* yr = y + (size_t)row * Dn;
#pragma unroll
    for (int i = 0; i < 4; i++) {
        int c = tid + 256 * i;
        yr[c] = (v[i] - mu) * rstd * g[c] + b[c];
    }
}

// ---------------- tf32 tensor-core GEMM: C = A@B^T (+bias)(+res)(gate) ---
// M=4096,N=1024,K=1024. BM=BN=128, BK=16, 256 thr = 8 warps,
// warp tile 32x64 (2 x 8 mma m16n8k8 tiles). smem [k][m]/[k][n] stride 136.
#define GSTR 136
__device__ __forceinline__ void gemm_core(
    const float* __restrict__ A, const float* __restrict__ B, float* __restrict__ C,
    const float* __restrict__ bias, const float* __restrict__ res,
    const float* __restrict__ gate, int bm, int bn)
{
    const int N = 1024, K = 1024, BK = 16;
    __shared__ unsigned As[BK][GSTR];
    __shared__ unsigned Bs[BK][GSTR];
    int t = threadIdx.x;
    int warp = t >> 5, lane = t & 31;
    int wm = warp >> 1, wn = warp & 1;          // 4 x 2 warp grid
    int g = lane >> 2, tg = lane & 3;

    float acc[2][8][4];
#pragma unroll
    for (int mt = 0; mt < 2; mt++)
#pragma unroll
        for (int nt = 0; nt < 8; nt++)
#pragma unroll
            for (int r = 0; r < 4; r++) acc[mt][nt][r] = 0.f;

    int r128 = t >> 1, kc = (t & 1) * 8;
    const float* Ab = A + (size_t)(bm + r128) * K + kc;
    const float* Bb = B + (size_t)(bn + r128) * K + kc;
    float4 a0 = *(const float4*)(Ab);
    float4 a1 = *(const float4*)(Ab + 4);
    float4 b0 = *(const float4*)(Bb);
    float4 b1 = *(const float4*)(Bb + 4);

    for (int k0 = 0; k0 < K; k0 += BK) {
        As[kc+0][r128]=f2tf32(a0.x); As[kc+1][r128]=f2tf32(a0.y);
        As[kc+2][r128]=f2tf32(a0.z); As[kc+3][r128]=f2tf32(a0.w);
        As[kc+4][r128]=f2tf32(a1.x); As[kc+5][r128]=f2tf32(a1.y);
        As[kc+6][r128]=f2tf32(a1.z); As[kc+7][r128]=f2tf32(a1.w);
        Bs[kc+0][r128]=f2tf32(b0.x); Bs[kc+1][r128]=f2tf32(b0.y);
        Bs[kc+2][r128]=f2tf32(b0.z); Bs[kc+3][r128]=f2tf32(b0.w);
        Bs[kc+4][r128]=f2tf32(b1.x); Bs[kc+5][r128]=f2tf32(b1.y);
        Bs[kc+6][r128]=f2tf32(b1.z); Bs[kc+7][r128]=f2tf32(b1.w);
        __syncthreads();
        if (k0 + BK < K) {
            a0 = *(const float4*)(Ab + k0 + BK);
            a1 = *(const float4*)(Ab + k0 + BK + 4);
            b0 = *(const float4*)(Bb + k0 + BK);
            b1 = *(const float4*)(Bb + k0 + BK + 4);
        }
#pragma unroll
        for (int ks = 0; ks < 2; ks++) {
            int kb = ks * 8;
            unsigned af[2][4], bf[8][2];
#pragma unroll
            for (int mt = 0; mt < 2; mt++) {
                int mb = wm * 32 + mt * 16 + g;
                af[mt][0] = As[kb+tg  ][mb];
                af[mt][1] = As[kb+tg  ][mb+8];
                af[mt][2] = As[kb+tg+4][mb];
                af[mt][3] = As[kb+tg+4][mb+8];
            }
#pragma unroll
            for (int nt = 0; nt < 8; nt++) {
                int nb = wn * 64 + nt * 8 + g;
                bf[nt][0] = Bs[kb+tg  ][nb];
                bf[nt][1] = Bs[kb+tg+4][nb];
            }
#pragma unroll
            for (int mt = 0; mt < 2; mt++)
#pragma unroll
                for (int nt = 0; nt < 8; nt++)
                    mma_tf32(acc[mt][nt], af[mt], bf[nt]);
        }
        __syncthreads();
    }

    // Epilogue
    float bs2[8][2], gv2[8][2];
#pragma unroll
    for (int nt = 0; nt < 8; nt++) {
        int col = bn + wn * 64 + nt * 8 + tg * 2;
        if (bias) { bs2[nt][0] = bias[col]; bs2[nt][1] = bias[col+1]; }
        else      { bs2[nt][0] = 0.f;       bs2[nt][1] = 0.f; }
        if (gate) { gv2[nt][0] = tanhf(gate[col]); gv2[nt][1] = tanhf(gate[col+1]); }
    }
#pragma unroll
    for (int mt = 0; mt < 2; mt++) {
        int row0 = bm + wm * 32 + mt * 16 + g;
#pragma unroll
        for (int nt = 0; nt < 8; nt++) {
            int col = bn + wn * 64 + nt * 8 + tg * 2;
            float v0 = acc[mt][nt][0] + bs2[nt][0];
            float v1 = acc[mt][nt][1] + bs2[nt][1];
            float v2 = acc[mt][nt][2] + bs2[nt][0];
            float v3 = acc[mt][nt][3] + bs2[nt][1];
            if (gate) {
                float2 r0 = *(const float2*)(res + (size_t)row0 * N + col);
                float2 r1 = *(const float2*)(res + (size_t)(row0+8) * N + col);
                v0 = r0.x + gv2[nt][0] * v0; v1 = r0.y + gv2[nt][1] * v1;
                v2 = r1.x + gv2[nt][0] * v2; v3 = r1.y + gv2[nt][1] * v3;
            } else if (res) {
                float2 r0 = *(const float2*)(res + (size_t)row0 * N + col);
                float2 r1 = *(const float2*)(res + (size_t)(row0+8) * N + col);
                v0 += r0.x; v1 += r0.y; v2 += r1.x; v3 += r1.y;
            }
            *(float2*)(C + (size_t)row0 * N + col)     = make_float2(v0, v1);
            *(float2*)(C + (size_t)(row0+8) * N + col) = make_float2(v2, v3);
        }
    }
}

__global__ __launch_bounds__(256) void gemm_nt_kernel(
    const float* __restrict__ A, const float* __restrict__ B, float* __restrict__ C,
    const float* __restrict__ bias, const float* __restrict__ res,
    const float* __restrict__ gate)
{
    gemm_core(A, B, C, bias, res, gate, blockIdx.y * 128, blockIdx.x * 128);
}

__global__ __launch_bounds__(256) void gemm3_nt_kernel(
    const float* __restrict__ A,
    const float* __restrict__ B0, const float* __restrict__ B1, const float* __restrict__ B2,
    float* __restrict__ C0, float* __restrict__ C1, float* __restrict__ C2,
    const float* __restrict__ b0, const float* __restrict__ b1, const float* __restrict__ b2)
{
    const float* B; float* C; const float* bias;
    if (blockIdx.z == 0)      { B = B0; C = C0; bias = b0; }
    else if (blockIdx.z == 1) { B = B1; C = C1; bias = b1; }
    else                      { B = B2; C = C2; bias = b2; }
    gemm_core(A, B, C, bias, nullptr, nullptr, blockIdx.y * 128, blockIdx.x * 128);
}

// ---------------- Flash attention (FFMA2, from R5) ----------------
#define AQ 68
#define AK 68
#define AP 65
#define ATT_SMEM ((64*AQ + 64*AK + 64*64 + 64*AP) * 4)

__global__ __launch_bounds__(256) void attn_flash_kernel(
    const float* __restrict__ q, const float* __restrict__ k,
    const float* __restrict__ v, float* __restrict__ o)
{
    extern __shared__ float sm[];
    float* Qs = sm;
    float* Ks = Qs + 64 * AQ;
    float* Vs = Ks + 64 * AK;
    float* Ps = Vs + 64 * 64;

    int qt = blockIdx.x, bh = blockIdx.y;
    int b = bh >> 4, h = bh & 15;
    int tid = threadIdx.x, tx = tid & 15, ty = tid >> 4;
    size_t base = ((size_t)b * Sn) * Dn + h * HDn;

    for (int idx = tid; idx < 4096; idx += 256) {
        int r = idx >> 6, e = idx & 63;
        Qs[r * AQ + e] = q[base + (size_t)(qt * 64 + r) * Dn + e] * 0.125f;
    }
    float m[4], l[4];
    u64 oa2[4][2];
#pragma unroll
    for (int u = 0; u < 4; u++) {
        m[u] = -1e30f; l[u] = 0.f;
        oa2[u][0] = 0ULL; oa2[u][1] = 0ULL;
    }
    __syncthreads();

    for (int kt = 0; kt <= qt; kt++) {
        for (int idx = tid; idx < 4096; idx += 256) {
            int r = idx >> 6, e = idx & 63;
            size_t g = base + (size_t)(kt * 64 + r) * Dn + e;
            Ks[r * AK + e] = k[g];
            Vs[r * 64 + e] = v[g];
        }
        __syncthreads();

        u64 s2[4][4];
#pragma unroll
        for (int u = 0; u < 4; u++)
#pragma unroll
            for (int vv = 0; vv < 4; vv++) s2[u][vv] = 0ULL;
#pragma unroll 2
        for (int e0 = 0; e0 < 64; e0 += 4) {
            u64 qa2[4][2], ka2[4][2];
#pragma unroll
            for (int u = 0; u < 4; u++) {
                float4 f = *(const float4*)(Qs + (ty*4+u)*AQ + e0);
                f4tou2(f, qa2[u][0], qa2[u][1]);
            }
#pragma unroll
            for (int vv = 0; vv < 4; vv++) {
                float4 f = *(const float4*)(Ks + (tx*4+vv)*AK + e0);
                f4tou2(f, ka2[vv][0], ka2[vv][1]);
            }
#pragma unroll
            for (int u = 0; u < 4; u++)
#pragma unroll
                for (int vv = 0; vv < 4; vv++) {
                    s2[u][vv] = ffma2(qa2[u][0], ka2[vv][0], s2[u][vv]);
                    s2[u][vv] = ffma2(qa2[u][1], ka2[vv][1], s2[u][vv]);
                }
        }
        float acc[4][4];
#pragma unroll
        for (int u = 0; u < 4; u++)
#pragma unroll
            for (int vv = 0; vv < 4; vv++) {
                float lo, hi; f2unpack(s2[u][vv], lo, hi);
                acc[u][vv] = lo + hi;
            }
        bool diag = (kt == qt);
#pragma unroll
        for (int u = 0; u < 4; u++) {
            int r = ty * 4 + u;
            float mx = -1e30f;
#pragma unroll
            for (int vv = 0; vv < 4; vv++) {
                int c = tx * 4 + vv;
                if (diag && c > r) acc[u][vv] = -1e30f;
                mx = fmaxf(mx, acc[u][vv]);
            }
            mx = hmax16(mx);
            float nm = fmaxf(m[u], mx);
            float corr = __expf(m[u] - nm);
            float ps = 0.f;
#pragma unroll
            for (int vv = 0; vv < 4; vv++) {
                float p = __expf(acc[u][vv] - nm);
                Ps[r * AP + tx * 4 + vv] = p;
                ps += p;
            }
            ps = hsum16(ps);
            l[u] = l[u] * corr + ps;
            m[u] = nm;
            u64 c2 = f2pack(corr, corr);
            u64 z = 0ULL;
            oa2[u][0] = ffma2(oa2[u][0], c2, z);
            oa2[u][1] = ffma2(oa2[u][1], c2, z);
        }
        __syncthreads();
#pragma unroll 4
        for (int kc = 0; kc < 64; kc++) {
            float4 v4 = *(const float4*)(Vs + kc * 64 + tx * 4);
            u64 v2[2];
            f4tou2(v4, v2[0], v2[1]);
#pragma unroll
            for (int u = 0; u < 4; u++) {
                float p = Ps[(ty * 4 + u) * AP + kc];
                u64 p2 = f2pack(p, p);
                oa2[u][0] = ffma2(p2, v2[0], oa2[u][0]);
                oa2[u][1] = ffma2(p2, v2[1], oa2[u][1]);
            }
        }
        __syncthreads();
    }
#pragma unroll
    for (int u = 0; u < 4; u++) {
        float inv = __fdividef(1.f, l[u]);
        float o0, o1, o2, o3;
        f2unpack(oa2[u][0], o0, o1);
        f2unpack(oa2[u][1], o2, o3);
        size_t g = base + (size_t)(qt * 64 + ty * 4 + u) * Dn + tx * 4;
        *(float4*)(o + g) = make_float4(o0*inv, o1*inv, o2*inv, o3*inv);
    }
}

// ---------------- prep & lr ----------------
__global__ __launch_bounds__(256) void prep_kernel(
    float* __restrict__ XQ, float* __restrict__ XK, float* __restrict__ XV,
    const float* __restrict__ nw, const float* __restrict__ nb)
{
    int w = (blockIdx.x * blockDim.x + threadIdx.x) >> 5;
    if (w >= Bn * Sn * Hn) return;
    int lane = threadIdx.x & 31;
    int h = w & 15, bs = w >> 4;
    size_t base = (size_t)bs * Dn + h * HDn;
    float q0 = XQ[base + lane], q1 = XQ[base + lane + 32];
    float qi = 1.f / fmaxf(sqrtf(warpsum(q0*q0 + q1*q1)), 1e-12f);
    XQ[base + lane] = q0 * qi; XQ[base + lane + 32] = q1 * qi;
    float k0 = XK[base + lane], k1 = XK[base + lane + 32];
    float ki = 1.f / fmaxf(sqrtf(warpsum(k0*k0 + k1*k1)), 1e-12f);
    k0 *= ki; k1 *= ki;
    XK[base + lane] = k0; XK[base + lane + 32] = k1;
    float v0 = XV[base + lane], v1 = XV[base + lane + 32];
    float mu = warpsum(v0 + v1) * (1.f / 64.f);
    float d0 = v0 - mu, d1 = v1 - mu;
    float var = warpsum(d0*d0 + d1*d1) * (1.f / 64.f);
    float rstd = rsqrtf(var + EPSc);
    XV[base + lane]      = nw[h*64+lane]    * d0 * rstd + nb[h*64+lane]    + k0;
    XV[base + lane + 32] = nw[h*64+lane+32] * d1 * rstd + nb[h*64+lane+32] + k1;
}

__global__ __launch_bounds__(256) void lr_kernel(
    const float* __restrict__ x1, const float* __restrict__ lrw,
    const float* __restrict__ lrb, float* __restrict__ lro)
{
    int w = (blockIdx.x * blockDim.x + threadIdx.x) >> 5;
    if (w >= Bn * Sn * Hn) return;
    int lane = threadIdx.x & 31;
    int h = w & 15, bs = w >> 4;
    int b = bs >> 10, s = bs & (Sn - 1);
    const float* xr = x1 + (size_t)bs * Dn;
    const float* wr = lrw + h * Dn;
    float acc = 0.f;
    for (int c = lane; c < Dn; c += 32) acc += xr[c] * wr[c];
    acc = warpsum(acc);
    if (lane == 0)
        lro[(size_t)(b * Hn + h) * Sn + s] = 1.f / (1.f + __expf(-(acc + lrb[h])));
}

// ---------------- TTT scan, 512 threads, FFMA2 hot loops ----------------
#define TP 65
#define PS 68
#define SCAN_SMEM ((3*64*TP + 2*64*PS + 256 + 64 + 64) * 4)

__global__ __launch_bounds__(512) void ttt_scan_kernel(
    const float* __restrict__ XQ, const float* __restrict__ XK, const float* __restrict__ XV,
    const float* __restrict__ lr,
    const float* __restrict__ W1i, const float* __restrict__ b1i,
    const float* __restrict__ W2i, const float* __restrict__ b2i,
    const float* __restrict__ nw,  const float* __restrict__ nb,
    float* __restrict__ W1G, float* __restrict__ W2G, float* __restrict__ W2TG,
    float* __restrict__ X2G, float* __restrict__ gZ1G, float* __restrict__ X2bG,
    float* __restrict__ outp)
{
    extern __shared__ float sm[];
    float* sxq  = sm;
    float* sxk  = sxq + 64 * TP;
    float* sxv  = sxk + 64 * TP;
    float* ssc  = sxv + 64 * TP;
    float* sgZ2 = ssc + 64 * PS;
    float* b1sm = sgZ2 + 64 * PS;
    float* b2sm = b1sm + 256;
    float* seta = b2sm + 64;

    int bh = blockIdx.x, b = bh >> 4, h = bh & 15;
    int tid = threadIdx.x, w = tid >> 5, l = tid & 31;
    int ty2 = tid >> 4, tx2 = tid & 15;
    int ft = tid >> 3, jt = tid & 7;
    float* W1r  = W1G  + (size_t)bh * 16384;
    float* W2r  = W2G  + (size_t)bh * 16384;
    float* W2Tr = W2TG + (size_t)bh * 16384;
    float* X2r  = X2G  + (size_t)bh * 16384;
    float* gZ1r = gZ1G + (size_t)bh * 16384;
    float* X2br = X2bG + (size_t)bh * 16384;
    const float* nwh = nw + h * 64;
    const float* nbh = nb + h * 64;

    for (int idx = tid; idx < 16384; idx += 512) {
        W1r[idx] = W1i[(size_t)h * 16384 + idx];
        W2r[idx] = W2i[(size_t)h * 16384 + idx];
        int e = idx >> 8, f = idx & 255;
        W2Tr[idx] = W2i[(size_t)h * 16384 + f * 64 + e];
    }
    if (tid < 256) b1sm[tid] = b1i[h * 256 + tid];
    if (tid < 64)  b2sm[tid] = b2i[h * 64 + tid];
    __syncthreads();

    for (int n = 0; n < NCn; n++) {
        size_t tokbase = (size_t)b * Sn + n * Cn;
        for (int idx = tid; idx < 4096; idx += 512) {
            int i = idx >> 6, e = idx & 63;
            size_t g = (tokbase + i) * Dn + h * 64 + e;
            sxq[i * TP + e] = XQ[g];
            sxk[i * TP + e] = XK[g];
            sxv[i * TP + e] = XV[g];
        }
        if (tid < 64) seta[tid] = lr[(size_t)bh * Sn + n * 64 + tid] * (1.f / 64.f);
        __syncthreads();

        // A: Z1 = xk@W1 + b1 -> X2, gZ1=gelu'   (FFMA2)
        {
            u64 acc2[4][4];
            {
                float4 bb0 = *(const float4*)(b1sm + l * 8);
                float4 bb1 = *(const float4*)(b1sm + l * 8 + 4);
                u64 p0, p1, p2, p3;
                f4tou2(bb0, p0, p1); f4tou2(bb1, p2, p3);
#pragma unroll
                for (int u = 0; u < 4; u++) {
                    acc2[u][0] = p0; acc2[u][1] = p1; acc2[u][2] = p2; acc2[u][3] = p3;
                }
            }
#pragma unroll 4
            for (int e = 0; e < 64; e++) {
                float4 w0 = *(const float4*)(W1r + e * 256 + l * 8);
                float4 w1 = *(const float4*)(W1r + e * 256 + l * 8 + 4);
                u64 w2[4];
                f4tou2(w0, w2[0], w2[1]); f4tou2(w1, w2[2], w2[3]);
#pragma unroll
                for (int u = 0; u < 4; u++) {
                    float a = sxk[(w * 4 + u) * TP + e];
                    u64 a2 = f2pack(a, a);
#pragma unroll
                    for (int p = 0; p < 4; p++) acc2[u][p] = ffma2(a2, w2[p], acc2[u][p]);
                }
            }
#pragma unroll
            for (int u = 0; u < 4; u++) {
                int row = w * 4 + u;
                float zz[8], x2v[8], gbv[8];
#pragma unroll
                for (int p = 0; p < 4; p++) f2unpack(acc2[u][p], zz[2*p], zz[2*p+1]);
#pragma unroll
                for (int v = 0; v < 8; v++) {
                    float z = zz[v];
                    float t = tanh_fast(0.79788456f * (z + 0.044715f * z * z * z));
                    x2v[v] = 0.5f * z * (1.f + t);
                    gbv[v] = 0.5f * z * (1.f - t * t) * (0.79788456f + 0.1070322243f * z * z)
                           + 0.5f * (1.f + t);
                }
                float4* xp = (float4*)(X2r + row * 256 + l * 8);
                xp[0] = make_float4(x2v[0],x2v[1],x2v[2],x2v[3]);
                xp[1] = make_float4(x2v[4],x2v[5],x2v[6],x2v[7]);
                float4* gp = (float4*)(gZ1r + row * 256 + l * 8);
                gp[0] = make_float4(gbv[0],gbv[1],gbv[2],gbv[3]);
                gp[1] = make_float4(gbv[4],gbv[5],gbv[6],gbv[7]);
            }
        }
        __syncthreads();

        // B: Z2 = X2@W2 + b2 -> ssc
        {
            float acc[2][4];
#pragma unroll
            for (int u = 0; u < 2; u++)
#pragma unroll
                for (int v = 0; v < 4; v++) acc[u][v] = b2sm[tx2 * 4 + v];
#pragma unroll 4
            for (int f0 = 0; f0 < 256; f0 += 4) {
                float4 a4[2], b4[4];
#pragma unroll
                for (int u = 0; u < 2; u++) a4[u] = *(const float4*)(X2r + (ty2*2+u)*256 + f0);
#pragma unroll
                for (int d = 0; d < 4; d++) b4[d] = *(const float4*)(W2r + (f0+d)*64 + tx2*4);
#pragma unroll
                for (int u = 0; u < 2; u++) {
                    acc[u][0] += a4[u].x*b4[0].x + a4[u].y*b4[1].x + a4[u].z*b4[2].x + a4[u].w*b4[3].x;
                    acc[u][1] += a4[u].x*b4[0].y + a4[u].y*b4[1].y + a4[u].z*b4[2].y + a4[u].w*b4[3].y;
                    acc[u][2] += a4[u].x*b4[0].z + a4[u].y*b4[1].z + a4[u].z*b4[2].z + a4[u].w*b4[3].z;
                    acc[u][3] += a4[u].x*b4[0].w + a4[u].y*b4[1].w + a4[u].z*b4[2].w + a4[u].w*b4[3].w;
                }
            }
#pragma unroll
            for (int u = 0; u < 2; u++)
#pragma unroll
                for (int v = 0; v < 4; v++) ssc[(ty2*2+u)*PS + tx2*4+v] = acc[u][v];
        }
        __syncthreads();

        // C: gZ2 = ln_l2_bwd(Z2, xv-xk)
        for (int i = w; i < 64; i += 16) {
            float z0 = ssc[i*PS + l], z1 = ssc[i*PS + l + 32];
            float mu = warpsum(z0 + z1) * (1.f/64.f);
            float d0 = z0 - mu, d1 = z1 - mu;
            float var = warpsum(d0*d0 + d1*d1) * (1.f/64.f);
            float rstd = rsqrtf(var + EPSc);
            float xh0 = d0 * rstd, xh1 = d1 * rstd;
            float g0 = nwh[l], g1 = nwh[l+32];
            float t0 = sxv[i*TP + l] - sxk[i*TP + l];
            float t1 = sxv[i*TP + l + 32] - sxk[i*TP + l + 32];
            float gh0 = (g0*xh0 + nbh[l]    - t0) * g0;
            float gh1 = (g1*xh1 + nbh[l+32] - t1) * g1;
            float sgh = warpsum(gh0 + gh1);
            float sgx = warpsum(gh0*xh0 + gh1*xh1);
            float cc = rstd * (1.f/64.f);
            sgZ2[i*PS + l]      = (64.f*gh0 - sgh - xh0*sgx) * cc;
            sgZ2[i*PS + l + 32] = (64.f*gh1 - sgh - xh1*sgx) * cc;
        }
        __syncthreads();

        // D: gZ1 = (gZ2 @ W2^T) * gb   (FFMA2)
        {
            u64 acc2[4][4];
#pragma unroll
            for (int u = 0; u < 4; u++)
#pragma unroll
                for (int p = 0; p < 4; p++) acc2[u][p] = 0ULL;
#pragma unroll 4
            for (int e = 0; e < 64; e++) {
                float4 w0 = *(const float4*)(W2Tr + e*256 + l*8);
                float4 w1 = *(const float4*)(W2Tr + e*256 + l*8 + 4);
                u64 w2[4];
                f4tou2(w0, w2[0], w2[1]); f4tou2(w1, w2[2], w2[3]);
#pragma unroll
                for (int u = 0; u < 4; u++) {
                    float a = sgZ2[(w*4+u)*PS + e];
                    u64 a2 = f2pack(a, a);
#pragma unroll
                    for (int p = 0; p < 4; p++) acc2[u][p] = ffma2(a2, w2[p], acc2[u][p]);
                }
            }
#pragma unroll
            for (int u = 0; u < 4; u++) {
                int row = w * 4 + u;
                float av[8];
#pragma unroll
                for (int p = 0; p < 4; p++) f2unpack(acc2[u][p], av[2*p], av[2*p+1]);
                float4* gp = (float4*)(gZ1r + row * 256 + l * 8);
                float4 g0 = gp[0], g1 = gp[1];
                gp[0] = make_float4(av[0]*g0.x, av[1]*g0.y, av[2]*g0.z, av[3]*g0.w);
                gp[1] = make_float4(av[4]*g1.x, av[5]*g1.y, av[6]*g1.z, av[7]*g1.w);
            }
        }
        __syncthreads();

        // E: coef1 = eta[k]*(tril(xq@xk^T)+1) -> ssc
        {
            float acc[2][4];
#pragma unroll
            for (int u = 0; u < 2; u++)
#pragma unroll
                for (int v = 0; v < 4; v++) acc[u][v] = 0.f;
            if (tx2 * 4 <= ty2 * 2 + 1) {
#pragma unroll 4
                for (int e = 0; e < 64; e++) {
                    float a[2], bb[4];
#pragma unroll
                    for (int u = 0; u < 2; u++) a[u]  = sxq[(ty2*2+u)*TP + e];
#pragma unroll
                    for (int v = 0; v < 4; v++) bb[v] = sxk[(tx2*4+v)*TP + e];
#pragma unroll
                    for (int u = 0; u < 2; u++)
#pragma unroll
                        for (int v = 0; v < 4; v++) acc[u][v] += a[u] * bb[v];
                }
            }
#pragma unroll
            for (int u = 0; u < 2; u++) {
                int i = ty2 * 2 + u;
#pragma unroll
                for (int v = 0; v < 4; v++) {
                    int kk = tx2 * 4 + v;
                    ssc[i*PS + kk] = (kk <= i) ? seta[kk] * (acc[u][v] + 1.f) : 0.f;
                }
            }
        }
        __syncthreads();

        // F: Z1b = xq@W1 + b1 - coef1@gZ1 ; X2b = gelu   (FFMA2)
        {
            u64 acc2[4][4];
            {
                float4 bb0 = *(const float4*)(b1sm + l * 8);
                float4 bb1 = *(const float4*)(b1sm + l * 8 + 4);
                u64 p0, p1, p2, p3;
                f4tou2(bb0, p0, p1); f4tou2(bb1, p2, p3);
#pragma unroll
                for (int u = 0; u < 4; u++) {
                    acc2[u][0] = p0; acc2[u][1] = p1; acc2[u][2] = p2; acc2[u][3] = p3;
                }
            }
#pragma unroll 4
            for (int e = 0; e < 64; e++) {
                float4 w0 = *(const float4*)(W1r + e*256 + l*8);
                float4 w1 = *(const float4*)(W1r + e*256 + l*8 + 4);
                u64 w2[4];
                f4tou2(w0, w2[0], w2[1]); f4tou2(w1, w2[2], w2[3]);
#pragma unroll
                for (int u = 0; u < 4; u++) {
                    float a = sxq[(w*4+u)*TP + e];
                    u64 a2 = f2pack(a, a);
#pragma unroll
                    for (int p = 0; p < 4; p++) acc2[u][p] = ffma2(a2, w2[p], acc2[u][p]);
                }
            }
#pragma unroll 4
            for (int k2 = 0; k2 < 64; k2++) {
                float4 g0 = *(const float4*)(gZ1r + k2*256 + l*8);
                float4 g1 = *(const float4*)(gZ1r + k2*256 + l*8 + 4);
                u64 gv2[4];
                f4tou2(g0, gv2[0], gv2[1]); f4tou2(g1, gv2[2], gv2[3]);
#pragma unroll
                for (int u = 0; u < 4; u++) {
                    float c = -ssc[(w*4+u)*PS + k2];
                    u64 c2 = f2pack(c, c);
#pragma unroll
                    for (int p = 0; p < 4; p++) acc2[u][p] = ffma2(c2, gv2[p], acc2[u][p]);
                }
            }
#pragma unroll
            for (int u = 0; u < 4; u++) {
                int row = w * 4 + u;
                float zz[8], xv2[8];
#pragma unroll
                for (int p = 0; p < 4; p++) f2unpack(acc2[u][p], zz[2*p], zz[2*p+1]);
#pragma unroll
                for (int v = 0; v < 8; v++) {
                    float z = zz[v];
                    float t = tanh_fast(0.79788456f * (z + 0.044715f * z * z * z));
                    xv2[v] = 0.5f * z * (1.f + t);
                }
                float4* xp = (float4*)(X2br + row * 256 + l * 8);
                xp[0] = make_float4(xv2[0],xv2[1],xv2[2],xv2[3]);
                xp[1] = make_float4(xv2[4],xv2[5],xv2[6],xv2[7]);
            }
        }
        __syncthreads();

        // G: coef2 = eta[j]*(tril(X2b@X2^T)+1) -> ssc
        {
            float acc[2][4];
#pragma unroll
            for (int u = 0; u < 2; u++)
#pragma unroll
                for (int v = 0; v < 4; v++) acc[u][v] = 0.f;
            if (tx2 * 4 <= ty2 * 2 + 1) {
#pragma unroll 2
                for (int f0 = 0; f0 < 256; f0 += 4) {
                    float4 a4[2], b4[4];
#pragma unroll
                    for (int u = 0; u < 2; u++) a4[u] = *(const float4*)(X2br + (ty2*2+u)*256 + f0);
#pragma unroll
                    for (int v = 0; v < 4; v++) b4[v] = *(const float4*)(X2r + (tx2*4+v)*256 + f0);
#pragma unroll
                    for (int u = 0; u < 2; u++)
#pragma unroll
                        for (int v = 0; v < 4; v++)
                            acc[u][v] += a4[u].x*b4[v].x + a4[u].y*b4[v].y
                                       + a4[u].z*b4[v].z + a4[u].w*b4[v].w;
                }
            }
#pragma unroll
            for (int u = 0; u < 2; u++) {
                int i = ty2 * 2 + u;
#pragma unroll
                for (int v = 0; v < 4; v++) {
                    int j = tx2 * 4 + v;
                    ssc[i*PS + j] = (j <= i) ? seta[j] * (acc[u][v] + 1.f) : 0.f;
                }
            }
        }
        __syncthreads();

        // H: Z2b = X2b@W2 + b2 - coef2@gZ2 -> sxv
        {
            float acc[2][4];
#pragma unroll
            for (int u = 0; u < 2; u++)
#pragma unroll
                for (int v = 0; v < 4; v++) acc[u][v] = b2sm[tx2 * 4 + v];
#pragma unroll 4
            for (int f0 = 0; f0 < 256; f0 += 4) {
                float4 a4[2], b4[4];
#pragma unroll
                for (int u = 0; u < 2; u++) a4[u] = *(const float4*)(X2br + (ty2*2+u)*256 + f0);
#pragma unroll
                for (int d = 0; d < 4; d++) b4[d] = *(const float4*)(W2r + (f0+d)*64 + tx2*4);
#pragma unroll
                for (int u = 0; u < 2; u++) {
                    acc[u][0] += a4[u].x*b4[0].x + a4[u].y*b4[1].x + a4[u].z*b4[2].x + a4[u].w*b4[3].x;
                    acc[u][1] += a4[u].x*b4[0].y + a4[u].y*b4[1].y + a4[u].z*b4[2].y + a4[u].w*b4[3].y;
                    acc[u][2] += a4[u].x*b4[0].z + a4[u].y*b4[1].z + a4[u].z*b4[2].z + a4[u].w*b4[3].z;
                    acc[u][3] += a4[u].x*b4[0].w + a4[u].y*b4[1].w + a4[u].z*b4[2].w + a4[u].w*b4[3].w;
                }
            }
#pragma unroll 4
            for (int k2 = 0; k2 < 64; k2++) {
                float c[2];
                c[0] = ssc[(ty2*2)*PS + k2];
                c[1] = ssc[(ty2*2+1)*PS + k2];
                float4 gv4 = *(const float4*)(sgZ2 + k2*PS + tx2*4);
                float gv[4] = {gv4.x, gv4.y, gv4.z, gv4.w};
#pragma unroll
                for (int u = 0; u < 2; u++)
#pragma unroll
                    for (int v = 0; v < 4; v++) acc[u][v] -= c[u] * gv[v];
            }
#pragma unroll
            for (int u = 0; u < 2; u++)
#pragma unroll
                for (int v = 0; v < 4; v++) sxv[(ty2*2+u)*TP + tx2*4+v] = acc[u][v];
        }
        __syncthreads();

        // I: out = xq + LN(Z2b)
        for (int i = w; i < 64; i += 16) {
            float z0 = sxv[i*TP + l], z1 = sxv[i*TP + l + 32];
            float mu = warpsum(z0 + z1) * (1.f/64.f);
            float d0 = z0 - mu, d1 = z1 - mu;
            float var = warpsum(d0*d0 + d1*d1) * (1.f/64.f);
            float rstd = rsqrtf(var + EPSc);
            size_t g = (tokbase + i) * Dn + h * 64;
            outp[g + l]      = sxq[i*TP + l]      + nwh[l]    * d0 * rstd + nbh[l];
            outp[g + l + 32] = sxq[i*TP + l + 32] + nwh[l+32] * d1 * rstd + nbh[l+32];
        }

        // J1: W1 -= (eta*xk)^T @ gZ1   (FFMA2)
        {
            u64 acc2[4][4];
#pragma unroll
            for (int u = 0; u < 4; u++)
#pragma unroll
                for (int p = 0; p < 4; p++) acc2[u][p] = 0ULL;
#pragma unroll 4
            for (int i = 0; i < 64; i++) {
                float et = seta[i];
                float4 g0 = *(const float4*)(gZ1r + i*256 + l*8);
                float4 g1 = *(const float4*)(gZ1r + i*256 + l*8 + 4);
                u64 gv2[4];
                f4tou2(g0, gv2[0], gv2[1]); f4tou2(g1, gv2[2], gv2[3]);
#pragma unroll
                for (int u = 0; u < 4; u++) {
                    float a = et * sxk[i*TP + w*4+u];
                    u64 a2 = f2pack(a, a);
#pragma unroll
                    for (int p = 0; p < 4; p++) acc2[u][p] = ffma2(a2, gv2[p], acc2[u][p]);
                }
            }
#pragma unroll
            for (int u = 0; u < 4; u++) {
                int e = w * 4 + u;
                float av[8];
#pragma unroll
                for (int p = 0; p < 4; p++) f2unpack(acc2[u][p], av[2*p], av[2*p+1]);
                float4* wp = (float4*)(W1r + e*256 + l*8);
                float4 o0 = wp[0], o1 = wp[1];
                wp[0] = make_float4(o0.x-av[0], o0.y-av[1], o0.z-av[2], o0.w-av[3]);
                wp[1] = make_float4(o1.x-av[4], o1.y-av[5], o1.z-av[6], o1.w-av[7]);
            }
        }
        // J2: b1
        if (tid < 256) {
            float acc = 0.f;
#pragma unroll 8
            for (int i = 0; i < 64; i++) acc += seta[i] * gZ1r[i*256 + tid];
            b1sm[tid] -= acc;
        }
        // J3: W2 and W2T   (FFMA2)
        {
            u64 acc2[4][4];
#pragma unroll
            for (int u = 0; u < 4; u++)
#pragma unroll
                for (int p = 0; p < 4; p++) acc2[u][p] = 0ULL;
#pragma unroll 4
            for (int i = 0; i < 64; i++) {
                float et = seta[i];
                float4 x0 = *(const float4*)(X2r + i*256 + ft*4);
                float4 gv0 = *(const float4*)(sgZ2 + i*PS + jt*8);
                float4 gv1 = *(const float4*)(sgZ2 + i*PS + jt*8 + 4);
                u64 gv2[4];
                f4tou2(gv0, gv2[0], gv2[1]); f4tou2(gv1, gv2[2], gv2[3]);
                float a[4] = {et*x0.x, et*x0.y, et*x0.z, et*x0.w};
#pragma unroll
                for (int u = 0; u < 4; u++) {
                    u64 a2 = f2pack(a[u], a[u]);
#pragma unroll
                    for (int p = 0; p < 4; p++) acc2[u][p] = ffma2(a2, gv2[p], acc2[u][p]);
                }
            }
#pragma unroll
            for (int u = 0; u < 4; u++) {
                int f = ft * 4 + u;
                float av[8];
#pragma unroll
                for (int p = 0; p < 4; p++) f2unpack(acc2[u][p], av[2*p], av[2*p+1]);
                float4* wp0 = (float4*)(W2r + f*64 + jt*8);
                float4* wp1 = (float4*)(W2r + f*64 + jt*8 + 4);
                float4 o0 = wp0[0], o1 = wp1[0];
                wp0[0] = make_float4(o0.x-av[0], o0.y-av[1], o0.z-av[2], o0.w-av[3]);
                wp1[0] = make_float4(o1.x-av[4], o1.y-av[5], o1.z-av[6], o1.w-av[7]);
#pragma unroll
                for (int v = 0; v < 8; v++)
                    W2Tr[(jt*8+v)*256 + f] -= av[v];
            }
        }
        // J4: b2
        if (tid < 64) {
            float acc = 0.f;
#pragma unroll 8
            for (int i = 0; i < 64; i++) acc += seta[i] * sgZ2[i*PS + tid];
            b2sm[tid] -= acc;
        }
        __syncthreads();
    }
}

// ---------------- Launch ----------------
extern "C" void kernel_launch(void* const* d_in, const int* in_sizes, int n_in,
                              void* d_out, int out_size)
{
    const float* x       = (const float*)d_in[0];
    const float* ln1_w   = (const float*)d_in[1];
    const float* ln1_b   = (const float*)d_in[2];
    const float* attn_wq = (const float*)d_in[3];
    const float* attn_wk = (const float*)d_in[4];
    const float* attn_wv = (const float*)d_in[5];
    const float* attn_wo = (const float*)d_in[6];
    const float* wq_w    = (const float*)d_in[7];
    const float* wq_b    = (const float*)d_in[8];
    const float* wk_w    = (const float*)d_in[9];
    const float* wk_b    = (const float*)d_in[10];
    const float* wv_w    = (const float*)d_in[11];
    const float* wv_b    = (const float*)d_in[12];
    const float* wo_w    = (const float*)d_in[13];
    const float* wo_b    = (const float*)d_in[14];
    const float* W1      = (const float*)d_in[15];
    const float* b1      = (const float*)d_in[16];
    const float* W2      = (const float*)d_in[17];
    const float* b2      = (const float*)d_in[18];
    const float* ttt_nw  = (const float*)d_in[19];
    const float* ttt_nb  = (const float*)d_in[20];
    const float* lr_w    = (const float*)d_in[21];
    const float* lr_b    = (const float*)d_in[22];
    const float* pn_w    = (const float*)d_in[23];
    const float* pn_b    = (const float*)d_in[24];
    const float* gate_a  = (const float*)d_in[25];
    float* out = (float*)d_out;

    float *p_h,*p_q,*p_k,*p_v,*p_o,*p_x1,*p_lr,*p_W1,*p_W2,*p_W2T,*p_X2,*p_gZ1,*p_X2b;
    cudaGetSymbolAddress((void**)&p_h,  g_h);
    cudaGetSymbolAddress((void**)&p_q,  g_q);
    cudaGetSymbolAddress((void**)&p_k,  g_k);
    cudaGetSymbolAddress((void**)&p_v,  g_v);
    cudaGetSymbolAddress((void**)&p_o,  g_o);
    cudaGetSymbolAddress((void**)&p_x1, g_x1);
    cudaGetSymbolAddress((void**)&p_lr, g_lr);
    cudaGetSymbolAddress((void**)&p_W1, g_W1s);
    cudaGetSymbolAddress((void**)&p_W2, g_W2s);
    cudaGetSymbolAddress((void**)&p_W2T,g_W2Ts);
    cudaGetSymbolAddress((void**)&p_X2, g_X2);
    cudaGetSymbolAddress((void**)&p_gZ1,g_gZ1);
    cudaGetSymbolAddress((void**)&p_X2b,g_X2b);

    cudaFuncSetAttribute(ttt_scan_kernel,   cudaFuncAttributeMaxDynamicSharedMemorySize, SCAN_SMEM);
    cudaFuncSetAttribute(attn_flash_kernel, cudaFuncAttributeMaxDynamicSharedMemorySize, ATT_SMEM);

    const int M = Bn * Sn;
    dim3 ggrid(Dn / 128, M / 128);
    dim3 ggrid3(Dn / 128, M / 128, 3);
    int nwarp_grid = (Bn * Sn * Hn) / 8;

    ln_kernel<<<M, 256>>>(x, ln1_w, ln1_b, p_h);
    gemm3_nt_kernel<<<ggrid3, 256>>>(p_h, attn_wq, attn_wk, attn_wv,
                                     p_q, p_k, p_v, nullptr, nullptr, nullptr);
    attn_flash_kernel<<<dim3(16, 64), 256, ATT_SMEM>>>(p_q, p_k, p_v, p_o);
    gemm_nt_kernel<<<ggrid, 256>>>(p_o, attn_wo, p_x1, nullptr, x, nullptr);
    gemm3_nt_kernel<<<ggrid3, 256>>>(p_x1, wq_w, wk_w, wv_w,
                                     p_q, p_k, p_v, wq_b, wk_b, wv_b);
    prep_kernel<<<nwarp_grid, 256>>>(p_q, p_k, p_v, ttt_nw, ttt_nb);
    lr_kernel<<<nwarp_grid, 256>>>(p_x1, lr_w, lr_b, p_lr);
    ttt_scan_kernel<<<Bn * Hn, 512, SCAN_SMEM>>>(
        p_q, p_k, p_v, p_lr, W1, b1, W2, b2, ttt_nw, ttt_nb,
        p_W1, p_W2, p_W2T, p_X2, p_gZ1, p_X2b, p_o);
    ln_kernel<<<M, 256>>>(p_o, pn_w, pn_b, p_h);
    gemm_nt_kernel<<<ggrid, 256>>>(p_h, wo_w, out, wo_b, p_x1, gate_a);
}